// round 4
// baseline (speedup 1.0000x reference)
#include <cuda_runtime.h>
#include <math.h>
#include <stdint.h>

#define NB 2
#define MM 512
#define DD 128
#define HH 8
#define DIN 64
#define NM (NB*MM)   // 1024

typedef unsigned long long u64;

// ---------------- packed f32x2 helpers --------------------------------------------
__device__ __forceinline__ u64 pk2(float lo, float hi) {
    u64 r; asm("mov.b64 %0, {%1,%2};" : "=l"(r) : "f"(lo), "f"(hi)); return r;
}
__device__ __forceinline__ void fma2(u64& d, u64 a, u64 b) {
    asm("fma.rn.f32x2 %0, %1, %2, %0;" : "+l"(d) : "l"(a), "l"(b));
}
__device__ __forceinline__ float2 up2(u64 v) {
    float lo, hi; asm("mov.b64 {%0,%1}, %2;" : "=f"(lo), "=f"(hi) : "l"(v));
    return make_float2(lo, hi);
}

// ---------------- scratch ---------------------------------------------------------
#define OFF_TMP  0
#define OFF_H    (OFF_TMP + NM*2*DD)
#define OFF_K    (OFF_H   + NM*DD)
#define OFF_Q    (OFF_K   + HH*NM*DD)
#define OFF_V    (OFF_Q   + HH*NM*DD)
#define OFF_S    (OFF_V   + HH*NM*DD)            // [H*N,M,M]; reused as K-split partials
#define OFF_ATTC (OFF_S   + HH*NB*MM*MM)         // [NM, H*D]
#define OFF_T2   (OFF_ATTC+ HH*NM*DD)
#define OFF_AB   (OFF_T2  + NM*DD)
#define OFF_P2   (OFF_AB  + 2*NM*DD)             // attV K-split partials [2][16][M][D]
#define SCRATCH_TOTAL (OFF_P2 + 2*HH*NB*MM*DD)

__device__ float g_scratch[SCRATCH_TOTAL];

#define F_TRANSB 1
#define F_RELU   2
#define F_LEAKY  4
#define F_TE     8
#define F_BIAS   16
#define F_ADD    32

// ---------------- FFMA2 GEMM body, duplicated-B smem -------------------------------
// tile 64(M) x 128(N), 128 threads, thread tile 8x8.
// As[k][m] transposed -> row pairs load as u64 directly.
// Bs holds each element twice: col j at floats {2j, 2j+1} -> broadcast pairs load
// as u64 directly. Inner loop: 6x LDS.128 + 32x fma.f32x2, zero packs.
template<int F>
__device__ __forceinline__ void gemm_body(
    const float* __restrict__ A, const float* __restrict__ B,
    const float* __restrict__ bias, const float* __restrict__ addsrc,
    float* __restrict__ C, int Kd, int Nc, int ldc, int ktb, int kte)
{
    __shared__ float As[2][16][64];
    __shared__ float Bs[2][16][256];
    int tid = threadIdx.x;
    int tx = tid & 15, ty = tid >> 4;
    int m0 = blockIdx.y << 6, n0 = blockIdx.x << 7;

    // A loader: 64x16 tile, thread = (row=tid>>1, colchunk=(tid&1)*8)
    int ar = tid >> 1, ac = (tid & 1) << 3;
    const float* Ap = A + (int64_t)(m0 + ar) * Kd + ac;
    // B loader
    int bk = tid >> 3, bc = (tid & 7) << 4;
    const float* Bp = (F & F_TRANSB)
        ? B + (int64_t)(n0 + tid) * Kd
        : B + (int64_t)bk * Nc + n0 + bc;

    u64 acc[4][8];   // [row-pair][col]
    #pragma unroll
    for (int i = 0; i < 4; i++)
        #pragma unroll
        for (int j = 0; j < 8; j++) acc[i][j] = 0ull;

    float4 la0, la1, lb[4];

    auto loadG = [&](int kt) {
        la0 = *(const float4*)(Ap + kt * 16);
        la1 = *(const float4*)(Ap + kt * 16 + 4);
        if (F & F_TE) {
            int kb = kt * 16 + ac;
            la0.x += sinf((float)(kb + 0) * (5.0f / 63.0f));
            la0.y += sinf((float)(kb + 1) * (5.0f / 63.0f));
            la0.z += sinf((float)(kb + 2) * (5.0f / 63.0f));
            la0.w += sinf((float)(kb + 3) * (5.0f / 63.0f));
            la1.x += sinf((float)(kb + 4) * (5.0f / 63.0f));
            la1.y += sinf((float)(kb + 5) * (5.0f / 63.0f));
            la1.z += sinf((float)(kb + 6) * (5.0f / 63.0f));
            la1.w += sinf((float)(kb + 7) * (5.0f / 63.0f));
        }
        if (F & F_TRANSB) {
            #pragma unroll
            for (int u = 0; u < 4; u++)
                lb[u] = *(const float4*)(Bp + kt * 16 + 4 * u);
        } else {
            #pragma unroll
            for (int u = 0; u < 4; u++)
                lb[u] = *(const float4*)(Bp + (int64_t)(kt * 16) * Nc + 4 * u);
        }
    };
    auto storeS = [&](int bf) {
        As[bf][ac + 0][ar] = la0.x; As[bf][ac + 1][ar] = la0.y;
        As[bf][ac + 2][ar] = la0.z; As[bf][ac + 3][ar] = la0.w;
        As[bf][ac + 4][ar] = la1.x; As[bf][ac + 5][ar] = la1.y;
        As[bf][ac + 6][ar] = la1.z; As[bf][ac + 7][ar] = la1.w;
        if (F & F_TRANSB) {
            // thread owns output-col tid; dup-write its 16 k values
            #pragma unroll
            for (int u = 0; u < 4; u++) {
                *(u64*)&Bs[bf][4 * u + 0][2 * tid] = pk2(lb[u].x, lb[u].x);
                *(u64*)&Bs[bf][4 * u + 1][2 * tid] = pk2(lb[u].y, lb[u].y);
                *(u64*)&Bs[bf][4 * u + 2][2 * tid] = pk2(lb[u].z, lb[u].z);
                *(u64*)&Bs[bf][4 * u + 3][2 * tid] = pk2(lb[u].w, lb[u].w);
            }
        } else {
            #pragma unroll
            for (int u = 0; u < 4; u++) {
                float4 v = lb[u];
                *(float4*)&Bs[bf][bk][2 * (bc + 4 * u)]     = make_float4(v.x, v.x, v.y, v.y);
                *(float4*)&Bs[bf][bk][2 * (bc + 4 * u) + 4] = make_float4(v.z, v.z, v.w, v.w);
            }
        }
    };

    loadG(ktb); storeS(0); __syncthreads();
    int buf = 0;
    for (int kt = ktb; kt < kte; kt++) {
        bool more = (kt + 1 < kte);
        if (more) loadG(kt + 1);
        #pragma unroll
        for (int kk = 0; kk < 16; kk++) {
            ulonglong2 a01 = *(const ulonglong2*)&As[buf][kk][ty << 2];
            ulonglong2 a23 = *(const ulonglong2*)&As[buf][kk][32 + (ty << 2)];
            ulonglong2 b0 = *(const ulonglong2*)&Bs[buf][kk][tx << 3];
            ulonglong2 b1 = *(const ulonglong2*)&Bs[buf][kk][(tx << 3) + 4];
            ulonglong2 b2 = *(const ulonglong2*)&Bs[buf][kk][128 + (tx << 3)];
            ulonglong2 b3 = *(const ulonglong2*)&Bs[buf][kk][128 + (tx << 3) + 4];
            u64 ap[4] = {a01.x, a01.y, a23.x, a23.y};
            u64 bd[8] = {b0.x, b0.y, b1.x, b1.y, b2.x, b2.y, b3.x, b3.y};
            #pragma unroll
            for (int rp = 0; rp < 4; rp++) {
                fma2(acc[rp][0], ap[rp], bd[0]);
                fma2(acc[rp][1], ap[rp], bd[1]);
                fma2(acc[rp][2], ap[rp], bd[2]);
                fma2(acc[rp][3], ap[rp], bd[3]);
                fma2(acc[rp][4], ap[rp], bd[4]);
                fma2(acc[rp][5], ap[rp], bd[5]);
                fma2(acc[rp][6], ap[rp], bd[6]);
                fma2(acc[rp][7], ap[rp], bd[7]);
            }
        }
        if (more) { storeS(buf ^ 1); __syncthreads(); buf ^= 1; }
    }

    // ---- epilogue: rows {4ty..+3, 32+4ty..+3}; lanes of acc pair = 2 rows.
    #pragma unroll
    for (int rp = 0; rp < 4; rp++) {
        int rbase = m0 + ((rp < 2) ? ((ty << 2) + rp * 2) : (32 + (ty << 2) + (rp - 2) * 2));
        float2 p[8];
        #pragma unroll
        for (int j = 0; j < 8; j++) p[j] = up2(acc[rp][j]);
        #pragma unroll
        for (int half = 0; half < 2; half++) {
            int row = rbase + half;
            float o[8];
            #pragma unroll
            for (int j = 0; j < 8; j++) o[j] = half ? p[j].y : p[j].x;
            #pragma unroll
            for (int j = 0; j < 8; j++) {
                int col = n0 + ((j < 4) ? ((tx << 2) + j) : (64 + (tx << 2) + j - 4));
                float v = o[j];
                if (F & F_BIAS)  v += bias[col];
                if (F & F_RELU)  v = fmaxf(v, 0.0f);
                if (F & F_LEAKY) v = (v >= 0.0f) ? v : 0.2f * v;
                if (F & F_ADD)   v += addsrc[(int64_t)row * ldc + col];
                o[j] = v;
            }
            *(float4*)&C[(int64_t)row * ldc + n0 + (tx << 2)]      = make_float4(o[0], o[1], o[2], o[3]);
            *(float4*)&C[(int64_t)row * ldc + n0 + 64 + (tx << 2)] = make_float4(o[4], o[5], o[6], o[7]);
        }
    }
}

// ---------------- generic wrapper (with optional K-split) --------------------------
template<int F, int NKS>
__global__ __launch_bounds__(128, 4)
void gemm_k(const float* __restrict__ A, const float* __restrict__ B,
            const float* __restrict__ bias, const float* __restrict__ addsrc,
            float* __restrict__ C, int Kd, int Nc, int ldc,
            int64_t sA, int64_t sB, int64_t sBias,
            int zdiv, int64_t sC1, int64_t sC2, int64_t sPart)
{
    int zz = blockIdx.z;
    int z = zz / NKS, ks = zz % NKS;
    int ktn = Kd >> 4;
    int ktb = ks * (ktn / NKS), kte = ktb + ktn / NKS;
    const float* bz = (F & F_BIAS) ? bias + sBias * z : nullptr;
    float* Cz = C + (int64_t)(z / zdiv) * sC1 + (int64_t)(z % zdiv) * sC2
                  + (int64_t)ks * sPart;
    gemm_body<F>(A + sA * z, B + sB * z, bz, addsrc, Cz, Kd, Nc, ldc, ktb, kte);
}

// ---------------- fused K/Q/V wrapper: z = which*8 + head --------------------------
__global__ __launch_bounds__(128, 4)
void kqv_k(const float* __restrict__ h,
           const float* __restrict__ wk, const float* __restrict__ bk,
           const float* __restrict__ wq, const float* __restrict__ bq,
           const float* __restrict__ wv, const float* __restrict__ bv,
           float* __restrict__ out)
{
    int z = blockIdx.z;
    int which = z >> 3, head = z & 7;
    const float* W  = (which == 0) ? wk : (which == 1) ? wq : wv;
    const float* Bi = (which == 0) ? bk : (which == 1) ? bq : bv;
    W  += (int64_t)head * DD * DD;
    Bi += (int64_t)head * DD;
    float* C = out + ((int64_t)which * HH + head) * NM * DD;
    gemm_body<F_BIAS>(h, W, Bi, nullptr, C, DD, DD, DD, 0, DD / 16);
}

// ---------------- K-split reduce: C = act(sum_ks P + bias) -------------------------
template<int F, int NKS>
__global__ __launch_bounds__(256)
void reduce_k(const float4* __restrict__ P, const float* __restrict__ bias,
              float4* __restrict__ C, int totalf4, int ncf4)
{
    int idx = blockIdx.x * 256 + threadIdx.x;
    if (idx >= totalf4) return;
    float4 s = P[idx];
    #pragma unroll
    for (int k = 1; k < NKS; k++) {
        float4 t = P[idx + (int64_t)k * totalf4];
        s.x += t.x; s.y += t.y; s.z += t.z; s.w += t.w;
    }
    if (F & F_BIAS) {
        float4 b = ((const float4*)bias)[idx % ncf4];
        s.x += b.x; s.y += b.y; s.z += b.z; s.w += b.w;
    }
    if (F & F_RELU) {
        s.x = fmaxf(s.x, 0.f); s.y = fmaxf(s.y, 0.f);
        s.z = fmaxf(s.z, 0.f); s.w = fmaxf(s.w, 0.f);
    }
    C[idx] = s;
}

// ---------------- attV reduce: sum 2 partials, leaky, write concat layout ----------
__global__ __launch_bounds__(256)
void reduce_att_k(const float4* __restrict__ P, float4* __restrict__ out)
{
    const int tot = HH * NB * MM * DD / 4;   // 262144
    int idx = blockIdx.x * 256 + threadIdx.x;
    if (idx >= tot) return;
    float4 a = P[idx], b = P[idx + tot];
    float4 s = make_float4(a.x + b.x, a.y + b.y, a.z + b.z, a.w + b.w);
    s.x = (s.x >= 0.f) ? s.x : 0.2f * s.x;
    s.y = (s.y >= 0.f) ? s.y : 0.2f * s.y;
    s.z = (s.z >= 0.f) ? s.z : 0.2f * s.z;
    s.w = (s.w >= 0.f) ? s.w : 0.2f * s.w;
    // P layout: [z=h*2+n][m][d]; out: [n][m][h*32 + d4] (f4 units, row = 256 f4)
    int z   = idx >> 14;            // / (512*32)
    int rem = idx & 16383;
    int m   = rem >> 5;
    int d4  = rem & 31;
    int hh  = z >> 1, n = z & 1;
    out[(int64_t)(n * MM + m) * (HH * DD / 4) + hh * 32 + d4] = s;
}

// ---------------- row softmax over 512 cols ---------------------------------------
__global__ __launch_bounds__(256)
void softmax_k(float* __restrict__ data)
{
    __shared__ float red[8];
    float* p = data + (int64_t)blockIdx.x * MM;
    int t = threadIdx.x;
    float v0 = p[t], v1 = p[t + 256];
    float m = fmaxf(v0, v1);
    #pragma unroll
    for (int o = 16; o; o >>= 1) m = fmaxf(m, __shfl_xor_sync(0xffffffffu, m, o));
    if ((t & 31) == 0) red[t >> 5] = m;
    __syncthreads();
    float bm = red[0];
    #pragma unroll
    for (int w = 1; w < 8; w++) bm = fmaxf(bm, red[w]);
    float e0 = __expf(v0 - bm), e1 = __expf(v1 - bm);
    float s = e0 + e1;
    #pragma unroll
    for (int o = 16; o; o >>= 1) s += __shfl_xor_sync(0xffffffffu, s, o);
    __syncthreads();
    if ((t & 31) == 0) red[t >> 5] = s;
    __syncthreads();
    float bs = red[0];
    #pragma unroll
    for (int w = 1; w < 8; w++) bs += red[w];
    float inv = 1.0f / bs;
    p[t] = e0 * inv;
    p[t + 256] = e1 * inv;
}

// ---------------- edge kernel ------------------------------------------------------
__global__ __launch_bounds__(256)
void edge_k(const float* __restrict__ AB, const float* __restrict__ b1,
            const float* __restrict__ w2, const float* __restrict__ b2,
            float* __restrict__ out)
{
    __shared__ float Ast[DD][36];
    __shared__ float Bst[DD][36];
    __shared__ float w2s[DD];
    int n  = blockIdx.z;
    int i0 = blockIdx.y << 5, j0 = blockIdx.x << 5;
    const float* Ab = AB + ((int64_t)n * MM + i0) * DD;
    const float* Bb = AB + (int64_t)NM * DD + ((int64_t)n * MM + j0) * DD;
    int t = threadIdx.x;
    if (t < DD) w2s[t] = w2[t];
    #pragma unroll
    for (int c = 0; c < 4; c++) {
        int idx = t + (c << 8);
        int r  = idx >> 5;
        int d4 = (idx & 31) << 2;
        float4 a = *(const float4*)(Ab + r * DD + d4);
        Ast[d4 + 0][r] = a.x; Ast[d4 + 1][r] = a.y;
        Ast[d4 + 2][r] = a.z; Ast[d4 + 3][r] = a.w;
        float4 bvl = *(const float4*)(Bb + r * DD + d4);
        float4 bb  = *(const float4*)(b1 + d4);
        Bst[d4 + 0][r] = bvl.x + bb.x; Bst[d4 + 1][r] = bvl.y + bb.y;
        Bst[d4 + 2][r] = bvl.z + bb.z; Bst[d4 + 3][r] = bvl.w + bb.w;
    }
    __syncthreads();
    int tx = t & 15, ty = t >> 4;
    float a00 = 0.f, a01 = 0.f, a10 = 0.f, a11 = 0.f;
    #pragma unroll 8
    for (int d = 0; d < DD; d++) {
        float2 av = *(const float2*)&Ast[d][ty << 1];
        float2 bv = *(const float2*)&Bst[d][tx << 1];
        float w = w2s[d];
        a00 = fmaf(fmaxf(av.x + bv.x, 0.f), w, a00);
        a01 = fmaf(fmaxf(av.x + bv.y, 0.f), w, a01);
        a10 = fmaf(fmaxf(av.y + bv.x, 0.f), w, a10);
        a11 = fmaf(fmaxf(av.y + bv.y, 0.f), w, a11);
    }
    float bb = b2[0];
    const float sc = 1.0f / (float)MM;
    int i = i0 + (ty << 1), j = j0 + (tx << 1);
    float* o = out + ((int64_t)n * MM + i) * MM + j;
    o[0]      = (a00 + bb) * sc;
    o[1]      = (a01 + bb) * sc;
    o[MM]     = (a10 + bb) * sc;
    o[MM + 1] = (a11 + bb) * sc;
}

// ---------------- host launcher ----------------------------------------------------
extern "C" void kernel_launch(void* const* d_in, const int* in_sizes, int n_in,
                              void* d_out, int out_size)
{
    const float* x     = (const float*)d_in[0];
    const float* fn_w1 = (const float*)d_in[1];
    const float* fn_b1 = (const float*)d_in[2];
    const float* fn_w2 = (const float*)d_in[3];
    const float* fn_b2 = (const float*)d_in[4];
    const float* wk    = (const float*)d_in[5];
    const float* bk    = (const float*)d_in[6];
    const float* wq    = (const float*)d_in[7];
    const float* bq    = (const float*)d_in[8];
    const float* wv    = (const float*)d_in[9];
    const float* bv    = (const float*)d_in[10];
    const float* fv_w1 = (const float*)d_in[11];
    const float* fv_b1 = (const float*)d_in[12];
    const float* fv_w2 = (const float*)d_in[13];
    const float* fv_b2 = (const float*)d_in[14];
    const float* fe_w1 = (const float*)d_in[15];
    const float* fe_b1 = (const float*)d_in[16];
    const float* fe_w2 = (const float*)d_in[17];
    const float* fe_b2 = (const float*)d_in[18];

    float* scratch = nullptr;
    cudaGetSymbolAddress((void**)&scratch, g_scratch);
    float* tmp  = scratch + OFF_TMP;
    float* h    = scratch + OFF_H;
    float* K    = scratch + OFF_K;
    float* V    = scratch + OFF_V;
    float* S    = scratch + OFF_S;
    float* P    = scratch + OFF_S;    // K-split partials when S dead
    float* P2   = scratch + OFF_P2;   // attV partials (S live)
    float* attc = scratch + OFF_ATTC;
    float* t2   = scratch + OFF_T2;
    float* ABuf = scratch + OFF_AB;

    float* x2   = (float*)d_out;
    float* edge = (float*)d_out + NM * DD;

    dim3 gb(128);
    const int MN4 = NM * DD / 4;   // 32768 float4
    const int NC4 = DD / 4;        // 32

    // 1) f_node hidden: relu((x+te) @ fn_w1 + fn_b1)  [1024,64]@[64,256]
    gemm_k<F_TE | F_RELU | F_BIAS, 1><<<dim3(2, 16, 1), gb>>>(
        x, fn_w1, fn_b1, nullptr, tmp, DIN, 2 * DD, 2 * DD, 0, 0, 0, 1, 0, 0, 0);
    // 2) h = tmp @ fn_w2 + fn_b2 — K-split 4 + reduce
    gemm_k<0, 4><<<dim3(1, 16, 4), gb>>>(
        tmp, fn_w2, nullptr, nullptr, P, 2 * DD, DD, DD, 0, 0, 0, 1, 0, 0,
        (int64_t)NM * DD);
    reduce_k<F_BIAS, 4><<<128, 256>>>((const float4*)P, fn_b2, (float4*)h, MN4, NC4);
    // 3) fused K/Q/V over 24 (which,head) pairs
    kqv_k<<<dim3(1, 16, 24), gb>>>(h, wk, bk, wq, bq, wv, bv, K);
    // 4) scores = leaky(K @ Q^T), z = h*2+n
    gemm_k<F_TRANSB | F_LEAKY, 1><<<dim3(4, 8, HH * NB), gb>>>(
        K, K + HH * NM * DD /*Q*/, nullptr, nullptr, S,
        DD, MM, MM, (int64_t)MM * DD, (int64_t)MM * DD, 0,
        1, (int64_t)MM * MM, 0, 0);
    // 5) softmax rows
    softmax_k<<<HH * NB * MM, 256>>>(S);
    // 6) att = alpha @ V — K-split 2, partials normal layout, then leaky+concat
    gemm_k<0, 2><<<dim3(1, 8, HH * NB * 2), gb>>>(
        S, V, nullptr, nullptr, P2,
        MM, DD, DD, (int64_t)MM * MM, (int64_t)MM * DD, 0,
        1, (int64_t)MM * DD, 0, (int64_t)HH * NB * MM * DD);
    reduce_att_k<<<1024, 256>>>((const float4*)P2, (float4*)attc);
    // 7) f_v hidden — K-split 16 + reduce (bias+relu)
    gemm_k<0, 16><<<dim3(1, 16, 16), gb>>>(
        attc, fv_w1, nullptr, nullptr, P, HH * DD, DD, DD, 0, 0, 0, 1, 0, 0,
        (int64_t)NM * DD);
    reduce_k<F_BIAS | F_RELU, 16><<<128, 256>>>((const float4*)P, fv_b1, (float4*)t2,
                                                MN4, NC4);
    // 8) x2 = t2 @ fv_w2 + fv_b2 + h
    gemm_k<F_BIAS | F_ADD, 1><<<dim3(1, 16, 1), gb>>>(
        t2, fv_w2, fv_b2, h, x2, DD, DD, DD, 0, 0, 0, 1, 0, 0, 0);
    // 9) A = x2 @ fe_w1[:128]; B = x2 @ fe_w1[128:]
    gemm_k<0, 1><<<dim3(1, 16, 2), gb>>>(
        x2, fe_w1, nullptr, nullptr, ABuf, DD, DD, DD,
        0, (int64_t)DD * DD, 0, 1, (int64_t)NM * DD, 0, 0);
    // 10) edge
    edge_k<<<dim3(16, 16, NB), 256>>>(ABuf, fe_b1, fe_w2, fe_b2, edge);
}

// round 5
// speedup vs baseline: 1.6003x; 1.6003x over previous
#include <cuda_runtime.h>
#include <math.h>
#include <stdint.h>

#define NB 2
#define MM 512
#define DD 128
#define HH 8
#define DIN 64
#define NM (NB*MM)   // 1024

typedef unsigned long long u64;

// ---------------- packed f32x2 helpers --------------------------------------------
__device__ __forceinline__ u64 pk2(float lo, float hi) {
    u64 r; asm("mov.b64 %0, {%1,%2};" : "=l"(r) : "f"(lo), "f"(hi)); return r;
}
__device__ __forceinline__ void fma2(u64& d, u64 a, u64 b) {
    asm("fma.rn.f32x2 %0, %1, %2, %0;" : "+l"(d) : "l"(a), "l"(b));
}
__device__ __forceinline__ float2 up2(u64 v) {
    float lo, hi; asm("mov.b64 {%0,%1}, %2;" : "=f"(lo), "=f"(hi) : "l"(v));
    return make_float2(lo, hi);
}

// ---------------- scratch ---------------------------------------------------------
#define OFF_TMP  0
#define OFF_H    (OFF_TMP + NM*2*DD)
#define OFF_K    (OFF_H   + NM*DD)
#define OFF_Q    (OFF_K   + HH*NM*DD)
#define OFF_V    (OFF_Q   + HH*NM*DD)
#define OFF_S    (OFF_V   + HH*NM*DD)            // [H*N,M,M]; doubles as K-split partials
#define OFF_ATTC (OFF_S   + HH*NB*MM*MM)         // [NM, H*D]
#define OFF_T2   (OFF_ATTC+ HH*NM*DD)
#define OFF_AB   (OFF_T2  + NM*DD)
#define OFF_P2   (OFF_AB  + 2*NM*DD)             // attV K-split partials [4][HN][M][D]
#define SCRATCH_TOTAL (OFF_P2 + 4*HH*NB*MM*DD)

__device__ float g_scratch[SCRATCH_TOTAL];

#define F_TRANSB 1
#define F_RELU   2
#define F_LEAKY  4
#define F_TE     8
#define F_BIAS   16
#define F_ADD    32

// ---------------- FFMA2 GEMM body, duplicated-A smem -------------------------------
// tile 64(M) x 128(N), 128 threads, thread tile 8x8.
// As stores each A value twice: As[k][2m]=As[k][2m+1]=A[m][k] -> dup (a,a) pairs
// load as u64 directly (ty-broadcast, conflict-free).
// Bs natural [k][n] -> natural column pairs load as u64 directly.
// Inner loop per k: 6x LDS.128 + 32x fma.f32x2, zero packs.
template<int F>
__device__ __forceinline__ void gemm_body(
    const float* __restrict__ A, const float* __restrict__ B,
    const float* __restrict__ bias, const float* __restrict__ addsrc,
    float* __restrict__ C, int Kd, int Nc, int ldc, int ktb, int kte)
{
    __shared__ float As[2][16][128];
    __shared__ float Bs[2][16][128];
    int tid = threadIdx.x;
    int tx = tid & 15, ty = tid >> 4;
    int m0 = blockIdx.y << 6, n0 = blockIdx.x << 7;

    // A loader: 64x16 tile, thread = (row=tid>>1, k-chunk=(tid&1)*8)
    int ar = tid >> 1, ac = (tid & 1) << 3;
    const float* Ap = A + (int64_t)(m0 + ar) * Kd + ac;
    // B loader
    int bk = tid >> 3, bc = (tid & 7) << 4;
    const float* Bp = (F & F_TRANSB)
        ? B + (int64_t)(n0 + tid) * Kd
        : B + (int64_t)bk * Nc + n0 + bc;

    u64 acc[8][4];   // [row][col-pair]
    #pragma unroll
    for (int i = 0; i < 8; i++)
        #pragma unroll
        for (int p = 0; p < 4; p++) acc[i][p] = 0ull;

    float4 la0, la1, lb[4];

    auto loadG = [&](int kt) {
        la0 = *(const float4*)(Ap + kt * 16);
        la1 = *(const float4*)(Ap + kt * 16 + 4);
        if (F & F_TE) {
            int kb = kt * 16 + ac;
            la0.x += sinf((float)(kb + 0) * (5.0f / 63.0f));
            la0.y += sinf((float)(kb + 1) * (5.0f / 63.0f));
            la0.z += sinf((float)(kb + 2) * (5.0f / 63.0f));
            la0.w += sinf((float)(kb + 3) * (5.0f / 63.0f));
            la1.x += sinf((float)(kb + 4) * (5.0f / 63.0f));
            la1.y += sinf((float)(kb + 5) * (5.0f / 63.0f));
            la1.z += sinf((float)(kb + 6) * (5.0f / 63.0f));
            la1.w += sinf((float)(kb + 7) * (5.0f / 63.0f));
        }
        if (F & F_TRANSB) {
            #pragma unroll
            for (int u = 0; u < 4; u++)
                lb[u] = *(const float4*)(Bp + kt * 16 + 4 * u);
        } else {
            #pragma unroll
            for (int u = 0; u < 4; u++)
                lb[u] = *(const float4*)(Bp + (int64_t)(kt * 16) * Nc + 4 * u);
        }
    };
    auto storeS = [&](int bf) {
        // duplicated A: 8 STS.64
        *(u64*)&As[bf][ac + 0][2 * ar] = pk2(la0.x, la0.x);
        *(u64*)&As[bf][ac + 1][2 * ar] = pk2(la0.y, la0.y);
        *(u64*)&As[bf][ac + 2][2 * ar] = pk2(la0.z, la0.z);
        *(u64*)&As[bf][ac + 3][2 * ar] = pk2(la0.w, la0.w);
        *(u64*)&As[bf][ac + 4][2 * ar] = pk2(la1.x, la1.x);
        *(u64*)&As[bf][ac + 5][2 * ar] = pk2(la1.y, la1.y);
        *(u64*)&As[bf][ac + 6][2 * ar] = pk2(la1.z, la1.z);
        *(u64*)&As[bf][ac + 7][2 * ar] = pk2(la1.w, la1.w);
        if (F & F_TRANSB) {
            #pragma unroll
            for (int u = 0; u < 4; u++) {
                Bs[bf][4 * u + 0][tid] = lb[u].x; Bs[bf][4 * u + 1][tid] = lb[u].y;
                Bs[bf][4 * u + 2][tid] = lb[u].z; Bs[bf][4 * u + 3][tid] = lb[u].w;
            }
        } else {
            #pragma unroll
            for (int u = 0; u < 4; u++)
                *(float4*)&Bs[bf][bk][bc + 4 * u] = lb[u];
        }
    };

    loadG(ktb); storeS(0); __syncthreads();
    int buf = 0;
    for (int kt = ktb; kt < kte; kt++) {
        bool more = (kt + 1 < kte);
        if (more) loadG(kt + 1);
        #pragma unroll
        for (int kk = 0; kk < 16; kk++) {
            ulonglong2 aL0 = *(const ulonglong2*)&As[buf][kk][(ty << 3)];
            ulonglong2 aL1 = *(const ulonglong2*)&As[buf][kk][(ty << 3) + 4];
            ulonglong2 aH0 = *(const ulonglong2*)&As[buf][kk][64 + (ty << 3)];
            ulonglong2 aH1 = *(const ulonglong2*)&As[buf][kk][64 + (ty << 3) + 4];
            ulonglong2 b0  = *(const ulonglong2*)&Bs[buf][kk][(tx << 2)];
            ulonglong2 b1  = *(const ulonglong2*)&Bs[buf][kk][64 + (tx << 2)];
            u64 ad[8] = {aL0.x, aL0.y, aL1.x, aL1.y, aH0.x, aH0.y, aH1.x, aH1.y};
            u64 bd[4] = {b0.x, b0.y, b1.x, b1.y};
            #pragma unroll
            for (int i = 0; i < 8; i++) {
                fma2(acc[i][0], ad[i], bd[0]);
                fma2(acc[i][1], ad[i], bd[1]);
                fma2(acc[i][2], ad[i], bd[2]);
                fma2(acc[i][3], ad[i], bd[3]);
            }
        }
        if (more) { storeS(buf ^ 1); __syncthreads(); buf ^= 1; }
    }

    // ---- epilogue: rows {4ty..+3, 32+4ty..+3}
    #pragma unroll
    for (int i = 0; i < 8; i++) {
        int row = m0 + ((i < 4) ? ((ty << 2) + i) : (32 + (ty << 2) + i - 4));
        float2 q0 = up2(acc[i][0]), q1 = up2(acc[i][1]);
        float2 q2 = up2(acc[i][2]), q3 = up2(acc[i][3]);
        float o[8] = {q0.x, q0.y, q1.x, q1.y, q2.x, q2.y, q3.x, q3.y};
        #pragma unroll
        for (int j = 0; j < 8; j++) {
            int col = n0 + ((j < 4) ? ((tx << 2) + j) : (64 + (tx << 2) + j - 4));
            float v = o[j];
            if (F & F_BIAS)  v += bias[col];
            if (F & F_RELU)  v = fmaxf(v, 0.0f);
            if (F & F_LEAKY) v = (v >= 0.0f) ? v : 0.2f * v;
            if (F & F_ADD)   v += addsrc[(int64_t)row * ldc + col];
            o[j] = v;
        }
        *(float4*)&C[(int64_t)row * ldc + n0 + (tx << 2)]      = make_float4(o[0], o[1], o[2], o[3]);
        *(float4*)&C[(int64_t)row * ldc + n0 + 64 + (tx << 2)] = make_float4(o[4], o[5], o[6], o[7]);
    }
}

// ---------------- generic wrapper (with optional K-split) --------------------------
template<int F, int NKS>
__global__ __launch_bounds__(128, 4)
void gemm_k(const float* __restrict__ A, const float* __restrict__ B,
            const float* __restrict__ bias, const float* __restrict__ addsrc,
            float* __restrict__ C, int Kd, int Nc, int ldc,
            int64_t sA, int64_t sB, int64_t sBias,
            int zdiv, int64_t sC1, int64_t sC2, int64_t sPart)
{
    int zz = blockIdx.z;
    int z = zz / NKS, ks = zz % NKS;
    int ktn = Kd >> 4;
    int ktb = ks * (ktn / NKS), kte = ktb + ktn / NKS;
    const float* bz = (F & F_BIAS) ? bias + sBias * z : nullptr;
    float* Cz = C + (int64_t)(z / zdiv) * sC1 + (int64_t)(z % zdiv) * sC2
                  + (int64_t)ks * sPart;
    gemm_body<F>(A + sA * z, B + sB * z, bz, addsrc, Cz, Kd, Nc, ldc, ktb, kte);
}

// ---------------- fused K/Q/V wrapper: z = which*8 + head --------------------------
__global__ __launch_bounds__(128, 4)
void kqv_k(const float* __restrict__ h,
           const float* __restrict__ wk, const float* __restrict__ bk,
           const float* __restrict__ wq, const float* __restrict__ bq,
           const float* __restrict__ wv, const float* __restrict__ bv,
           float* __restrict__ out)
{
    int z = blockIdx.z;
    int which = z >> 3, head = z & 7;
    const float* W  = (which == 0) ? wk : (which == 1) ? wq : wv;
    const float* Bi = (which == 0) ? bk : (which == 1) ? bq : bv;
    W  += (int64_t)head * DD * DD;
    Bi += (int64_t)head * DD;
    float* C = out + ((int64_t)which * HH + head) * NM * DD;
    gemm_body<F_BIAS>(h, W, Bi, nullptr, C, DD, DD, DD, 0, DD / 16);
}

// ---------------- K-split reduce: C = act(sum_ks P + bias) (+ add) -----------------
template<int F, int NKS>
__global__ __launch_bounds__(256)
void reduce_k(const float4* __restrict__ P, const float* __restrict__ bias,
              const float4* __restrict__ addsrc, float4* __restrict__ C,
              int totalf4, int ncf4)
{
    int idx = blockIdx.x * 256 + threadIdx.x;
    if (idx >= totalf4) return;
    float4 s = P[idx];
    #pragma unroll
    for (int k = 1; k < NKS; k++) {
        float4 t = P[idx + (int64_t)k * totalf4];
        s.x += t.x; s.y += t.y; s.z += t.z; s.w += t.w;
    }
    if (F & F_BIAS) {
        float4 b = ((const float4*)bias)[idx % ncf4];
        s.x += b.x; s.y += b.y; s.z += b.z; s.w += b.w;
    }
    if (F & F_RELU) {
        s.x = fmaxf(s.x, 0.f); s.y = fmaxf(s.y, 0.f);
        s.z = fmaxf(s.z, 0.f); s.w = fmaxf(s.w, 0.f);
    }
    if (F & F_ADD) {
        float4 a = addsrc[idx];
        s.x += a.x; s.y += a.y; s.z += a.z; s.w += a.w;
    }
    C[idx] = s;
}

// ---------------- attV reduce: sum 4 partials, leaky, write concat layout ----------
__global__ __launch_bounds__(256)
void reduce_att_k(const float4* __restrict__ P, float4* __restrict__ out)
{
    const int tot = HH * NB * MM * DD / 4;   // 262144
    int idx = blockIdx.x * 256 + threadIdx.x;
    if (idx >= tot) return;
    float4 s = P[idx];
    #pragma unroll
    for (int k = 1; k < 4; k++) {
        float4 t = P[idx + (int64_t)k * tot];
        s.x += t.x; s.y += t.y; s.z += t.z; s.w += t.w;
    }
    s.x = (s.x >= 0.f) ? s.x : 0.2f * s.x;
    s.y = (s.y >= 0.f) ? s.y : 0.2f * s.y;
    s.z = (s.z >= 0.f) ? s.z : 0.2f * s.z;
    s.w = (s.w >= 0.f) ? s.w : 0.2f * s.w;
    // P layout: [z=h*2+n][m][d]; out: [n][m][h*32 + d4] (f4 units, row = 256 f4)
    int z   = idx >> 14;
    int rem = idx & 16383;
    int m   = rem >> 5;
    int d4  = rem & 31;
    int hh  = z >> 1, n = z & 1;
    out[(int64_t)(n * MM + m) * (HH * DD / 4) + hh * 32 + d4] = s;
}

// ---------------- row softmax over 512 cols ---------------------------------------
__global__ __launch_bounds__(256)
void softmax_k(float* __restrict__ data)
{
    __shared__ float red[8];
    float* p = data + (int64_t)blockIdx.x * MM;
    int t = threadIdx.x;
    float v0 = p[t], v1 = p[t + 256];
    float m = fmaxf(v0, v1);
    #pragma unroll
    for (int o = 16; o; o >>= 1) m = fmaxf(m, __shfl_xor_sync(0xffffffffu, m, o));
    if ((t & 31) == 0) red[t >> 5] = m;
    __syncthreads();
    float bm = red[0];
    #pragma unroll
    for (int w = 1; w < 8; w++) bm = fmaxf(bm, red[w]);
    float e0 = __expf(v0 - bm), e1 = __expf(v1 - bm);
    float s = e0 + e1;
    #pragma unroll
    for (int o = 16; o; o >>= 1) s += __shfl_xor_sync(0xffffffffu, s, o);
    __syncthreads();
    if ((t & 31) == 0) red[t >> 5] = s;
    __syncthreads();
    float bs = red[0];
    #pragma unroll
    for (int w = 1; w < 8; w++) bs += red[w];
    float inv = 1.0f / bs;
    p[t] = e0 * inv;
    p[t + 256] = e1 * inv;
}

// ---------------- edge kernel ------------------------------------------------------
__global__ __launch_bounds__(256)
void edge_k(const float* __restrict__ AB, const float* __restrict__ b1,
            const float* __restrict__ w2, const float* __restrict__ b2,
            float* __restrict__ out)
{
    __shared__ float Ast[DD][36];
    __shared__ float Bst[DD][36];
    __shared__ float w2s[DD];
    int n  = blockIdx.z;
    int i0 = blockIdx.y << 5, j0 = blockIdx.x << 5;
    const float* Ab = AB + ((int64_t)n * MM + i0) * DD;
    const float* Bb = AB + (int64_t)NM * DD + ((int64_t)n * MM + j0) * DD;
    int t = threadIdx.x;
    if (t < DD) w2s[t] = w2[t];
    #pragma unroll
    for (int c = 0; c < 4; c++) {
        int idx = t + (c << 8);
        int r  = idx >> 5;
        int d4 = (idx & 31) << 2;
        float4 a = *(const float4*)(Ab + r * DD + d4);
        Ast[d4 + 0][r] = a.x; Ast[d4 + 1][r] = a.y;
        Ast[d4 + 2][r] = a.z; Ast[d4 + 3][r] = a.w;
        float4 bvl = *(const float4*)(Bb + r * DD + d4);
        float4 bb  = *(const float4*)(b1 + d4);
        Bst[d4 + 0][r] = bvl.x + bb.x; Bst[d4 + 1][r] = bvl.y + bb.y;
        Bst[d4 + 2][r] = bvl.z + bb.z; Bst[d4 + 3][r] = bvl.w + bb.w;
    }
    __syncthreads();
    int tx = t & 15, ty = t >> 4;
    float a00 = 0.f, a01 = 0.f, a10 = 0.f, a11 = 0.f;
    #pragma unroll 8
    for (int d = 0; d < DD; d++) {
        float2 av = *(const float2*)&Ast[d][ty << 1];
        float2 bv = *(const float2*)&Bst[d][tx << 1];
        float w = w2s[d];
        a00 = fmaf(fmaxf(av.x + bv.x, 0.f), w, a00);
        a01 = fmaf(fmaxf(av.x + bv.y, 0.f), w, a01);
        a10 = fmaf(fmaxf(av.y + bv.x, 0.f), w, a10);
        a11 = fmaf(fmaxf(av.y + bv.y, 0.f), w, a11);
    }
    float bb = b2[0];
    const float sc = 1.0f / (float)MM;
    int i = i0 + (ty << 1), j = j0 + (tx << 1);
    float* o = out + ((int64_t)n * MM + i) * MM + j;
    o[0]      = (a00 + bb) * sc;
    o[1]      = (a01 + bb) * sc;
    o[MM]     = (a10 + bb) * sc;
    o[MM + 1] = (a11 + bb) * sc;
}

// ---------------- host launcher ----------------------------------------------------
extern "C" void kernel_launch(void* const* d_in, const int* in_sizes, int n_in,
                              void* d_out, int out_size)
{
    const float* x     = (const float*)d_in[0];
    const float* fn_w1 = (const float*)d_in[1];
    const float* fn_b1 = (const float*)d_in[2];
    const float* fn_w2 = (const float*)d_in[3];
    const float* fn_b2 = (const float*)d_in[4];
    const float* wk    = (const float*)d_in[5];
    const float* bk    = (const float*)d_in[6];
    const float* wq    = (const float*)d_in[7];
    const float* bq    = (const float*)d_in[8];
    const float* wv    = (const float*)d_in[9];
    const float* bv    = (const float*)d_in[10];
    const float* fv_w1 = (const float*)d_in[11];
    const float* fv_b1 = (const float*)d_in[12];
    const float* fv_w2 = (const float*)d_in[13];
    const float* fv_b2 = (const float*)d_in[14];
    const float* fe_w1 = (const float*)d_in[15];
    const float* fe_b1 = (const float*)d_in[16];
    const float* fe_w2 = (const float*)d_in[17];
    const float* fe_b2 = (const float*)d_in[18];

    float* scratch = nullptr;
    cudaGetSymbolAddress((void**)&scratch, g_scratch);
    float* tmp  = scratch + OFF_TMP;
    float* h    = scratch + OFF_H;
    float* K    = scratch + OFF_K;
    float* V    = scratch + OFF_V;
    float* S    = scratch + OFF_S;
    float* P    = scratch + OFF_S;    // K-split partials while S is dead
    float* P2   = scratch + OFF_P2;   // attV partials (S live)
    float* attc = scratch + OFF_ATTC;
    float* t2   = scratch + OFF_T2;
    float* ABuf = scratch + OFF_AB;

    float* x2   = (float*)d_out;
    float* edge = (float*)d_out + NM * DD;

    dim3 gb(128);
    const int MN4  = NM * DD / 4;       // 32768
    const int MN24 = NM * 2 * DD / 4;   // 65536
    const int NC4  = DD / 4;            // 32
    const int NC24 = 2 * DD / 4;        // 64

    // 1) f_node hidden: relu((x+te)@fn_w1+fn_b1) — K-split 2 + reduce
    gemm_k<F_TE, 2><<<dim3(2, 16, 2), gb>>>(
        x, fn_w1, nullptr, nullptr, P, DIN, 2 * DD, 2 * DD, 0, 0, 0, 1, 0, 0,
        (int64_t)NM * 2 * DD);
    reduce_k<F_BIAS | F_RELU, 2><<<256, 256>>>(
        (const float4*)P, fn_b1, nullptr, (float4*)tmp, MN24, NC24);
    // 2) h = tmp @ fn_w2 + fn_b2 — K-split 8 + reduce (partials after f_node1's)
    {
        float* Ph = P + NM * 2 * DD * 2;   // still inside S region
        gemm_k<0, 8><<<dim3(1, 16, 8), gb>>>(
            tmp, fn_w2, nullptr, nullptr, Ph, 2 * DD, DD, DD, 0, 0, 0, 1, 0, 0,
            (int64_t)NM * DD);
        reduce_k<F_BIAS, 8><<<128, 256>>>(
            (const float4*)Ph, fn_b2, nullptr, (float4*)h, MN4, NC4);
    }
    // 3) fused K/Q/V over 24 (which,head) pairs
    kqv_k<<<dim3(1, 16, 24), gb>>>(h, wk, bk, wq, bq, wv, bv, K);
    // 4) scores = leaky(K @ Q^T), z = h*2+n
    gemm_k<F_TRANSB | F_LEAKY, 1><<<dim3(4, 8, HH * NB), gb>>>(
        K, K + HH * NM * DD /*Q*/, nullptr, nullptr, S,
        DD, MM, MM, (int64_t)MM * DD, (int64_t)MM * DD, 0,
        1, (int64_t)MM * MM, 0, 0);
    // 5) softmax rows
    softmax_k<<<HH * NB * MM, 256>>>(S);
    // 6) att = alpha @ V — K-split 4 + leaky/concat reduce
    gemm_k<0, 4><<<dim3(1, 8, HH * NB * 4), gb>>>(
        S, V, nullptr, nullptr, P2,
        MM, DD, DD, (int64_t)MM * MM, (int64_t)MM * DD, 0,
        1, (int64_t)MM * DD, 0, (int64_t)HH * NB * MM * DD);
    reduce_att_k<<<1024, 256>>>((const float4*)P2, (float4*)attc);
    // 7) f_v hidden — K-split 16 + reduce (bias+relu)
    gemm_k<0, 16><<<dim3(1, 16, 16), gb>>>(
        attc, fv_w1, nullptr, nullptr, P, HH * DD, DD, DD, 0, 0, 0, 1, 0, 0,
        (int64_t)NM * DD);
    reduce_k<F_BIAS | F_RELU, 16><<<128, 256>>>(
        (const float4*)P, fv_b1, nullptr, (float4*)t2, MN4, NC4);
    // 8) x2 = t2 @ fv_w2 + fv_b2 + h — K-split 4 + reduce(bias,add h)
    gemm_k<0, 4><<<dim3(1, 16, 4), gb>>>(
        t2, fv_w2, nullptr, nullptr, P, DD, DD, DD, 0, 0, 0, 1, 0, 0,
        (int64_t)NM * DD);
    reduce_k<F_BIAS | F_ADD, 4><<<128, 256>>>(
        (const float4*)P, fv_b2, (const float4*)h, (float4*)x2, MN4, NC4);
    // 9) A/B = x2 @ fe_w1 halves — z=2 batched, K-split 2 + reduce
    gemm_k<0, 2><<<dim3(1, 16, 4), gb>>>(
        x2, fe_w1, nullptr, nullptr, P, DD, DD, DD,
        0, (int64_t)DD * DD, 0, 1, (int64_t)NM * DD, 0, (int64_t)2 * NM * DD);
    reduce_k<0, 2><<<256, 256>>>(
        (const float4*)P, nullptr, nullptr, (float4*)ABuf, 2 * MN4, NC4);
    // 10) edge
    edge_k<<<dim3(16, 16, NB), 256>>>(ABuf, fe_b1, fe_w2, fe_b2, edge);
}

// round 7
// speedup vs baseline: 2.6651x; 1.6654x over previous
#include <cuda_runtime.h>
#include <cuda_bf16.h>
#include <math.h>
#include <stdint.h>

#define NB 2
#define MM 512
#define DD 128
#define HH 8
#define DIN 64
#define NM (NB*MM)   // 1024

typedef unsigned long long u64;

// ================= packed f32x2 helpers (scalar GEMM path) ========================
__device__ __forceinline__ u64 pk2(float lo, float hi) {
    u64 r; asm("mov.b64 %0, {%1,%2};" : "=l"(r) : "f"(lo), "f"(hi)); return r;
}
__device__ __forceinline__ void fma2(u64& d, u64 a, u64 b) {
    asm("fma.rn.f32x2 %0, %1, %2, %0;" : "+l"(d) : "l"(a), "l"(b));
}
__device__ __forceinline__ float2 up2(u64 v) {
    float lo, hi; asm("mov.b64 {%0,%1}, %2;" : "=f"(lo), "=f"(hi) : "l"(v));
    return make_float2(lo, hi);
}

// ================= mma.sync helpers ================================================
__device__ __forceinline__ uint32_t smem_to_u32(const void* p) {
    uint32_t a;
    asm("{ .reg .u64 t; cvta.to.shared.u64 t, %1; cvt.u32.u64 %0, t; }" : "=r"(a) : "l"(p));
    return a;
}
__device__ __forceinline__ void ldsm4(uint32_t& r0, uint32_t& r1, uint32_t& r2,
                                      uint32_t& r3, uint32_t addr) {
    asm volatile("ldmatrix.sync.aligned.m8n8.x4.shared.b16 {%0,%1,%2,%3}, [%4];"
                 : "=r"(r0), "=r"(r1), "=r"(r2), "=r"(r3) : "r"(addr));
}
__device__ __forceinline__ void mma16816(float* d, uint32_t a0, uint32_t a1,
                                         uint32_t a2, uint32_t a3,
                                         uint32_t b0, uint32_t b1) {
    asm volatile("mma.sync.aligned.m16n8k16.row.col.f32.bf16.bf16.f32 "
                 "{%0,%1,%2,%3},{%4,%5,%6,%7},{%8,%9},{%0,%1,%2,%3};"
                 : "+f"(d[0]), "+f"(d[1]), "+f"(d[2]), "+f"(d[3])
                 : "r"(a0), "r"(a1), "r"(a2), "r"(a3), "r"(b0), "r"(b1));
}

#define KT 32
#define SPAD 40   // smem row stride (bf16) — pad for conflict-free ldmatrix

// C[128,128] += A[128,K] @ B[128,K]^T over nkt k-tiles of 32. 256 thr, 8 warps (2x4),
// warp tile 64x32, acc[mf][nf][4].
__device__ __forceinline__ void mma_loop(
    const __nv_bfloat16* __restrict__ A, int lda,
    const __nv_bfloat16* __restrict__ B, int ldb,
    int nkt, float acc[4][4][4])
{
    __shared__ __nv_bfloat16 As[128][SPAD];
    __shared__ __nv_bfloat16 Bs[128][SPAD];
    int tid = threadIdx.x, lane = tid & 31, wid = tid >> 5;
    int wm = wid >> 2, wn = wid & 3;

    int lrow = tid >> 1, lcol = (tid & 1) << 4;   // G->S: each thread 2x16B, one row
    const __nv_bfloat16* Ag = A + (int64_t)lrow * lda + lcol;
    const __nv_bfloat16* Bg = B + (int64_t)lrow * ldb + lcol;

    uint32_t asb = smem_to_u32(As), bsb = smem_to_u32(Bs);
    int arow = ((lane >> 3) & 1) * 8 + (lane & 7);
    int acol = ((lane >> 4) & 1) * 8;
    int brow = ((lane >> 4) & 1) * 8 + (lane & 7);
    int bcol = ((lane >> 3) & 1) * 8;

    for (int kt = 0; kt < nkt; kt++) {
        __syncthreads();
        *(uint4*)&As[lrow][lcol]     = *(const uint4*)(Ag + kt * KT);
        *(uint4*)&As[lrow][lcol + 8] = *(const uint4*)(Ag + kt * KT + 8);
        *(uint4*)&Bs[lrow][lcol]     = *(const uint4*)(Bg + kt * KT);
        *(uint4*)&Bs[lrow][lcol + 8] = *(const uint4*)(Bg + kt * KT + 8);
        __syncthreads();
        #pragma unroll
        for (int kf = 0; kf < 2; kf++) {
            uint32_t a[4][4];
            #pragma unroll
            for (int mf = 0; mf < 4; mf++)
                ldsm4(a[mf][0], a[mf][1], a[mf][2], a[mf][3],
                      asb + ((wm * 64 + mf * 16 + arow) * SPAD + kf * 16 + acol) * 2);
            uint32_t b[2][4];
            #pragma unroll
            for (int p = 0; p < 2; p++)
                ldsm4(b[p][0], b[p][1], b[p][2], b[p][3],
                      bsb + ((wn * 32 + p * 16 + brow) * SPAD + kf * 16 + bcol) * 2);
            #pragma unroll
            for (int mf = 0; mf < 4; mf++)
                #pragma unroll
                for (int nf = 0; nf < 4; nf++)
                    mma16816(acc[mf][nf], a[mf][0], a[mf][1], a[mf][2], a[mf][3],
                             b[nf >> 1][(nf & 1) * 2], b[nf >> 1][(nf & 1) * 2 + 1]);
        }
    }
}

// ================= scratch =========================================================
#define OFF_TMP   0
#define OFF_H     (OFF_TMP + NM*2*DD)
#define OFF_S     (OFF_H   + NM*DD)              // fp32 scores; also scalar K-split partials
#define OFF_ATTC  (OFF_S   + HH*NB*MM*MM)
#define OFF_T2    (OFF_ATTC+ HH*NM*DD)
#define OFF_AB    (OFF_T2  + NM*DD)
#define OFF_HB    (OFF_AB  + 2*NM*DD)            // bf16 h   [1024][128]
#define OFF_WTB   (OFF_HB  + NM*DD/2)            // bf16 W^T [3][8][128][128]
#define OFF_KB    (OFF_WTB + 3*HH*DD*DD/2)       // bf16 K   [8][1024][128]
#define OFF_QB    (OFF_KB  + HH*NM*DD/2)
#define OFF_VTB   (OFF_QB  + HH*NM*DD/2)         // bf16 V^T [16][128][512]
#define OFF_ALB   (OFF_VTB + HH*NM*DD/2)         // bf16 alpha [16][512][512]
#define OFF_P2    (OFF_ALB + HH*NB*MM*MM/2)      // attV partials [2][16][512][128] fp32
#define SCRATCH_TOTAL (OFF_P2 + 2*HH*NB*MM*DD)

__device__ float g_scratch[SCRATCH_TOTAL];

#define F_TRANSB 1
#define F_RELU   2
#define F_LEAKY  4
#define F_TE     8
#define F_BIAS   16
#define F_ADD    32

// ================= scalar FFMA2 GEMM (R5, proven) ==================================
template<int F>
__device__ __forceinline__ void gemm_body(
    const float* __restrict__ A, const float* __restrict__ B,
    const float* __restrict__ bias, const float* __restrict__ addsrc,
    float* __restrict__ C, int Kd, int Nc, int ldc, int ktb, int kte)
{
    __shared__ float As[2][16][128];
    __shared__ float Bs[2][16][128];
    int tid = threadIdx.x;
    int tx = tid & 15, ty = tid >> 4;
    int m0 = blockIdx.y << 6, n0 = blockIdx.x << 7;

    int ar = tid >> 1, ac = (tid & 1) << 3;
    const float* Ap = A + (int64_t)(m0 + ar) * Kd + ac;
    int bk = tid >> 3, bc = (tid & 7) << 4;
    const float* Bp = (F & F_TRANSB)
        ? B + (int64_t)(n0 + tid) * Kd
        : B + (int64_t)bk * Nc + n0 + bc;

    u64 acc[8][4];
    #pragma unroll
    for (int i = 0; i < 8; i++)
        #pragma unroll
        for (int p = 0; p < 4; p++) acc[i][p] = 0ull;

    float4 la0, la1, lb[4];
    auto loadG = [&](int kt) {
        la0 = *(const float4*)(Ap + kt * 16);
        la1 = *(const float4*)(Ap + kt * 16 + 4);
        if (F & F_TE) {
            int kb = kt * 16 + ac;
            la0.x += sinf((float)(kb + 0) * (5.0f / 63.0f));
            la0.y += sinf((float)(kb + 1) * (5.0f / 63.0f));
            la0.z += sinf((float)(kb + 2) * (5.0f / 63.0f));
            la0.w += sinf((float)(kb + 3) * (5.0f / 63.0f));
            la1.x += sinf((float)(kb + 4) * (5.0f / 63.0f));
            la1.y += sinf((float)(kb + 5) * (5.0f / 63.0f));
            la1.z += sinf((float)(kb + 6) * (5.0f / 63.0f));
            la1.w += sinf((float)(kb + 7) * (5.0f / 63.0f));
        }
        if (F & F_TRANSB) {
            #pragma unroll
            for (int u = 0; u < 4; u++) lb[u] = *(const float4*)(Bp + kt * 16 + 4 * u);
        } else {
            #pragma unroll
            for (int u = 0; u < 4; u++) lb[u] = *(const float4*)(Bp + (int64_t)(kt * 16) * Nc + 4 * u);
        }
    };
    auto storeS = [&](int bf) {
        *(u64*)&As[bf][ac + 0][2 * ar] = pk2(la0.x, la0.x);
        *(u64*)&As[bf][ac + 1][2 * ar] = pk2(la0.y, la0.y);
        *(u64*)&As[bf][ac + 2][2 * ar] = pk2(la0.z, la0.z);
        *(u64*)&As[bf][ac + 3][2 * ar] = pk2(la0.w, la0.w);
        *(u64*)&As[bf][ac + 4][2 * ar] = pk2(la1.x, la1.x);
        *(u64*)&As[bf][ac + 5][2 * ar] = pk2(la1.y, la1.y);
        *(u64*)&As[bf][ac + 6][2 * ar] = pk2(la1.z, la1.z);
        *(u64*)&As[bf][ac + 7][2 * ar] = pk2(la1.w, la1.w);
        if (F & F_TRANSB) {
            #pragma unroll
            for (int u = 0; u < 4; u++) {
                Bs[bf][4 * u + 0][tid] = lb[u].x; Bs[bf][4 * u + 1][tid] = lb[u].y;
                Bs[bf][4 * u + 2][tid] = lb[u].z; Bs[bf][4 * u + 3][tid] = lb[u].w;
            }
        } else {
            #pragma unroll
            for (int u = 0; u < 4; u++) *(float4*)&Bs[bf][bk][bc + 4 * u] = lb[u];
        }
    };

    loadG(ktb); storeS(0); __syncthreads();
    int buf = 0;
    for (int kt = ktb; kt < kte; kt++) {
        bool more = (kt + 1 < kte);
        if (more) loadG(kt + 1);
        #pragma unroll
        for (int kk = 0; kk < 16; kk++) {
            ulonglong2 aL0 = *(const ulonglong2*)&As[buf][kk][(ty << 3)];
            ulonglong2 aL1 = *(const ulonglong2*)&As[buf][kk][(ty << 3) + 4];
            ulonglong2 aH0 = *(const ulonglong2*)&As[buf][kk][64 + (ty << 3)];
            ulonglong2 aH1 = *(const ulonglong2*)&As[buf][kk][64 + (ty << 3) + 4];
            ulonglong2 b0  = *(const ulonglong2*)&Bs[buf][kk][(tx << 2)];
            ulonglong2 b1  = *(const ulonglong2*)&Bs[buf][kk][64 + (tx << 2)];
            u64 ad[8] = {aL0.x, aL0.y, aL1.x, aL1.y, aH0.x, aH0.y, aH1.x, aH1.y};
            u64 bd[4] = {b0.x, b0.y, b1.x, b1.y};
            #pragma unroll
            for (int i = 0; i < 8; i++) {
                fma2(acc[i][0], ad[i], bd[0]);
                fma2(acc[i][1], ad[i], bd[1]);
                fma2(acc[i][2], ad[i], bd[2]);
                fma2(acc[i][3], ad[i], bd[3]);
            }
        }
        if (more) { storeS(buf ^ 1); __syncthreads(); buf ^= 1; }
    }

    #pragma unroll
    for (int i = 0; i < 8; i++) {
        int row = m0 + ((i < 4) ? ((ty << 2) + i) : (32 + (ty << 2) + i - 4));
        float2 q0 = up2(acc[i][0]), q1 = up2(acc[i][1]);
        float2 q2 = up2(acc[i][2]), q3 = up2(acc[i][3]);
        float o[8] = {q0.x, q0.y, q1.x, q1.y, q2.x, q2.y, q3.x, q3.y};
        #pragma unroll
        for (int j = 0; j < 8; j++) {
            int col = n0 + ((j < 4) ? ((tx << 2) + j) : (64 + (tx << 2) + j - 4));
            float v = o[j];
            if (F & F_BIAS)  v += bias[col];
            if (F & F_RELU)  v = fmaxf(v, 0.0f);
            if (F & F_LEAKY) v = (v >= 0.0f) ? v : 0.2f * v;
            if (F & F_ADD)   v += addsrc[(int64_t)row * ldc + col];
            o[j] = v;
        }
        *(float4*)&C[(int64_t)row * ldc + n0 + (tx << 2)]      = make_float4(o[0], o[1], o[2], o[3]);
        *(float4*)&C[(int64_t)row * ldc + n0 + 64 + (tx << 2)] = make_float4(o[4], o[5], o[6], o[7]);
    }
}

template<int F, int NKS>
__global__ __launch_bounds__(128, 4)
void gemm_k(const float* __restrict__ A, const float* __restrict__ B,
            const float* __restrict__ bias, const float* __restrict__ addsrc,
            float* __restrict__ C, int Kd, int Nc, int ldc,
            int64_t sA, int64_t sB, int64_t sBias,
            int zdiv, int64_t sC1, int64_t sC2, int64_t sPart)
{
    int zz = blockIdx.z;
    int z = zz / NKS, ks = zz % NKS;
    int ktn = Kd >> 4;
    int ktb = ks * (ktn / NKS), kte = ktb + ktn / NKS;
    const float* bz = (F & F_BIAS) ? bias + sBias * z : nullptr;
    float* Cz = C + (int64_t)(z / zdiv) * sC1 + (int64_t)(z % zdiv) * sC2
                  + (int64_t)ks * sPart;
    gemm_body<F>(A + sA * z, B + sB * z, bz, addsrc, Cz, Kd, Nc, ldc, ktb, kte);
}

template<int F, int NKS>
__global__ __launch_bounds__(256)
void reduce_k(const float4* __restrict__ P, const float* __restrict__ bias,
              const float4* __restrict__ addsrc, float4* __restrict__ C,
              int totalf4, int ncf4)
{
    int idx = blockIdx.x * 256 + threadIdx.x;
    if (idx >= totalf4) return;
    float4 s = P[idx];
    #pragma unroll
    for (int k = 1; k < NKS; k++) {
        float4 t = P[idx + (int64_t)k * totalf4];
        s.x += t.x; s.y += t.y; s.z += t.z; s.w += t.w;
    }
    if (F & F_BIAS) {
        float4 b = ((const float4*)bias)[idx % ncf4];
        s.x += b.x; s.y += b.y; s.z += b.z; s.w += b.w;
    }
    if (F & F_RELU) {
        s.x = fmaxf(s.x, 0.f); s.y = fmaxf(s.y, 0.f);
        s.z = fmaxf(s.z, 0.f); s.w = fmaxf(s.w, 0.f);
    }
    if (F & F_ADD) {
        float4 a = addsrc[idx];
        s.x += a.x; s.y += a.y; s.z += a.z; s.w += a.w;
    }
    C[idx] = s;
}

// ================= prep: h -> bf16, W -> bf16 transposed ===========================
__global__ __launch_bounds__(256)
void prep_k(const float* __restrict__ h,
            const float* __restrict__ wk, const float* __restrict__ wq,
            const float* __restrict__ wv,
            __nv_bfloat16* __restrict__ hb, __nv_bfloat16* __restrict__ wtb)
{
    int i = blockIdx.x * 256 + threadIdx.x;
    if (i < NM * DD) hb[i] = __float2bfloat16(h[i]);
    if (i < 3 * HH * DD * DD) {
        int w = i >> 17;
        int r = i & 131071;
        int hd = r >> 14; int rem = r & 16383;
        int n = rem >> 7, k = rem & 127;
        const float* src = (w == 0) ? wk : (w == 1) ? wq : wv;
        wtb[i] = __float2bfloat16(src[hd * 16384 + k * 128 + n]);
    }
}

// ================= KQV via mma.sync ================================================
// z = which*8+head; C = hb[128 rows at m0] @ wtb[z]^T + bias
__global__ __launch_bounds__(256)
void kqv_mma_k(const __nv_bfloat16* __restrict__ hb, const __nv_bfloat16* __restrict__ wtb,
               const float* __restrict__ bk, const float* __restrict__ bq,
               const float* __restrict__ bv,
               __nv_bfloat16* __restrict__ Kb, __nv_bfloat16* __restrict__ Qb,
               __nv_bfloat16* __restrict__ Vtb)
{
    int z = blockIdx.z, which = z >> 3, head = z & 7;
    int m0 = blockIdx.y << 7;
    float acc[4][4][4] = {};
    mma_loop(hb + (int64_t)m0 * DD, DD,
             wtb + (int64_t)z * DD * DD, DD, DD / KT, acc);

    int lane = threadIdx.x & 31, wid = threadIdx.x >> 5;
    int wm = wid >> 2, wn = wid & 3;
    const float* bias = ((which == 0) ? bk : (which == 1) ? bq : bv) + head * DD;

    #pragma unroll
    for (int mf = 0; mf < 4; mf++) {
        #pragma unroll
        for (int nf = 0; nf < 4; nf++) {
            int r   = wm * 64 + mf * 16 + (lane >> 2);
            int col = wn * 32 + nf * 8 + ((lane & 3) << 1);
            float b0 = bias[col], b1 = bias[col + 1];
            float v00 = acc[mf][nf][0] + b0, v01 = acc[mf][nf][1] + b1;
            float v10 = acc[mf][nf][2] + b0, v11 = acc[mf][nf][3] + b1;
            if (which < 2) {
                __nv_bfloat16* out = ((which == 0) ? Kb : Qb) + (int64_t)head * NM * DD;
                __nv_bfloat162 p0 = __floats2bfloat162_rn(v00, v01);
                __nv_bfloat162 p1 = __floats2bfloat162_rn(v10, v11);
                *(uint32_t*)&out[(int64_t)(m0 + r) * DD + col]     = *(uint32_t*)&p0;
                *(uint32_t*)&out[(int64_t)(m0 + r + 8) * DD + col] = *(uint32_t*)&p1;
            } else {
                int node0 = m0 + r, node1 = m0 + r + 8;
                __nv_bfloat16* vt0 = Vtb + (int64_t)(head * 2 + (node0 >> 9)) * DD * MM;
                __nv_bfloat16* vt1 = Vtb + (int64_t)(head * 2 + (node1 >> 9)) * DD * MM;
                vt0[(int64_t)col * MM + (node0 & 511)]       = __float2bfloat16(v00);
                vt0[(int64_t)(col + 1) * MM + (node0 & 511)] = __float2bfloat16(v01);
                vt1[(int64_t)col * MM + (node1 & 511)]       = __float2bfloat16(v10);
                vt1[(int64_t)(col + 1) * MM + (node1 & 511)] = __float2bfloat16(v11);
            }
        }
    }
}

// ================= scores via mma.sync: S = leaky(K @ Q^T) =========================
__global__ __launch_bounds__(256)
void scores_mma_k(const __nv_bfloat16* __restrict__ Kb, const __nv_bfloat16* __restrict__ Qb,
                  float* __restrict__ S)
{
    int z = blockIdx.z, h = z >> 1, n = z & 1;
    int m0 = blockIdx.y << 7, n0 = blockIdx.x << 7;
    float acc[4][4][4] = {};
    mma_loop(Kb + ((int64_t)h * NM + n * MM + m0) * DD, DD,
             Qb + ((int64_t)h * NM + n * MM + n0) * DD, DD, DD / KT, acc);

    int lane = threadIdx.x & 31, wid = threadIdx.x >> 5;
    int wm = wid >> 2, wn = wid & 3;
    float* out = S + (int64_t)z * MM * MM;
    #pragma unroll
    for (int mf = 0; mf < 4; mf++) {
        #pragma unroll
        for (int nf = 0; nf < 4; nf++) {
            int r   = m0 + wm * 64 + mf * 16 + (lane >> 2);
            int col = n0 + wn * 32 + nf * 8 + ((lane & 3) << 1);
            float v0 = acc[mf][nf][0]; v0 = (v0 >= 0.f) ? v0 : 0.2f * v0;
            float v1 = acc[mf][nf][1]; v1 = (v1 >= 0.f) ? v1 : 0.2f * v1;
            float v2 = acc[mf][nf][2]; v2 = (v2 >= 0.f) ? v2 : 0.2f * v2;
            float v3 = acc[mf][nf][3]; v3 = (v3 >= 0.f) ? v3 : 0.2f * v3;
            *(float2*)&out[(int64_t)r * MM + col]       = make_float2(v0, v1);
            *(float2*)&out[(int64_t)(r + 8) * MM + col] = make_float2(v2, v3);
        }
    }
}

// ================= softmax: fp32 in -> bf16 alpha ==================================
__global__ __launch_bounds__(256)
void softmax_k(const float* __restrict__ data, __nv_bfloat16* __restrict__ ab)
{
    __shared__ float red[8];
    const float* p = data + (int64_t)blockIdx.x * MM;
    __nv_bfloat16* o = ab + (int64_t)blockIdx.x * MM;
    int t = threadIdx.x;
    float v0 = p[t], v1 = p[t + 256];
    float m = fmaxf(v0, v1);
    #pragma unroll
    for (int off = 16; off; off >>= 1) m = fmaxf(m, __shfl_xor_sync(0xffffffffu, m, off));
    if ((t & 31) == 0) red[t >> 5] = m;
    __syncthreads();
    float bm = red[0];
    #pragma unroll
    for (int w = 1; w < 8; w++) bm = fmaxf(bm, red[w]);
    float e0 = __expf(v0 - bm), e1 = __expf(v1 - bm);
    float s = e0 + e1;
    #pragma unroll
    for (int off = 16; off; off >>= 1) s += __shfl_xor_sync(0xffffffffu, s, off);
    __syncthreads();
    if ((t & 31) == 0) red[t >> 5] = s;
    __syncthreads();
    float bs = red[0];
    #pragma unroll
    for (int w = 1; w < 8; w++) bs += red[w];
    float inv = 1.0f / bs;
    o[t]       = __float2bfloat16(e0 * inv);
    o[t + 256] = __float2bfloat16(e1 * inv);
}

// ================= attV via mma.sync (K-split 2, fp32 partials) ====================
__global__ __launch_bounds__(256)
void attv_mma_k(const __nv_bfloat16* __restrict__ ab, const __nv_bfloat16* __restrict__ Vtb,
                float* __restrict__ P)
{
    int zz = blockIdx.z, z = zz >> 1, ks = zz & 1;
    int m0 = blockIdx.y << 7;
    float acc[4][4][4] = {};
    mma_loop(ab  + (int64_t)z * MM * MM + (int64_t)m0 * MM + ks * 256, MM,
             Vtb + (int64_t)z * DD * MM + ks * 256, MM, 256 / KT, acc);

    int lane = threadIdx.x & 31, wid = threadIdx.x >> 5;
    int wm = wid >> 2, wn = wid & 3;
    float* out = P + ((int64_t)ks * HH * NB + z) * MM * DD;
    #pragma unroll
    for (int mf = 0; mf < 4; mf++) {
        #pragma unroll
        for (int nf = 0; nf < 4; nf++) {
            int r   = m0 + wm * 64 + mf * 16 + (lane >> 2);
            int col = wn * 32 + nf * 8 + ((lane & 3) << 1);
            *(float2*)&out[(int64_t)r * DD + col]       = make_float2(acc[mf][nf][0], acc[mf][nf][1]);
            *(float2*)&out[(int64_t)(r + 8) * DD + col] = make_float2(acc[mf][nf][2], acc[mf][nf][3]);
        }
    }
}

// ================= attV reduce: sum 2, leaky, concat layout ========================
__global__ __launch_bounds__(256)
void reduce_att_k(const float4* __restrict__ P, float4* __restrict__ out)
{
    const int tot = HH * NB * MM * DD / 4;   // 262144
    int idx = blockIdx.x * 256 + threadIdx.x;
    if (idx >= tot) return;
    float4 a = P[idx], b = P[idx + tot];
    float4 s = make_float4(a.x + b.x, a.y + b.y, a.z + b.z, a.w + b.w);
    s.x = (s.x >= 0.f) ? s.x : 0.2f * s.x;
    s.y = (s.y >= 0.f) ? s.y : 0.2f * s.y;
    s.z = (s.z >= 0.f) ? s.z : 0.2f * s.z;
    s.w = (s.w >= 0.f) ? s.w : 0.2f * s.w;
    int z   = idx >> 14;
    int rem = idx & 16383;
    int m   = rem >> 5;
    int d4  = rem & 31;
    int hh  = z >> 1, n = z & 1;
    out[(int64_t)(n * MM + m) * (HH * DD / 4) + hh * 32 + d4] = s;
}

// ================= edge kernel =====================================================
__global__ __launch_bounds__(256)
void edge_k(const float* __restrict__ AB, const float* __restrict__ b1,
            const float* __restrict__ w2, const float* __restrict__ b2,
            float* __restrict__ out)
{
    __shared__ float Ast[DD][36];
    __shared__ float Bst[DD][36];
    __shared__ float w2s[DD];
    int n  = blockIdx.z;
    int i0 = blockIdx.y << 5, j0 = blockIdx.x << 5;
    const float* Ab = AB + ((int64_t)n * MM + i0) * DD;
    const float* Bb = AB + (int64_t)NM * DD + ((int64_t)n * MM + j0) * DD;
    int t = threadIdx.x;
    if (t < DD) w2s[t] = w2[t];
    #pragma unroll
    for (int c = 0; c < 4; c++) {
        int idx = t + (c << 8);
        int r  = idx >> 5;
        int d4 = (idx & 31) << 2;
        float4 a = *(const float4*)(Ab + r * DD + d4);
        Ast[d4 + 0][r] = a.x; Ast[d4 + 1][r] = a.y;
        Ast[d4 + 2][r] = a.z; Ast[d4 + 3][r] = a.w;
        float4 bvl = *(const float4*)(Bb + r * DD + d4);
        float4 bb  = *(const float4*)(b1 + d4);
        Bst[d4 + 0][r] = bvl.x + bb.x; Bst[d4 + 1][r] = bvl.y + bb.y;
        Bst[d4 + 2][r] = bvl.z + bb.z; Bst[d4 + 3][r] = bvl.w + bb.w;
    }
    __syncthreads();
    int tx = t & 15, ty = t >> 4;
    float a00 = 0.f, a01 = 0.f, a10 = 0.f, a11 = 0.f;
    #pragma unroll 8
    for (int d = 0; d < DD; d++) {
        float2 av = *(const float2*)&Ast[d][ty << 1];
        float2 bv = *(const float2*)&Bst[d][tx << 1];
        float w = w2s[d];
        a00 = fmaf(fmaxf(av.x + bv.x, 0.f), w, a00);
        a01 = fmaf(fmaxf(av.x + bv.y, 0.f), w, a01);
        a10 = fmaf(fmaxf(av.y + bv.x, 0.f), w, a10);
        a11 = fmaf(fmaxf(av.y + bv.y, 0.f), w, a11);
    }
    float bb = b2[0];
    const float sc = 1.0f / (float)MM;
    int i = i0 + (ty << 1), j = j0 + (tx << 1);
    float* o = out + ((int64_t)n * MM + i) * MM + j;
    o[0]      = (a00 + bb) * sc;
    o[1]      = (a01 + bb) * sc;
    o[MM]     = (a10 + bb) * sc;
    o[MM + 1] = (a11 + bb) * sc;
}

// ================= host launcher ===================================================
extern "C" void kernel_launch(void* const* d_in, const int* in_sizes, int n_in,
                              void* d_out, int out_size)
{
    const float* x     = (const float*)d_in[0];
    const float* fn_w1 = (const float*)d_in[1];
    const float* fn_b1 = (const float*)d_in[2];
    const float* fn_w2 = (const float*)d_in[3];
    const float* fn_b2 = (const float*)d_in[4];
    const float* wk    = (const float*)d_in[5];
    const float* bk    = (const float*)d_in[6];
    const float* wq    = (const float*)d_in[7];
    const float* bq    = (const float*)d_in[8];
    const float* wv    = (const float*)d_in[9];
    const float* bv    = (const float*)d_in[10];
    const float* fv_w1 = (const float*)d_in[11];
    const float* fv_b1 = (const float*)d_in[12];
    const float* fv_w2 = (const float*)d_in[13];
    const float* fv_b2 = (const float*)d_in[14];
    const float* fe_w1 = (const float*)d_in[15];
    const float* fe_b1 = (const float*)d_in[16];
    const float* fe_w2 = (const float*)d_in[17];
    const float* fe_b2 = (const float*)d_in[18];

    float* scratch = nullptr;
    cudaGetSymbolAddress((void**)&scratch, g_scratch);
    float* tmp  = scratch + OFF_TMP;
    float* h    = scratch + OFF_H;
    float* S    = scratch + OFF_S;
    float* P    = scratch + OFF_S;    // scalar split partials while S dead
    float* attc = scratch + OFF_ATTC;
    float* t2   = scratch + OFF_T2;
    float* ABuf = scratch + OFF_AB;
    float* P2   = scratch + OFF_P2;
    __nv_bfloat16* hb  = (__nv_bfloat16*)(scratch + OFF_HB);
    __nv_bfloat16* wtb = (__nv_bfloat16*)(scratch + OFF_WTB);
    __nv_bfloat16* Kb  = (__nv_bfloat16*)(scratch + OFF_KB);
    __nv_bfloat16* Qb  = (__nv_bfloat16*)(scratch + OFF_QB);
    __nv_bfloat16* Vtb = (__nv_bfloat16*)(scratch + OFF_VTB);
    __nv_bfloat16* alb = (__nv_bfloat16*)(scratch + OFF_ALB);

    float* x2   = (float*)d_out;
    float* edge = (float*)d_out + NM * DD;

    dim3 gb(128);
    const int MN4  = NM * DD / 4;
    const int MN24 = NM * 2 * DD / 4;
    const int NC4  = DD / 4;
    const int NC24 = 2 * DD / 4;

    // 1) f_node hidden (scalar, K-split 2 + reduce)
    gemm_k<F_TE, 2><<<dim3(2, 16, 2), gb>>>(
        x, fn_w1, nullptr, nullptr, P, DIN, 2 * DD, 2 * DD, 0, 0, 0, 1, 0, 0,
        (int64_t)NM * 2 * DD);
    reduce_k<F_BIAS | F_RELU, 2><<<256, 256>>>(
        (const float4*)P, fn_b1, nullptr, (float4*)tmp, MN24, NC24);
    // 2) h (scalar, K-split 8 + reduce)
    {
        float* Ph = P + NM * 2 * DD * 2;
        gemm_k<0, 8><<<dim3(1, 16, 8), gb>>>(
            tmp, fn_w2, nullptr, nullptr, Ph, 2 * DD, DD, DD, 0, 0, 0, 1, 0, 0,
            (int64_t)NM * DD);
        reduce_k<F_BIAS, 8><<<128, 256>>>(
            (const float4*)Ph, fn_b2, nullptr, (float4*)h, MN4, NC4);
    }
    // 3) prep bf16
    prep_k<<<1536, 256>>>(h, wk, wq, wv, hb, wtb);
    // 4) K/Q/V via mma.sync
    kqv_mma_k<<<dim3(1, 8, 24), 256>>>(hb, wtb, bk, bq, bv, Kb, Qb, Vtb);
    // 5) scores via mma.sync (leaky)
    scores_mma_k<<<dim3(4, 4, 16), 256>>>(Kb, Qb, S);
    // 6) softmax -> bf16 alpha
    softmax_k<<<HH * NB * MM, 256>>>(S, alb);
    // 7) attV via mma.sync (K-split 2) + leaky/concat reduce
    attv_mma_k<<<dim3(1, 4, 32), 256>>>(alb, Vtb, P2);
    reduce_att_k<<<1024, 256>>>((const float4*)P2, (float4*)attc);
    // 8) f_v hidden (scalar, K-split 16 + reduce)
    gemm_k<0, 16><<<dim3(1, 16, 16), gb>>>(
        attc, fv_w1, nullptr, nullptr, P, HH * DD, DD, DD, 0, 0, 0, 1, 0, 0,
        (int64_t)NM * DD);
    reduce_k<F_BIAS | F_RELU, 16><<<128, 256>>>(
        (const float4*)P, fv_b1, nullptr, (float4*)t2, MN4, NC4);
    // 9) x2 (scalar, K-split 4 + reduce add h)
    gemm_k<0, 4><<<dim3(1, 16, 4), gb>>>(
        t2, fv_w2, nullptr, nullptr, P, DD, DD, DD, 0, 0, 0, 1, 0, 0,
        (int64_t)NM * DD);
    reduce_k<F_BIAS | F_ADD, 4><<<128, 256>>>(
        (const float4*)P, fv_b2, (const float4*)h, (float4*)x2, MN4, NC4);
    // 10) A/B for edges (scalar, K-split 2 + reduce)
    gemm_k<0, 2><<<dim3(1, 16, 4), gb>>>(
        x2, fe_w1, nullptr, nullptr, P, DD, DD, DD,
        0, (int64_t)DD * DD, 0, 1, (int64_t)NM * DD, 0, (int64_t)2 * NM * DD);
    reduce_k<0, 2><<<256, 256>>>(
        (const float4*)P, nullptr, nullptr, (float4*)ABuf, 2 * MN4, NC4);
    // 11) edge
    edge_k<<<dim3(16, 16, NB), 256>>>(ABuf, fe_b1, fe_w2, fe_b2, edge);
}

// round 8
// speedup vs baseline: 2.8656x; 1.0752x over previous
#include <cuda_runtime.h>
#include <cuda_bf16.h>
#include <math.h>
#include <stdint.h>

#define NB 2
#define MM 512
#define DD 128
#define HH 8
#define DIN 64
#define NM (NB*MM)   // 1024

typedef unsigned long long u64;

// ================= packed f32x2 helpers (scalar GEMM path) ========================
__device__ __forceinline__ u64 pk2(float lo, float hi) {
    u64 r; asm("mov.b64 %0, {%1,%2};" : "=l"(r) : "f"(lo), "f"(hi)); return r;
}
__device__ __forceinline__ void fma2(u64& d, u64 a, u64 b) {
    asm("fma.rn.f32x2 %0, %1, %2, %0;" : "+l"(d) : "l"(a), "l"(b));
}
__device__ __forceinline__ float2 up2(u64 v) {
    float lo, hi; asm("mov.b64 {%0,%1}, %2;" : "=f"(lo), "=f"(hi) : "l"(v));
    return make_float2(lo, hi);
}

// ================= mma.sync helpers ================================================
__device__ __forceinline__ uint32_t smem_to_u32(const void* p) {
    uint32_t a;
    asm("{ .reg .u64 t; cvta.to.shared.u64 t, %1; cvt.u32.u64 %0, t; }" : "=r"(a) : "l"(p));
    return a;
}
__device__ __forceinline__ void ldsm4(uint32_t& r0, uint32_t& r1, uint32_t& r2,
                                      uint32_t& r3, uint32_t addr) {
    asm volatile("ldmatrix.sync.aligned.m8n8.x4.shared.b16 {%0,%1,%2,%3}, [%4];"
                 : "=r"(r0), "=r"(r1), "=r"(r2), "=r"(r3) : "r"(addr));
}
__device__ __forceinline__ void mma16816(float* d, uint32_t a0, uint32_t a1,
                                         uint32_t a2, uint32_t a3,
                                         uint32_t b0, uint32_t b1) {
    asm volatile("mma.sync.aligned.m16n8k16.row.col.f32.bf16.bf16.f32 "
                 "{%0,%1,%2,%3},{%4,%5,%6,%7},{%8,%9},{%0,%1,%2,%3};"
                 : "+f"(d[0]), "+f"(d[1]), "+f"(d[2]), "+f"(d[3])
                 : "r"(a0), "r"(a1), "r"(a2), "r"(a3), "r"(b0), "r"(b1));
}

#define KT 32
#define SPAD 40   // smem row stride (bf16) — conflict-free ldmatrix

// C[128,128] += A[128,K] @ B[128,K]^T over nkt k-tiles of 32. 256 thr, 8 warps (2x4).
__device__ __forceinline__ void mma_loop(
    const __nv_bfloat16* __restrict__ A, int lda,
    const __nv_bfloat16* __restrict__ B, int ldb,
    int nkt, float acc[4][4][4])
{
    __shared__ __nv_bfloat16 As[128][SPAD];
    __shared__ __nv_bfloat16 Bs[128][SPAD];
    int tid = threadIdx.x, lane = tid & 31, wid = tid >> 5;
    int wm = wid >> 2, wn = wid & 3;

    int lrow = tid >> 1, lcol = (tid & 1) << 4;
    const __nv_bfloat16* Ag = A + (int64_t)lrow * lda + lcol;
    const __nv_bfloat16* Bg = B + (int64_t)lrow * ldb + lcol;

    uint32_t asb = smem_to_u32(As), bsb = smem_to_u32(Bs);
    int arow = ((lane >> 3) & 1) * 8 + (lane & 7);
    int acol = ((lane >> 4) & 1) * 8;
    int brow = ((lane >> 4) & 1) * 8 + (lane & 7);
    int bcol = ((lane >> 3) & 1) * 8;

    for (int kt = 0; kt < nkt; kt++) {
        __syncthreads();
        *(uint4*)&As[lrow][lcol]     = *(const uint4*)(Ag + kt * KT);
        *(uint4*)&As[lrow][lcol + 8] = *(const uint4*)(Ag + kt * KT + 8);
        *(uint4*)&Bs[lrow][lcol]     = *(const uint4*)(Bg + kt * KT);
        *(uint4*)&Bs[lrow][lcol + 8] = *(const uint4*)(Bg + kt * KT + 8);
        __syncthreads();
        #pragma unroll
        for (int kf = 0; kf < 2; kf++) {
            uint32_t a[4][4];
            #pragma unroll
            for (int mf = 0; mf < 4; mf++)
                ldsm4(a[mf][0], a[mf][1], a[mf][2], a[mf][3],
                      asb + ((wm * 64 + mf * 16 + arow) * SPAD + kf * 16 + acol) * 2);
            uint32_t b[2][4];
            #pragma unroll
            for (int p = 0; p < 2; p++)
                ldsm4(b[p][0], b[p][1], b[p][2], b[p][3],
                      bsb + ((wn * 32 + p * 16 + brow) * SPAD + kf * 16 + bcol) * 2);
            #pragma unroll
            for (int mf = 0; mf < 4; mf++)
                #pragma unroll
                for (int nf = 0; nf < 4; nf++)
                    mma16816(acc[mf][nf], a[mf][0], a[mf][1], a[mf][2], a[mf][3],
                             b[nf >> 1][(nf & 1) * 2], b[nf >> 1][(nf & 1) * 2 + 1]);
        }
    }
}

// ================= scratch =========================================================
#define OFF_TMP   0
#define OFF_H     (OFF_TMP + NM*2*DD)
#define OFF_S     (OFF_H   + NM*DD)              // fp32 scores; also K-split partials
#define OFF_ATTC  (OFF_S   + HH*NB*MM*MM)        // bf16 attc [1024][1024] (region reuse)
#define OFF_T2    (OFF_ATTC+ HH*NM*DD)
#define OFF_AB    (OFF_T2  + NM*DD)
#define OFF_HB    (OFF_AB  + 2*NM*DD)            // bf16 h   [1024][128]
#define OFF_WTB   (OFF_HB  + NM*DD/2)            // bf16 W^T [3][8][128][128]
#define OFF_KB    (OFF_WTB + 3*HH*DD*DD/2)       // bf16 K   [8][1024][128]
#define OFF_QB    (OFF_KB  + HH*NM*DD/2)
#define OFF_VTB   (OFF_QB  + HH*NM*DD/2)         // bf16 V^T [16][128][512]
#define OFF_ALB   (OFF_VTB + HH*NM*DD/2)         // bf16 alpha [16][512][512]
#define OFF_P2    (OFF_ALB + HH*NB*MM*MM/2)      // attV partials [2][16][512][128] fp32
#define OFF_FVWT  (OFF_P2  + 2*HH*NB*MM*DD)      // bf16 fv_w1^T [128][1024]
#define SCRATCH_TOTAL (OFF_FVWT + NM*DD/8)

__device__ float g_scratch[SCRATCH_TOTAL];

#define F_TRANSB 1
#define F_RELU   2
#define F_LEAKY  4
#define F_TE     8
#define F_BIAS   16
#define F_ADD    32

// ================= scalar FFMA2 GEMM (proven) ======================================
template<int F>
__device__ __forceinline__ void gemm_body(
    const float* __restrict__ A, const float* __restrict__ B,
    const float* __restrict__ bias, const float* __restrict__ addsrc,
    float* __restrict__ C, int Kd, int Nc, int ldc, int ktb, int kte)
{
    __shared__ float As[2][16][128];
    __shared__ float Bs[2][16][128];
    int tid = threadIdx.x;
    int tx = tid & 15, ty = tid >> 4;
    int m0 = blockIdx.y << 6, n0 = blockIdx.x << 7;

    int ar = tid >> 1, ac = (tid & 1) << 3;
    const float* Ap = A + (int64_t)(m0 + ar) * Kd + ac;
    int bk = tid >> 3, bc = (tid & 7) << 4;
    const float* Bp = (F & F_TRANSB)
        ? B + (int64_t)(n0 + tid) * Kd
        : B + (int64_t)bk * Nc + n0 + bc;

    u64 acc[8][4];
    #pragma unroll
    for (int i = 0; i < 8; i++)
        #pragma unroll
        for (int p = 0; p < 4; p++) acc[i][p] = 0ull;

    float4 la0, la1, lb[4];
    auto loadG = [&](int kt) {
        la0 = *(const float4*)(Ap + kt * 16);
        la1 = *(const float4*)(Ap + kt * 16 + 4);
        if (F & F_TE) {
            int kb = kt * 16 + ac;
            la0.x += sinf((float)(kb + 0) * (5.0f / 63.0f));
            la0.y += sinf((float)(kb + 1) * (5.0f / 63.0f));
            la0.z += sinf((float)(kb + 2) * (5.0f / 63.0f));
            la0.w += sinf((float)(kb + 3) * (5.0f / 63.0f));
            la1.x += sinf((float)(kb + 4) * (5.0f / 63.0f));
            la1.y += sinf((float)(kb + 5) * (5.0f / 63.0f));
            la1.z += sinf((float)(kb + 6) * (5.0f / 63.0f));
            la1.w += sinf((float)(kb + 7) * (5.0f / 63.0f));
        }
        if (F & F_TRANSB) {
            #pragma unroll
            for (int u = 0; u < 4; u++) lb[u] = *(const float4*)(Bp + kt * 16 + 4 * u);
        } else {
            #pragma unroll
            for (int u = 0; u < 4; u++) lb[u] = *(const float4*)(Bp + (int64_t)(kt * 16) * Nc + 4 * u);
        }
    };
    auto storeS = [&](int bf) {
        *(u64*)&As[bf][ac + 0][2 * ar] = pk2(la0.x, la0.x);
        *(u64*)&As[bf][ac + 1][2 * ar] = pk2(la0.y, la0.y);
        *(u64*)&As[bf][ac + 2][2 * ar] = pk2(la0.z, la0.z);
        *(u64*)&As[bf][ac + 3][2 * ar] = pk2(la0.w, la0.w);
        *(u64*)&As[bf][ac + 4][2 * ar] = pk2(la1.x, la1.x);
        *(u64*)&As[bf][ac + 5][2 * ar] = pk2(la1.y, la1.y);
        *(u64*)&As[bf][ac + 6][2 * ar] = pk2(la1.z, la1.z);
        *(u64*)&As[bf][ac + 7][2 * ar] = pk2(la1.w, la1.w);
        if (F & F_TRANSB) {
            #pragma unroll
            for (int u = 0; u < 4; u++) {
                Bs[bf][4 * u + 0][tid] = lb[u].x; Bs[bf][4 * u + 1][tid] = lb[u].y;
                Bs[bf][4 * u + 2][tid] = lb[u].z; Bs[bf][4 * u + 3][tid] = lb[u].w;
            }
        } else {
            #pragma unroll
            for (int u = 0; u < 4; u++) *(float4*)&Bs[bf][bk][bc + 4 * u] = lb[u];
        }
    };

    loadG(ktb); storeS(0); __syncthreads();
    int buf = 0;
    for (int kt = ktb; kt < kte; kt++) {
        bool more = (kt + 1 < kte);
        if (more) loadG(kt + 1);
        #pragma unroll
        for (int kk = 0; kk < 16; kk++) {
            ulonglong2 aL0 = *(const ulonglong2*)&As[buf][kk][(ty << 3)];
            ulonglong2 aL1 = *(const ulonglong2*)&As[buf][kk][(ty << 3) + 4];
            ulonglong2 aH0 = *(const ulonglong2*)&As[buf][kk][64 + (ty << 3)];
            ulonglong2 aH1 = *(const ulonglong2*)&As[buf][kk][64 + (ty << 3) + 4];
            ulonglong2 b0  = *(const ulonglong2*)&Bs[buf][kk][(tx << 2)];
            ulonglong2 b1  = *(const ulonglong2*)&Bs[buf][kk][64 + (tx << 2)];
            u64 ad[8] = {aL0.x, aL0.y, aL1.x, aL1.y, aH0.x, aH0.y, aH1.x, aH1.y};
            u64 bd[4] = {b0.x, b0.y, b1.x, b1.y};
            #pragma unroll
            for (int i = 0; i < 8; i++) {
                fma2(acc[i][0], ad[i], bd[0]);
                fma2(acc[i][1], ad[i], bd[1]);
                fma2(acc[i][2], ad[i], bd[2]);
                fma2(acc[i][3], ad[i], bd[3]);
            }
        }
        if (more) { storeS(buf ^ 1); __syncthreads(); buf ^= 1; }
    }

    #pragma unroll
    for (int i = 0; i < 8; i++) {
        int row = m0 + ((i < 4) ? ((ty << 2) + i) : (32 + (ty << 2) + i - 4));
        float2 q0 = up2(acc[i][0]), q1 = up2(acc[i][1]);
        float2 q2 = up2(acc[i][2]), q3 = up2(acc[i][3]);
        float o[8] = {q0.x, q0.y, q1.x, q1.y, q2.x, q2.y, q3.x, q3.y};
        #pragma unroll
        for (int j = 0; j < 8; j++) {
            int col = n0 + ((j < 4) ? ((tx << 2) + j) : (64 + (tx << 2) + j - 4));
            float v = o[j];
            if (F & F_BIAS)  v += bias[col];
            if (F & F_RELU)  v = fmaxf(v, 0.0f);
            if (F & F_LEAKY) v = (v >= 0.0f) ? v : 0.2f * v;
            if (F & F_ADD)   v += addsrc[(int64_t)row * ldc + col];
            o[j] = v;
        }
        *(float4*)&C[(int64_t)row * ldc + n0 + (tx << 2)]      = make_float4(o[0], o[1], o[2], o[3]);
        *(float4*)&C[(int64_t)row * ldc + n0 + 64 + (tx << 2)] = make_float4(o[4], o[5], o[6], o[7]);
    }
}

template<int F, int NKS>
__global__ __launch_bounds__(128, 4)
void gemm_k(const float* __restrict__ A, const float* __restrict__ B,
            const float* __restrict__ bias, const float* __restrict__ addsrc,
            float* __restrict__ C, int Kd, int Nc, int ldc,
            int64_t sA, int64_t sB, int64_t sBias,
            int zdiv, int64_t sC1, int64_t sC2, int64_t sPart)
{
    int zz = blockIdx.z;
    int z = zz / NKS, ks = zz % NKS;
    int ktn = Kd >> 4;
    int ktb = ks * (ktn / NKS), kte = ktb + ktn / NKS;
    const float* bz = (F & F_BIAS) ? bias + sBias * z : nullptr;
    float* Cz = C + (int64_t)(z / zdiv) * sC1 + (int64_t)(z % zdiv) * sC2
                  + (int64_t)ks * sPart;
    gemm_body<F>(A + sA * z, B + sB * z, bz, addsrc, Cz, Kd, Nc, ldc, ktb, kte);
}

template<int F, int NKS>
__global__ __launch_bounds__(256)
void reduce_k(const float4* __restrict__ P, const float* __restrict__ bias,
              const float4* __restrict__ addsrc, float4* __restrict__ C,
              int totalf4, int ncf4)
{
    int idx = blockIdx.x * 256 + threadIdx.x;
    if (idx >= totalf4) return;
    float4 s = P[idx];
    #pragma unroll
    for (int k = 1; k < NKS; k++) {
        float4 t = P[idx + (int64_t)k * totalf4];
        s.x += t.x; s.y += t.y; s.z += t.z; s.w += t.w;
    }
    if (F & F_BIAS) {
        float4 b = ((const float4*)bias)[idx % ncf4];
        s.x += b.x; s.y += b.y; s.z += b.z; s.w += b.w;
    }
    if (F & F_RELU) {
        s.x = fmaxf(s.x, 0.f); s.y = fmaxf(s.y, 0.f);
        s.z = fmaxf(s.z, 0.f); s.w = fmaxf(s.w, 0.f);
    }
    if (F & F_ADD) {
        float4 a = addsrc[idx];
        s.x += a.x; s.y += a.y; s.z += a.z; s.w += a.w;
    }
    C[idx] = s;
}

// ================= fused: h reduce (+bf16 hb) + weight transposes to bf16 ==========
__global__ __launch_bounds__(256)
void fuse_prep_k(const float4* __restrict__ Ph, const float* __restrict__ fn_b2,
                 float4* __restrict__ h, __nv_bfloat16* __restrict__ hb,
                 const float* __restrict__ wk, const float* __restrict__ wq,
                 const float* __restrict__ wv, const float* __restrict__ fv_w1,
                 __nv_bfloat16* __restrict__ wtb, __nv_bfloat16* __restrict__ fvwt)
{
    int b = blockIdx.x, t = threadIdx.x;
    if (b < 128) {                       // h = sum8(Ph) + bias; also emit bf16 hb
        int idx = b * 256 + t;           // 32768 float4
        float4 s = Ph[idx];
        #pragma unroll
        for (int k = 1; k < 8; k++) {
            float4 v = Ph[idx + k * (NM * DD / 4)];
            s.x += v.x; s.y += v.y; s.z += v.z; s.w += v.w;
        }
        float4 bb = ((const float4*)fn_b2)[idx & 31];
        s.x += bb.x; s.y += bb.y; s.z += bb.z; s.w += bb.w;
        h[idx] = s;
        __nv_bfloat162 p0 = __floats2bfloat162_rn(s.x, s.y);
        __nv_bfloat162 p1 = __floats2bfloat162_rn(s.z, s.w);
        uint2 w; w.x = *(uint32_t*)&p0; w.y = *(uint32_t*)&p1;
        *(uint2*)&hb[idx * 4] = w;
    } else if (b < 128 + 1536) {         // wtb[w][head][n][k] = W[head][k][n]
        int i = (b - 128) * 256 + t;
        if (i < 3 * HH * DD * DD) {
            int w = i >> 17;
            int r = i & 131071;
            int hd = r >> 14; int rem = r & 16383;
            int n = rem >> 7, k = rem & 127;
            const float* src = (w == 0) ? wk : (w == 1) ? wq : wv;
            wtb[i] = __float2bfloat16(src[hd * 16384 + k * 128 + n]);
        }
    } else {                             // fvwt[n][k] = fv_w1[k][n]
        int i = (b - 1664) * 256 + t;    // 131072
        int n = i >> 10, k = i & 1023;
        fvwt[i] = __float2bfloat16(fv_w1[k * 128 + n]);
    }
}

// ================= KQV via mma.sync ================================================
__global__ __launch_bounds__(256)
void kqv_mma_k(const __nv_bfloat16* __restrict__ hb, const __nv_bfloat16* __restrict__ wtb,
               const float* __restrict__ bk, const float* __restrict__ bq,
               const float* __restrict__ bv,
               __nv_bfloat16* __restrict__ Kb, __nv_bfloat16* __restrict__ Qb,
               __nv_bfloat16* __restrict__ Vtb)
{
    int z = blockIdx.z, which = z >> 3, head = z & 7;
    int m0 = blockIdx.y << 7;
    float acc[4][4][4] = {};
    mma_loop(hb + (int64_t)m0 * DD, DD,
             wtb + (int64_t)z * DD * DD, DD, DD / KT, acc);

    int lane = threadIdx.x & 31, wid = threadIdx.x >> 5;
    int wm = wid >> 2, wn = wid & 3;
    const float* bias = ((which == 0) ? bk : (which == 1) ? bq : bv) + head * DD;

    #pragma unroll
    for (int mf = 0; mf < 4; mf++) {
        #pragma unroll
        for (int nf = 0; nf < 4; nf++) {
            int r   = wm * 64 + mf * 16 + (lane >> 2);
            int col = wn * 32 + nf * 8 + ((lane & 3) << 1);
            float b0 = bias[col], b1 = bias[col + 1];
            float v00 = acc[mf][nf][0] + b0, v01 = acc[mf][nf][1] + b1;
            float v10 = acc[mf][nf][2] + b0, v11 = acc[mf][nf][3] + b1;
            if (which < 2) {
                __nv_bfloat16* out = ((which == 0) ? Kb : Qb) + (int64_t)head * NM * DD;
                __nv_bfloat162 p0 = __floats2bfloat162_rn(v00, v01);
                __nv_bfloat162 p1 = __floats2bfloat162_rn(v10, v11);
                *(uint32_t*)&out[(int64_t)(m0 + r) * DD + col]     = *(uint32_t*)&p0;
                *(uint32_t*)&out[(int64_t)(m0 + r + 8) * DD + col] = *(uint32_t*)&p1;
            } else {
                int node0 = m0 + r, node1 = m0 + r + 8;
                __nv_bfloat16* vt0 = Vtb + (int64_t)(head * 2 + (node0 >> 9)) * DD * MM;
                __nv_bfloat16* vt1 = Vtb + (int64_t)(head * 2 + (node1 >> 9)) * DD * MM;
                vt0[(int64_t)col * MM + (node0 & 511)]       = __float2bfloat16(v00);
                vt0[(int64_t)(col + 1) * MM + (node0 & 511)] = __float2bfloat16(v01);
                vt1[(int64_t)col * MM + (node1 & 511)]       = __float2bfloat16(v10);
                vt1[(int64_t)(col + 1) * MM + (node1 & 511)] = __float2bfloat16(v11);
            }
        }
    }
}

// ================= scores via mma.sync: S = leaky(K @ Q^T) =========================
__global__ __launch_bounds__(256)
void scores_mma_k(const __nv_bfloat16* __restrict__ Kb, const __nv_bfloat16* __restrict__ Qb,
                  float* __restrict__ S)
{
    int z = blockIdx.z, h = z >> 1, n = z & 1;
    int m0 = blockIdx.y << 7, n0 = blockIdx.x << 7;
    float acc[4][4][4] = {};
    mma_loop(Kb + ((int64_t)h * NM + n * MM + m0) * DD, DD,
             Qb + ((int64_t)h * NM + n * MM + n0) * DD, DD, DD / KT, acc);

    int lane = threadIdx.x & 31, wid = threadIdx.x >> 5;
    int wm = wid >> 2, wn = wid & 3;
    float* out = S + (int64_t)z * MM * MM;
    #pragma unroll
    for (int mf = 0; mf < 4; mf++) {
        #pragma unroll
        for (int nf = 0; nf < 4; nf++) {
            int r   = m0 + wm * 64 + mf * 16 + (lane >> 2);
            int col = n0 + wn * 32 + nf * 8 + ((lane & 3) << 1);
            float v0 = acc[mf][nf][0]; v0 = (v0 >= 0.f) ? v0 : 0.2f * v0;
            float v1 = acc[mf][nf][1]; v1 = (v1 >= 0.f) ? v1 : 0.2f * v1;
            float v2 = acc[mf][nf][2]; v2 = (v2 >= 0.f) ? v2 : 0.2f * v2;
            float v3 = acc[mf][nf][3]; v3 = (v3 >= 0.f) ? v3 : 0.2f * v3;
            *(float2*)&out[(int64_t)r * MM + col]       = make_float2(v0, v1);
            *(float2*)&out[(int64_t)(r + 8) * MM + col] = make_float2(v2, v3);
        }
    }
}

// ================= softmax: fp32 in -> bf16 alpha ==================================
__global__ __launch_bounds__(256)
void softmax_k(const float* __restrict__ data, __nv_bfloat16* __restrict__ ab)
{
    __shared__ float red[8];
    const float* p = data + (int64_t)blockIdx.x * MM;
    __nv_bfloat16* o = ab + (int64_t)blockIdx.x * MM;
    int t = threadIdx.x;
    float v0 = p[t], v1 = p[t + 256];
    float m = fmaxf(v0, v1);
    #pragma unroll
    for (int off = 16; off; off >>= 1) m = fmaxf(m, __shfl_xor_sync(0xffffffffu, m, off));
    if ((t & 31) == 0) red[t >> 5] = m;
    __syncthreads();
    float bm = red[0];
    #pragma unroll
    for (int w = 1; w < 8; w++) bm = fmaxf(bm, red[w]);
    float e0 = __expf(v0 - bm), e1 = __expf(v1 - bm);
    float s = e0 + e1;
    #pragma unroll
    for (int off = 16; off; off >>= 1) s += __shfl_xor_sync(0xffffffffu, s, off);
    __syncthreads();
    if ((t & 31) == 0) red[t >> 5] = s;
    __syncthreads();
    float bs = red[0];
    #pragma unroll
    for (int w = 1; w < 8; w++) bs += red[w];
    float inv = 1.0f / bs;
    o[t]       = __float2bfloat16(e0 * inv);
    o[t + 256] = __float2bfloat16(e1 * inv);
}

// ================= attV via mma.sync (K-split 2, fp32 partials) ====================
__global__ __launch_bounds__(256)
void attv_mma_k(const __nv_bfloat16* __restrict__ ab, const __nv_bfloat16* __restrict__ Vtb,
                float* __restrict__ P)
{
    int zz = blockIdx.z, z = zz >> 1, ks = zz & 1;
    int m0 = blockIdx.y << 7;
    float acc[4][4][4] = {};
    mma_loop(ab  + (int64_t)z * MM * MM + (int64_t)m0 * MM + ks * 256, MM,
             Vtb + (int64_t)z * DD * MM + ks * 256, MM, 256 / KT, acc);

    int lane = threadIdx.x & 31, wid = threadIdx.x >> 5;
    int wm = wid >> 2, wn = wid & 3;
    float* out = P + ((int64_t)ks * HH * NB + z) * MM * DD;
    #pragma unroll
    for (int mf = 0; mf < 4; mf++) {
        #pragma unroll
        for (int nf = 0; nf < 4; nf++) {
            int r   = m0 + wm * 64 + mf * 16 + (lane >> 2);
            int col = wn * 32 + nf * 8 + ((lane & 3) << 1);
            *(float2*)&out[(int64_t)r * DD + col]       = make_float2(acc[mf][nf][0], acc[mf][nf][1]);
            *(float2*)&out[(int64_t)(r + 8) * DD + col] = make_float2(acc[mf][nf][2], acc[mf][nf][3]);
        }
    }
}

// ================= attV reduce: sum 2, leaky, bf16 concat layout ===================
__global__ __launch_bounds__(256)
void reduce_att_k(const float4* __restrict__ P, __nv_bfloat16* __restrict__ out)
{
    const int tot = HH * NB * MM * DD / 4;   // 262144
    int idx = blockIdx.x * 256 + threadIdx.x;
    if (idx >= tot) return;
    float4 a = P[idx], b = P[idx + tot];
    float4 s = make_float4(a.x + b.x, a.y + b.y, a.z + b.z, a.w + b.w);
    s.x = (s.x >= 0.f) ? s.x : 0.2f * s.x;
    s.y = (s.y >= 0.f) ? s.y : 0.2f * s.y;
    s.z = (s.z >= 0.f) ? s.z : 0.2f * s.z;
    s.w = (s.w >= 0.f) ? s.w : 0.2f * s.w;
    int z   = idx >> 14;
    int rem = idx & 16383;
    int m   = rem >> 5;
    int d4  = rem & 31;
    int hh  = z >> 1, n = z & 1;
    __nv_bfloat162 p0 = __floats2bfloat162_rn(s.x, s.y);
    __nv_bfloat162 p1 = __floats2bfloat162_rn(s.z, s.w);
    uint2 w; w.x = *(uint32_t*)&p0; w.y = *(uint32_t*)&p1;
    *(uint2*)&out[(int64_t)(n * MM + m) * (HH * DD) + hh * DD + d4 * 4] = w;
}

// ================= f_v hidden via mma.sync (K-split 8, fp32 partials) ==============
__global__ __launch_bounds__(256)
void fv1_mma_k(const __nv_bfloat16* __restrict__ attcb, const __nv_bfloat16* __restrict__ fvwt,
               float* __restrict__ P)
{
    int ks = blockIdx.z;
    int m0 = blockIdx.y << 7;
    float acc[4][4][4] = {};
    mma_loop(attcb + (int64_t)m0 * (HH * DD) + ks * 128, HH * DD,
             fvwt + ks * 128, HH * DD, 128 / KT, acc);

    int lane = threadIdx.x & 31, wid = threadIdx.x >> 5;
    int wm = wid >> 2, wn = wid & 3;
    float* out = P + (int64_t)ks * NM * DD;
    #pragma unroll
    for (int mf = 0; mf < 4; mf++) {
        #pragma unroll
        for (int nf = 0; nf < 4; nf++) {
            int r   = m0 + wm * 64 + mf * 16 + (lane >> 2);
            int col = wn * 32 + nf * 8 + ((lane & 3) << 1);
            *(float2*)&out[(int64_t)r * DD + col]       = make_float2(acc[mf][nf][0], acc[mf][nf][1]);
            *(float2*)&out[(int64_t)(r + 8) * DD + col] = make_float2(acc[mf][nf][2], acc[mf][nf][3]);
        }
    }
}

// ================= edge kernel =====================================================
__global__ __launch_bounds__(256)
void edge_k(const float* __restrict__ AB, const float* __restrict__ b1,
            const float* __restrict__ w2, const float* __restrict__ b2,
            float* __restrict__ out)
{
    __shared__ float Ast[DD][36];
    __shared__ float Bst[DD][36];
    __shared__ float w2s[DD];
    int n  = blockIdx.z;
    int i0 = blockIdx.y << 5, j0 = blockIdx.x << 5;
    const float* Ab = AB + ((int64_t)n * MM + i0) * DD;
    const float* Bb = AB + (int64_t)NM * DD + ((int64_t)n * MM + j0) * DD;
    int t = threadIdx.x;
    if (t < DD) w2s[t] = w2[t];
    #pragma unroll
    for (int c = 0; c < 4; c++) {
        int idx = t + (c << 8);
        int r  = idx >> 5;
        int d4 = (idx & 31) << 2;
        float4 a = *(const float4*)(Ab + r * DD + d4);
        Ast[d4 + 0][r] = a.x; Ast[d4 + 1][r] = a.y;
        Ast[d4 + 2][r] = a.z; Ast[d4 + 3][r] = a.w;
        float4 bvl = *(const float4*)(Bb + r * DD + d4);
        float4 bb  = *(const float4*)(b1 + d4);
        Bst[d4 + 0][r] = bvl.x + bb.x; Bst[d4 + 1][r] = bvl.y + bb.y;
        Bst[d4 + 2][r] = bvl.z + bb.z; Bst[d4 + 3][r] = bvl.w + bb.w;
    }
    __syncthreads();
    int tx = t & 15, ty = t >> 4;
    float a00 = 0.f, a01 = 0.f, a10 = 0.f, a11 = 0.f;
    #pragma unroll 8
    for (int d = 0; d < DD; d++) {
        float2 av = *(const float2*)&Ast[d][ty << 1];
        float2 bv = *(const float2*)&Bst[d][tx << 1];
        float w = w2s[d];
        a00 = fmaf(fmaxf(av.x + bv.x, 0.f), w, a00);
        a01 = fmaf(fmaxf(av.x + bv.y, 0.f), w, a01);
        a10 = fmaf(fmaxf(av.y + bv.x, 0.f), w, a10);
        a11 = fmaf(fmaxf(av.y + bv.y, 0.f), w, a11);
    }
    float bb = b2[0];
    const float sc = 1.0f / (float)MM;
    int i = i0 + (ty << 1), j = j0 + (tx << 1);
    float* o = out + ((int64_t)n * MM + i) * MM + j;
    o[0]      = (a00 + bb) * sc;
    o[1]      = (a01 + bb) * sc;
    o[MM]     = (a10 + bb) * sc;
    o[MM + 1] = (a11 + bb) * sc;
}

// ================= host launcher ===================================================
extern "C" void kernel_launch(void* const* d_in, const int* in_sizes, int n_in,
                              void* d_out, int out_size)
{
    const float* x     = (const float*)d_in[0];
    const float* fn_w1 = (const float*)d_in[1];
    const float* fn_b1 = (const float*)d_in[2];
    const float* fn_w2 = (const float*)d_in[3];
    const float* fn_b2 = (const float*)d_in[4];
    const float* wk    = (const float*)d_in[5];
    const float* bk    = (const float*)d_in[6];
    const float* wq    = (const float*)d_in[7];
    const float* bq    = (const float*)d_in[8];
    const float* wv    = (const float*)d_in[9];
    const float* bv    = (const float*)d_in[10];
    const float* fv_w1 = (const float*)d_in[11];
    const float* fv_b1 = (const float*)d_in[12];
    const float* fv_w2 = (const float*)d_in[13];
    const float* fv_b2 = (const float*)d_in[14];
    const float* fe_w1 = (const float*)d_in[15];
    const float* fe_b1 = (const float*)d_in[16];
    const float* fe_w2 = (const float*)d_in[17];
    const float* fe_b2 = (const float*)d_in[18];

    float* scratch = nullptr;
    cudaGetSymbolAddress((void**)&scratch, g_scratch);
    float* tmp  = scratch + OFF_TMP;
    float* h    = scratch + OFF_H;
    float* S    = scratch + OFF_S;
    float* P    = scratch + OFF_S;    // split partials while S dead
    float* t2   = scratch + OFF_T2;
    float* ABuf = scratch + OFF_AB;
    float* P2   = scratch + OFF_P2;
    __nv_bfloat16* attcb = (__nv_bfloat16*)(scratch + OFF_ATTC);
    __nv_bfloat16* hb  = (__nv_bfloat16*)(scratch + OFF_HB);
    __nv_bfloat16* wtb = (__nv_bfloat16*)(scratch + OFF_WTB);
    __nv_bfloat16* Kb  = (__nv_bfloat16*)(scratch + OFF_KB);
    __nv_bfloat16* Qb  = (__nv_bfloat16*)(scratch + OFF_QB);
    __nv_bfloat16* Vtb = (__nv_bfloat16*)(scratch + OFF_VTB);
    __nv_bfloat16* alb = (__nv_bfloat16*)(scratch + OFF_ALB);
    __nv_bfloat16* fvwt = (__nv_bfloat16*)(scratch + OFF_FVWT);

    float* x2   = (float*)d_out;
    float* edge = (float*)d_out + NM * DD;

    dim3 gb(128);
    const int MN4  = NM * DD / 4;
    const int MN24 = NM * 2 * DD / 4;
    const int NC4  = DD / 4;
    const int NC24 = 2 * DD / 4;

    // 1) f_node hidden (scalar, K-split 2 + reduce)
    gemm_k<F_TE, 2><<<dim3(2, 16, 2), gb>>>(
        x, fn_w1, nullptr, nullptr, P, DIN, 2 * DD, 2 * DD, 0, 0, 0, 1, 0, 0,
        (int64_t)NM * 2 * DD);
    reduce_k<F_BIAS | F_RELU, 2><<<256, 256>>>(
        (const float4*)P, fn_b1, nullptr, (float4*)tmp, MN24, NC24);
    // 2) h (scalar, K-split 8) then fused reduce + bf16 prep
    float* Ph = P + NM * 2 * DD * 2;
    gemm_k<0, 8><<<dim3(1, 16, 8), gb>>>(
        tmp, fn_w2, nullptr, nullptr, Ph, 2 * DD, DD, DD, 0, 0, 0, 1, 0, 0,
        (int64_t)NM * DD);
    fuse_prep_k<<<2176, 256>>>((const float4*)Ph, fn_b2, (float4*)h, hb,
                               wk, wq, wv, fv_w1, wtb, fvwt);
    // 3) K/Q/V via mma.sync
    kqv_mma_k<<<dim3(1, 8, 24), 256>>>(hb, wtb, bk, bq, bv, Kb, Qb, Vtb);
    // 4) scores via mma.sync (leaky)
    scores_mma_k<<<dim3(4, 4, 16), 256>>>(Kb, Qb, S);
    // 5) softmax -> bf16 alpha
    softmax_k<<<HH * NB * MM, 256>>>(S, alb);
    // 6) attV via mma.sync (K-split 2) + leaky/concat reduce -> bf16 attc
    attv_mma_k<<<dim3(1, 4, 32), 256>>>(alb, Vtb, P2);
    reduce_att_k<<<1024, 256>>>((const float4*)P2, attcb);
    // 7) f_v hidden via mma.sync (K-split 8) + reduce (bias+relu)
    fv1_mma_k<<<dim3(1, 8, 8), 256>>>(attcb, fvwt, P);
    reduce_k<F_BIAS | F_RELU, 8><<<128, 256>>>(
        (const float4*)P, fv_b1, nullptr, (float4*)t2, MN4, NC4);
    // 8) x2 (scalar, K-split 4 + reduce add h)
    gemm_k<0, 4><<<dim3(1, 16, 4), gb>>>(
        t2, fv_w2, nullptr, nullptr, P, DD, DD, DD, 0, 0, 0, 1, 0, 0,
        (int64_t)NM * DD);
    reduce_k<F_BIAS | F_ADD, 4><<<128, 256>>>(
        (const float4*)P, fv_b2, (const float4*)h, (float4*)x2, MN4, NC4);
    // 9) A/B for edges (scalar, K-split 2 + reduce)
    gemm_k<0, 2><<<dim3(1, 16, 4), gb>>>(
        x2, fe_w1, nullptr, nullptr, P, DD, DD, DD,
        0, (int64_t)DD * DD, 0, 1, (int64_t)NM * DD, 0, (int64_t)2 * NM * DD);
    reduce_k<0, 2><<<256, 256>>>(
        (const float4*)P, nullptr, nullptr, (float4*)ABuf, 2 * MN4, NC4);
    // 10) edge
    edge_k<<<dim3(16, 16, NB), 256>>>(ABuf, fe_b1, fe_w2, fe_b2, edge);
}

// round 9
// speedup vs baseline: 2.8869x; 1.0075x over previous
#include <cuda_runtime.h>
#include <cuda_bf16.h>
#include <math.h>
#include <stdint.h>

#define NB 2
#define MM 512
#define DD 128
#define HH 8
#define DIN 64
#define NM (NB*MM)   // 1024

typedef unsigned long long u64;

// ================= packed f32x2 helpers (scalar GEMM path) ========================
__device__ __forceinline__ u64 pk2(float lo, float hi) {
    u64 r; asm("mov.b64 %0, {%1,%2};" : "=l"(r) : "f"(lo), "f"(hi)); return r;
}
__device__ __forceinline__ void fma2(u64& d, u64 a, u64 b) {
    asm("fma.rn.f32x2 %0, %1, %2, %0;" : "+l"(d) : "l"(a), "l"(b));
}
__device__ __forceinline__ float2 up2(u64 v) {
    float lo, hi; asm("mov.b64 {%0,%1}, %2;" : "=f"(lo), "=f"(hi) : "l"(v));
    return make_float2(lo, hi);
}

// ================= mma.sync helpers ================================================
__device__ __forceinline__ uint32_t smem_to_u32(const void* p) {
    uint32_t a;
    asm("{ .reg .u64 t; cvta.to.shared.u64 t, %1; cvt.u32.u64 %0, t; }" : "=r"(a) : "l"(p));
    return a;
}
__device__ __forceinline__ void ldsm4(uint32_t& r0, uint32_t& r1, uint32_t& r2,
                                      uint32_t& r3, uint32_t addr) {
    asm volatile("ldmatrix.sync.aligned.m8n8.x4.shared.b16 {%0,%1,%2,%3}, [%4];"
                 : "=r"(r0), "=r"(r1), "=r"(r2), "=r"(r3) : "r"(addr));
}
__device__ __forceinline__ void mma16816(float* d, uint32_t a0, uint32_t a1,
                                         uint32_t a2, uint32_t a3,
                                         uint32_t b0, uint32_t b1) {
    asm volatile("mma.sync.aligned.m16n8k16.row.col.f32.bf16.bf16.f32 "
                 "{%0,%1,%2,%3},{%4,%5,%6,%7},{%8,%9},{%0,%1,%2,%3};"
                 : "+f"(d[0]), "+f"(d[1]), "+f"(d[2]), "+f"(d[3])
                 : "r"(a0), "r"(a1), "r"(a2), "r"(a3), "r"(b0), "r"(b1));
}

#define KT 32
#define SPAD 40   // smem row stride (bf16) — conflict-free ldmatrix

// C[128,128] += A[128,K] @ B[128,K]^T. 256 thr, 8 warps (2x4), warp tile 64x32.
__device__ __forceinline__ void mma_loop(
    const __nv_bfloat16* __restrict__ A, int lda,
    const __nv_bfloat16* __restrict__ B, int ldb,
    int nkt, float acc[4][4][4])
{
    __shared__ __nv_bfloat16 As[128][SPAD];
    __shared__ __nv_bfloat16 Bs[128][SPAD];
    int tid = threadIdx.x, lane = tid & 31, wid = tid >> 5;
    int wm = wid >> 2, wn = wid & 3;

    int lrow = tid >> 1, lcol = (tid & 1) << 4;
    const __nv_bfloat16* Ag = A + (int64_t)lrow * lda + lcol;
    const __nv_bfloat16* Bg = B + (int64_t)lrow * ldb + lcol;

    uint32_t asb = smem_to_u32(As), bsb = smem_to_u32(Bs);
    int arow = ((lane >> 3) & 1) * 8 + (lane & 7);
    int acol = ((lane >> 4) & 1) * 8;
    int brow = ((lane >> 4) & 1) * 8 + (lane & 7);
    int bcol = ((lane >> 3) & 1) * 8;

    for (int kt = 0; kt < nkt; kt++) {
        __syncthreads();
        *(uint4*)&As[lrow][lcol]     = *(const uint4*)(Ag + kt * KT);
        *(uint4*)&As[lrow][lcol + 8] = *(const uint4*)(Ag + kt * KT + 8);
        *(uint4*)&Bs[lrow][lcol]     = *(const uint4*)(Bg + kt * KT);
        *(uint4*)&Bs[lrow][lcol + 8] = *(const uint4*)(Bg + kt * KT + 8);
        __syncthreads();
        #pragma unroll
        for (int kf = 0; kf < 2; kf++) {
            uint32_t a[4][4];
            #pragma unroll
            for (int mf = 0; mf < 4; mf++)
                ldsm4(a[mf][0], a[mf][1], a[mf][2], a[mf][3],
                      asb + ((wm * 64 + mf * 16 + arow) * SPAD + kf * 16 + acol) * 2);
            uint32_t b[2][4];
            #pragma unroll
            for (int p = 0; p < 2; p++)
                ldsm4(b[p][0], b[p][1], b[p][2], b[p][3],
                      bsb + ((wn * 32 + p * 16 + brow) * SPAD + kf * 16 + bcol) * 2);
            #pragma unroll
            for (int mf = 0; mf < 4; mf++)
                #pragma unroll
                for (int nf = 0; nf < 4; nf++)
                    mma16816(acc[mf][nf], a[mf][0], a[mf][1], a[mf][2], a[mf][3],
                             b[nf >> 1][(nf & 1) * 2], b[nf >> 1][(nf & 1) * 2 + 1]);
        }
    }
}

// C[64,128] += A[64,K] @ B[128,K]^T. 256 thr, 8 warps (2x4), warp tile 32x32.
__device__ __forceinline__ void mma_loop64(
    const __nv_bfloat16* __restrict__ A, int lda,
    const __nv_bfloat16* __restrict__ B, int ldb,
    int nkt, float acc[2][4][4])
{
    __shared__ __nv_bfloat16 As[64][SPAD];
    __shared__ __nv_bfloat16 Bs[128][SPAD];
    int tid = threadIdx.x, lane = tid & 31, wid = tid >> 5;
    int wm = wid >> 2, wn = wid & 3;

    int arow_l = tid >> 2, acol_l = (tid & 3) << 3;   // A: 64 rows x 4 chunks of 8
    int lrow = tid >> 1, lcol = (tid & 1) << 4;       // B: 128 rows x 2 chunks of 16
    const __nv_bfloat16* Ag = A + (int64_t)arow_l * lda + acol_l;
    const __nv_bfloat16* Bg = B + (int64_t)lrow * ldb + lcol;

    uint32_t asb = smem_to_u32(As), bsb = smem_to_u32(Bs);
    int arow = ((lane >> 3) & 1) * 8 + (lane & 7);
    int acol = ((lane >> 4) & 1) * 8;
    int brow = ((lane >> 4) & 1) * 8 + (lane & 7);
    int bcol = ((lane >> 3) & 1) * 8;

    for (int kt = 0; kt < nkt; kt++) {
        __syncthreads();
        *(uint4*)&As[arow_l][acol_l] = *(const uint4*)(Ag + kt * KT);
        *(uint4*)&Bs[lrow][lcol]     = *(const uint4*)(Bg + kt * KT);
        *(uint4*)&Bs[lrow][lcol + 8] = *(const uint4*)(Bg + kt * KT + 8);
        __syncthreads();
        #pragma unroll
        for (int kf = 0; kf < 2; kf++) {
            uint32_t a[2][4];
            #pragma unroll
            for (int mf = 0; mf < 2; mf++)
                ldsm4(a[mf][0], a[mf][1], a[mf][2], a[mf][3],
                      asb + ((wm * 32 + mf * 16 + arow) * SPAD + kf * 16 + acol) * 2);
            uint32_t b[2][4];
            #pragma unroll
            for (int p = 0; p < 2; p++)
                ldsm4(b[p][0], b[p][1], b[p][2], b[p][3],
                      bsb + ((wn * 32 + p * 16 + brow) * SPAD + kf * 16 + bcol) * 2);
            #pragma unroll
            for (int mf = 0; mf < 2; mf++)
                #pragma unroll
                for (int nf = 0; nf < 4; nf++)
                    mma16816(acc[mf][nf], a[mf][0], a[mf][1], a[mf][2], a[mf][3],
                             b[nf >> 1][(nf & 1) * 2], b[nf >> 1][(nf & 1) * 2 + 1]);
        }
    }
}

// ================= scratch =========================================================
#define OFF_TMP   0
#define OFF_H     (OFF_TMP + NM*2*DD)
#define OFF_S     (OFF_H   + NM*DD)              // fp32 scores; also K-split partials
#define OFF_ATTC  (OFF_S   + HH*NB*MM*MM)        // bf16 attc [1024][1024]
#define OFF_T2    (OFF_ATTC+ HH*NM*DD)
#define OFF_AB    (OFF_T2  + NM*DD)
#define OFF_HB    (OFF_AB  + 2*NM*DD)            // bf16 h   [1024][128]
#define OFF_WTB   (OFF_HB  + NM*DD/2)            // bf16 W^T [3][8][128][128]
#define OFF_KB    (OFF_WTB + 3*HH*DD*DD/2)       // bf16 K   [8][1024][128]
#define OFF_QB    (OFF_KB  + HH*NM*DD/2)
#define OFF_VTB   (OFF_QB  + HH*NM*DD/2)         // bf16 V^T [16][128][512]
#define OFF_ALB   (OFF_VTB + HH*NM*DD/2)         // bf16 alpha [16][512][512]
#define OFF_FVWT  (OFF_ALB + HH*NB*MM*MM/2)      // bf16 fv_w1^T [128][1024]
#define SCRATCH_TOTAL (OFF_FVWT + NM*DD/8)

__device__ float g_scratch[SCRATCH_TOTAL];

#define F_TRANSB 1
#define F_RELU   2
#define F_LEAKY  4
#define F_TE     8
#define F_BIAS   16
#define F_ADD    32

// ================= scalar FFMA2 GEMM (proven) ======================================
template<int F>
__device__ __forceinline__ void gemm_body(
    const float* __restrict__ A, const float* __restrict__ B,
    const float* __restrict__ bias, const float* __restrict__ addsrc,
    float* __restrict__ C, int Kd, int Nc, int ldc, int ktb, int kte)
{
    __shared__ float As[2][16][128];
    __shared__ float Bs[2][16][128];
    int tid = threadIdx.x;
    int tx = tid & 15, ty = tid >> 4;
    int m0 = blockIdx.y << 6, n0 = blockIdx.x << 7;

    int ar = tid >> 1, ac = (tid & 1) << 3;
    const float* Ap = A + (int64_t)(m0 + ar) * Kd + ac;
    int bk = tid >> 3, bc = (tid & 7) << 4;
    const float* Bp = (F & F_TRANSB)
        ? B + (int64_t)(n0 + tid) * Kd
        : B + (int64_t)bk * Nc + n0 + bc;

    u64 acc[8][4];
    #pragma unroll
    for (int i = 0; i < 8; i++)
        #pragma unroll
        for (int p = 0; p < 4; p++) acc[i][p] = 0ull;

    float4 la0, la1, lb[4];
    auto loadG = [&](int kt) {
        la0 = *(const float4*)(Ap + kt * 16);
        la1 = *(const float4*)(Ap + kt * 16 + 4);
        if (F & F_TE) {
            int kb = kt * 16 + ac;
            la0.x += sinf((float)(kb + 0) * (5.0f / 63.0f));
            la0.y += sinf((float)(kb + 1) * (5.0f / 63.0f));
            la0.z += sinf((float)(kb + 2) * (5.0f / 63.0f));
            la0.w += sinf((float)(kb + 3) * (5.0f / 63.0f));
            la1.x += sinf((float)(kb + 4) * (5.0f / 63.0f));
            la1.y += sinf((float)(kb + 5) * (5.0f / 63.0f));
            la1.z += sinf((float)(kb + 6) * (5.0f / 63.0f));
            la1.w += sinf((float)(kb + 7) * (5.0f / 63.0f));
        }
        if (F & F_TRANSB) {
            #pragma unroll
            for (int u = 0; u < 4; u++) lb[u] = *(const float4*)(Bp + kt * 16 + 4 * u);
        } else {
            #pragma unroll
            for (int u = 0; u < 4; u++) lb[u] = *(const float4*)(Bp + (int64_t)(kt * 16) * Nc + 4 * u);
        }
    };
    auto storeS = [&](int bf) {
        *(u64*)&As[bf][ac + 0][2 * ar] = pk2(la0.x, la0.x);
        *(u64*)&As[bf][ac + 1][2 * ar] = pk2(la0.y, la0.y);
        *(u64*)&As[bf][ac + 2][2 * ar] = pk2(la0.z, la0.z);
        *(u64*)&As[bf][ac + 3][2 * ar] = pk2(la0.w, la0.w);
        *(u64*)&As[bf][ac + 4][2 * ar] = pk2(la1.x, la1.x);
        *(u64*)&As[bf][ac + 5][2 * ar] = pk2(la1.y, la1.y);
        *(u64*)&As[bf][ac + 6][2 * ar] = pk2(la1.z, la1.z);
        *(u64*)&As[bf][ac + 7][2 * ar] = pk2(la1.w, la1.w);
        if (F & F_TRANSB) {
            #pragma unroll
            for (int u = 0; u < 4; u++) {
                Bs[bf][4 * u + 0][tid] = lb[u].x; Bs[bf][4 * u + 1][tid] = lb[u].y;
                Bs[bf][4 * u + 2][tid] = lb[u].z; Bs[bf][4 * u + 3][tid] = lb[u].w;
            }
        } else {
            #pragma unroll
            for (int u = 0; u < 4; u++) *(float4*)&Bs[bf][bk][bc + 4 * u] = lb[u];
        }
    };

    loadG(ktb); storeS(0); __syncthreads();
    int buf = 0;
    for (int kt = ktb; kt < kte; kt++) {
        bool more = (kt + 1 < kte);
        if (more) loadG(kt + 1);
        #pragma unroll
        for (int kk = 0; kk < 16; kk++) {
            ulonglong2 aL0 = *(const ulonglong2*)&As[buf][kk][(ty << 3)];
            ulonglong2 aL1 = *(const ulonglong2*)&As[buf][kk][(ty << 3) + 4];
            ulonglong2 aH0 = *(const ulonglong2*)&As[buf][kk][64 + (ty << 3)];
            ulonglong2 aH1 = *(const ulonglong2*)&As[buf][kk][64 + (ty << 3) + 4];
            ulonglong2 b0  = *(const ulonglong2*)&Bs[buf][kk][(tx << 2)];
            ulonglong2 b1  = *(const ulonglong2*)&Bs[buf][kk][64 + (tx << 2)];
            u64 ad[8] = {aL0.x, aL0.y, aL1.x, aL1.y, aH0.x, aH0.y, aH1.x, aH1.y};
            u64 bd[4] = {b0.x, b0.y, b1.x, b1.y};
            #pragma unroll
            for (int i = 0; i < 8; i++) {
                fma2(acc[i][0], ad[i], bd[0]);
                fma2(acc[i][1], ad[i], bd[1]);
                fma2(acc[i][2], ad[i], bd[2]);
                fma2(acc[i][3], ad[i], bd[3]);
            }
        }
        if (more) { storeS(buf ^ 1); __syncthreads(); buf ^= 1; }
    }

    #pragma unroll
    for (int i = 0; i < 8; i++) {
        int row = m0 + ((i < 4) ? ((ty << 2) + i) : (32 + (ty << 2) + i - 4));
        float2 q0 = up2(acc[i][0]), q1 = up2(acc[i][1]);
        float2 q2 = up2(acc[i][2]), q3 = up2(acc[i][3]);
        float o[8] = {q0.x, q0.y, q1.x, q1.y, q2.x, q2.y, q3.x, q3.y};
        #pragma unroll
        for (int j = 0; j < 8; j++) {
            int col = n0 + ((j < 4) ? ((tx << 2) + j) : (64 + (tx << 2) + j - 4));
            float v = o[j];
            if (F & F_BIAS)  v += bias[col];
            if (F & F_RELU)  v = fmaxf(v, 0.0f);
            if (F & F_LEAKY) v = (v >= 0.0f) ? v : 0.2f * v;
            if (F & F_ADD)   v += addsrc[(int64_t)row * ldc + col];
            o[j] = v;
        }
        *(float4*)&C[(int64_t)row * ldc + n0 + (tx << 2)]      = make_float4(o[0], o[1], o[2], o[3]);
        *(float4*)&C[(int64_t)row * ldc + n0 + 64 + (tx << 2)] = make_float4(o[4], o[5], o[6], o[7]);
    }
}

template<int F, int NKS>
__global__ __launch_bounds__(128, 4)
void gemm_k(const float* __restrict__ A, const float* __restrict__ B,
            const float* __restrict__ bias, const float* __restrict__ addsrc,
            float* __restrict__ C, int Kd, int Nc, int ldc,
            int64_t sA, int64_t sB, int64_t sBias,
            int zdiv, int64_t sC1, int64_t sC2, int64_t sPart)
{
    int zz = blockIdx.z;
    int z = zz / NKS, ks = zz % NKS;
    int ktn = Kd >> 4;
    int ktb = ks * (ktn / NKS), kte = ktb + ktn / NKS;
    const float* bz = (F & F_BIAS) ? bias + sBias * z : nullptr;
    float* Cz = C + (int64_t)(z / zdiv) * sC1 + (int64_t)(z % zdiv) * sC2
                  + (int64_t)ks * sPart;
    gemm_body<F>(A + sA * z, B + sB * z, bz, addsrc, Cz, Kd, Nc, ldc, ktb, kte);
}

template<int F, int NKS>
__global__ __launch_bounds__(256)
void reduce_k(const float4* __restrict__ P, const float* __restrict__ bias,
              const float4* __restrict__ addsrc, float4* __restrict__ C,
              int totalf4, int ncf4)
{
    int idx = blockIdx.x * 256 + threadIdx.x;
    if (idx >= totalf4) return;
    float4 s = P[idx];
    #pragma unroll
    for (int k = 1; k < NKS; k++) {
        float4 t = P[idx + (int64_t)k * totalf4];
        s.x += t.x; s.y += t.y; s.z += t.z; s.w += t.w;
    }
    if (F & F_BIAS) {
        float4 b = ((const float4*)bias)[idx % ncf4];
        s.x += b.x; s.y += b.y; s.z += b.z; s.w += b.w;
    }
    if (F & F_RELU) {
        s.x = fmaxf(s.x, 0.f); s.y = fmaxf(s.y, 0.f);
        s.z = fmaxf(s.z, 0.f); s.w = fmaxf(s.w, 0.f);
    }
    if (F & F_ADD) {
        float4 a = addsrc[idx];
        s.x += a.x; s.y += a.y; s.z += a.z; s.w += a.w;
    }
    C[idx] = s;
}

// ================= fused prep: h reduce + COALESCED weight transposes ==============
// grid: [0,128) h-reduce; [128,512) wtb tiles (24 mats x 16 tiles);
//       [512,640) fvwt tiles (128 tiles)
__global__ __launch_bounds__(256)
void fuse_prep_k(const float4* __restrict__ Ph, const float* __restrict__ fn_b2,
                 float4* __restrict__ h, __nv_bfloat16* __restrict__ hb,
                 const float* __restrict__ wk, const float* __restrict__ wq,
                 const float* __restrict__ wv, const float* __restrict__ fv_w1,
                 __nv_bfloat16* __restrict__ wtb, __nv_bfloat16* __restrict__ fvwt)
{
    int b = blockIdx.x, t = threadIdx.x;
    if (b < 128) {
        int idx = b * 256 + t;
        float4 s = Ph[idx];
        #pragma unroll
        for (int k = 1; k < 8; k++) {
            float4 v = Ph[idx + k * (NM * DD / 4)];
            s.x += v.x; s.y += v.y; s.z += v.z; s.w += v.w;
        }
        float4 bb = ((const float4*)fn_b2)[idx & 31];
        s.x += bb.x; s.y += bb.y; s.z += bb.z; s.w += bb.w;
        h[idx] = s;
        __nv_bfloat162 p0 = __floats2bfloat162_rn(s.x, s.y);
        __nv_bfloat162 p1 = __floats2bfloat162_rn(s.z, s.w);
        uint2 w; w.x = *(uint32_t*)&p0; w.y = *(uint32_t*)&p1;
        *(uint2*)&hb[idx * 4] = w;
        return;
    }
    __shared__ float ts[32][33];
    int c = t & 31, r0 = t >> 5;
    if (b < 512) {        // wtb: mat mi of 24, tile ti of 16 (kb x nb)
        int q = b - 128;
        int mi = q >> 4, ti = q & 15;
        int kb = ti >> 2, nb = ti & 3;
        int w = mi / 8, hd = mi & 7;
        const float* src = ((w == 0) ? wk : (w == 1) ? wq : wv) + hd * 16384;
        #pragma unroll
        for (int i = 0; i < 4; i++) {
            int r = r0 + 8 * i;
            ts[r][c] = src[(kb * 32 + r) * 128 + nb * 32 + c];
        }
        __syncthreads();
        // write wtb[mi][n][k], pairs of k per thread
        int ck = (t & 15) << 1, rn0 = t >> 4;
        __nv_bfloat16* dst = wtb + (int64_t)mi * 16384;
        #pragma unroll
        for (int i = 0; i < 2; i++) {
            int rn = rn0 + 16 * i;
            __nv_bfloat162 p = __floats2bfloat162_rn(ts[ck][rn], ts[ck + 1][rn]);
            *(uint32_t*)&dst[(nb * 32 + rn) * 128 + kb * 32 + ck] = *(uint32_t*)&p;
        }
    } else {              // fvwt: fv_w1 [1024k x 128n] -> [128n x 1024k]
        int q = b - 512;  // 128 tiles: kb 0..31, nb 0..3
        int kb = q >> 2, nb = q & 3;
        #pragma unroll
        for (int i = 0; i < 4; i++) {
            int r = r0 + 8 * i;
            ts[r][c] = fv_w1[(kb * 32 + r) * 128 + nb * 32 + c];
        }
        __syncthreads();
        int ck = (t & 15) << 1, rn0 = t >> 4;
        #pragma unroll
        for (int i = 0; i < 2; i++) {
            int rn = rn0 + 16 * i;
            __nv_bfloat162 p = __floats2bfloat162_rn(ts[ck][rn], ts[ck + 1][rn]);
            *(uint32_t*)&fvwt[(int64_t)(nb * 32 + rn) * 1024 + kb * 32 + ck] = *(uint32_t*)&p;
        }
    }
}

// ================= KQV via mma.sync ================================================
__global__ __launch_bounds__(256)
void kqv_mma_k(const __nv_bfloat16* __restrict__ hb, const __nv_bfloat16* __restrict__ wtb,
               const float* __restrict__ bk, const float* __restrict__ bq,
               const float* __restrict__ bv,
               __nv_bfloat16* __restrict__ Kb, __nv_bfloat16* __restrict__ Qb,
               __nv_bfloat16* __restrict__ Vtb)
{
    int z = blockIdx.z, which = z >> 3, head = z & 7;
    int m0 = blockIdx.y << 7;
    float acc[4][4][4] = {};
    mma_loop(hb + (int64_t)m0 * DD, DD,
             wtb + (int64_t)z * DD * DD, DD, DD / KT, acc);

    int lane = threadIdx.x & 31, wid = threadIdx.x >> 5;
    int wm = wid >> 2, wn = wid & 3;
    const float* bias = ((which == 0) ? bk : (which == 1) ? bq : bv) + head * DD;

    #pragma unroll
    for (int mf = 0; mf < 4; mf++) {
        #pragma unroll
        for (int nf = 0; nf < 4; nf++) {
            int r   = wm * 64 + mf * 16 + (lane >> 2);
            int col = wn * 32 + nf * 8 + ((lane & 3) << 1);
            float b0 = bias[col], b1 = bias[col + 1];
            float v00 = acc[mf][nf][0] + b0, v01 = acc[mf][nf][1] + b1;
            float v10 = acc[mf][nf][2] + b0, v11 = acc[mf][nf][3] + b1;
            if (which < 2) {
                __nv_bfloat16* out = ((which == 0) ? Kb : Qb) + (int64_t)head * NM * DD;
                __nv_bfloat162 p0 = __floats2bfloat162_rn(v00, v01);
                __nv_bfloat162 p1 = __floats2bfloat162_rn(v10, v11);
                *(uint32_t*)&out[(int64_t)(m0 + r) * DD + col]     = *(uint32_t*)&p0;
                *(uint32_t*)&out[(int64_t)(m0 + r + 8) * DD + col] = *(uint32_t*)&p1;
            } else {
                int node0 = m0 + r, node1 = m0 + r + 8;
                __nv_bfloat16* vt0 = Vtb + (int64_t)(head * 2 + (node0 >> 9)) * DD * MM;
                __nv_bfloat16* vt1 = Vtb + (int64_t)(head * 2 + (node1 >> 9)) * DD * MM;
                vt0[(int64_t)col * MM + (node0 & 511)]       = __float2bfloat16(v00);
                vt0[(int64_t)(col + 1) * MM + (node0 & 511)] = __float2bfloat16(v01);
                vt1[(int64_t)col * MM + (node1 & 511)]       = __float2bfloat16(v10);
                vt1[(int64_t)(col + 1) * MM + (node1 & 511)] = __float2bfloat16(v11);
            }
        }
    }
}

// ================= scores via mma.sync: S = leaky(K @ Q^T) =========================
__global__ __launch_bounds__(256)
void scores_mma_k(const __nv_bfloat16* __restrict__ Kb, const __nv_bfloat16* __restrict__ Qb,
                  float* __restrict__ S)
{
    int z = blockIdx.z, h = z >> 1, n = z & 1;
    int m0 = blockIdx.y << 7, n0 = blockIdx.x << 7;
    float acc[4][4][4] = {};
    mma_loop(Kb + ((int64_t)h * NM + n * MM + m0) * DD, DD,
             Qb + ((int64_t)h * NM + n * MM + n0) * DD, DD, DD / KT, acc);

    int lane = threadIdx.x & 31, wid = threadIdx.x >> 5;
    int wm = wid >> 2, wn = wid & 3;
    float* out = S + (int64_t)z * MM * MM;
    #pragma unroll
    for (int mf = 0; mf < 4; mf++) {
        #pragma unroll
        for (int nf = 0; nf < 4; nf++) {
            int r   = m0 + wm * 64 + mf * 16 + (lane >> 2);
            int col = n0 + wn * 32 + nf * 8 + ((lane & 3) << 1);
            float v0 = acc[mf][nf][0]; v0 = (v0 >= 0.f) ? v0 : 0.2f * v0;
            float v1 = acc[mf][nf][1]; v1 = (v1 >= 0.f) ? v1 : 0.2f * v1;
            float v2 = acc[mf][nf][2]; v2 = (v2 >= 0.f) ? v2 : 0.2f * v2;
            float v3 = acc[mf][nf][3]; v3 = (v3 >= 0.f) ? v3 : 0.2f * v3;
            *(float2*)&out[(int64_t)r * MM + col]       = make_float2(v0, v1);
            *(float2*)&out[(int64_t)(r + 8) * MM + col] = make_float2(v2, v3);
        }
    }
}

// ================= softmax: fp32 in -> bf16 alpha ==================================
__global__ __launch_bounds__(256)
void softmax_k(const float* __restrict__ data, __nv_bfloat16* __restrict__ ab)
{
    __shared__ float red[8];
    const float* p = data + (int64_t)blockIdx.x * MM;
    __nv_bfloat16* o = ab + (int64_t)blockIdx.x * MM;
    int t = threadIdx.x;
    float v0 = p[t], v1 = p[t + 256];
    float m = fmaxf(v0, v1);
    #pragma unroll
    for (int off = 16; off; off >>= 1) m = fmaxf(m, __shfl_xor_sync(0xffffffffu, m, off));
    if ((t & 31) == 0) red[t >> 5] = m;
    __syncthreads();
    float bm = red[0];
    #pragma unroll
    for (int w = 1; w < 8; w++) bm = fmaxf(bm, red[w]);
    float e0 = __expf(v0 - bm), e1 = __expf(v1 - bm);
    float s = e0 + e1;
    #pragma unroll
    for (int off = 16; off; off >>= 1) s += __shfl_xor_sync(0xffffffffu, s, off);
    __syncthreads();
    if ((t & 31) == 0) red[t >> 5] = s;
    __syncthreads();
    float bs = red[0];
    #pragma unroll
    for (int w = 1; w < 8; w++) bs += red[w];
    float inv = 1.0f / bs;
    o[t]       = __float2bfloat16(e0 * inv);
    o[t + 256] = __float2bfloat16(e1 * inv);
}

// ================= attV via mma.sync, M-tile 64, full K, fused epilogue ============
__global__ __launch_bounds__(256)
void attv_mma_k(const __nv_bfloat16* __restrict__ ab, const __nv_bfloat16* __restrict__ Vtb,
                __nv_bfloat16* __restrict__ attc)
{
    int z = blockIdx.z, h = z >> 1, n = z & 1;
    int m0 = blockIdx.y << 6;
    float acc[2][4][4] = {};
    mma_loop64(ab  + (int64_t)z * MM * MM + (int64_t)m0 * MM, MM,
               Vtb + (int64_t)z * DD * MM, MM, MM / KT, acc);

    int lane = threadIdx.x & 31, wid = threadIdx.x >> 5;
    int wm = wid >> 2, wn = wid & 3;
    #pragma unroll
    for (int mf = 0; mf < 2; mf++) {
        #pragma unroll
        for (int nf = 0; nf < 4; nf++) {
            int r   = m0 + wm * 32 + mf * 16 + (lane >> 2);
            int col = wn * 32 + nf * 8 + ((lane & 3) << 1);
            float v0 = acc[mf][nf][0]; v0 = (v0 >= 0.f) ? v0 : 0.2f * v0;
            float v1 = acc[mf][nf][1]; v1 = (v1 >= 0.f) ? v1 : 0.2f * v1;
            float v2 = acc[mf][nf][2]; v2 = (v2 >= 0.f) ? v2 : 0.2f * v2;
            float v3 = acc[mf][nf][3]; v3 = (v3 >= 0.f) ? v3 : 0.2f * v3;
            __nv_bfloat162 p0 = __floats2bfloat162_rn(v0, v1);
            __nv_bfloat162 p1 = __floats2bfloat162_rn(v2, v3);
            __nv_bfloat16* o0 = attc + (int64_t)(n * MM + r) * (HH * DD) + h * DD + col;
            __nv_bfloat16* o1 = attc + (int64_t)(n * MM + r + 8) * (HH * DD) + h * DD + col;
            *(uint32_t*)o0 = *(uint32_t*)&p0;
            *(uint32_t*)o1 = *(uint32_t*)&p1;
        }
    }
}

// ================= f_v hidden via mma.sync (K-split 8, fp32 partials) ==============
__global__ __launch_bounds__(256)
void fv1_mma_k(const __nv_bfloat16* __restrict__ attcb, const __nv_bfloat16* __restrict__ fvwt,
               float* __restrict__ P)
{
    int ks = blockIdx.z;
    int m0 = blockIdx.y << 7;
    float acc[4][4][4] = {};
    mma_loop(attcb + (int64_t)m0 * (HH * DD) + ks * 128, HH * DD,
             fvwt + ks * 128, HH * DD, 128 / KT, acc);

    int lane = threadIdx.x & 31, wid = threadIdx.x >> 5;
    int wm = wid >> 2, wn = wid & 3;
    float* out = P + (int64_t)ks * NM * DD;
    #pragma unroll
    for (int mf = 0; mf < 4; mf++) {
        #pragma unroll
        for (int nf = 0; nf < 4; nf++) {
            int r   = m0 + wm * 64 + mf * 16 + (lane >> 2);
            int col = wn * 32 + nf * 8 + ((lane & 3) << 1);
            *(float2*)&out[(int64_t)r * DD + col]       = make_float2(acc[mf][nf][0], acc[mf][nf][1]);
            *(float2*)&out[(int64_t)(r + 8) * DD + col] = make_float2(acc[mf][nf][2], acc[mf][nf][3]);
        }
    }
}

// ================= edge kernel =====================================================
__global__ __launch_bounds__(256)
void edge_k(const float* __restrict__ AB, const float* __restrict__ b1,
            const float* __restrict__ w2, const float* __restrict__ b2,
            float* __restrict__ out)
{
    __shared__ float Ast[DD][36];
    __shared__ float Bst[DD][36];
    __shared__ float w2s[DD];
    int n  = blockIdx.z;
    int i0 = blockIdx.y << 5, j0 = blockIdx.x << 5;
    const float* Ab = AB + ((int64_t)n * MM + i0) * DD;
    const float* Bb = AB + (int64_t)NM * DD + ((int64_t)n * MM + j0) * DD;
    int t = threadIdx.x;
    if (t < DD) w2s[t] = w2[t];
    #pragma unroll
    for (int c = 0; c < 4; c++) {
        int idx = t + (c << 8);
        int r  = idx >> 5;
        int d4 = (idx & 31) << 2;
        float4 a = *(const float4*)(Ab + r * DD + d4);
        Ast[d4 + 0][r] = a.x; Ast[d4 + 1][r] = a.y;
        Ast[d4 + 2][r] = a.z; Ast[d4 + 3][r] = a.w;
        float4 bvl = *(const float4*)(Bb + r * DD + d4);
        float4 bb  = *(const float4*)(b1 + d4);
        Bst[d4 + 0][r] = bvl.x + bb.x; Bst[d4 + 1][r] = bvl.y + bb.y;
        Bst[d4 + 2][r] = bvl.z + bb.z; Bst[d4 + 3][r] = bvl.w + bb.w;
    }
    __syncthreads();
    int tx = t & 15, ty = t >> 4;
    float a00 = 0.f, a01 = 0.f, a10 = 0.f, a11 = 0.f;
    #pragma unroll 8
    for (int d = 0; d < DD; d++) {
        float2 av = *(const float2*)&Ast[d][ty << 1];
        float2 bv = *(const float2*)&Bst[d][tx << 1];
        float w = w2s[d];
        a00 = fmaf(fmaxf(av.x + bv.x, 0.f), w, a00);
        a01 = fmaf(fmaxf(av.x + bv.y, 0.f), w, a01);
        a10 = fmaf(fmaxf(av.y + bv.x, 0.f), w, a10);
        a11 = fmaf(fmaxf(av.y + bv.y, 0.f), w, a11);
    }
    float bb = b2[0];
    const float sc = 1.0f / (float)MM;
    int i = i0 + (ty << 1), j = j0 + (tx << 1);
    float* o = out + ((int64_t)n * MM + i) * MM + j;
    o[0]      = (a00 + bb) * sc;
    o[1]      = (a01 + bb) * sc;
    o[MM]     = (a10 + bb) * sc;
    o[MM + 1] = (a11 + bb) * sc;
}

// ================= host launcher ===================================================
extern "C" void kernel_launch(void* const* d_in, const int* in_sizes, int n_in,
                              void* d_out, int out_size)
{
    const float* x     = (const float*)d_in[0];
    const float* fn_w1 = (const float*)d_in[1];
    const float* fn_b1 = (const float*)d_in[2];
    const float* fn_w2 = (const float*)d_in[3];
    const float* fn_b2 = (const float*)d_in[4];
    const float* wk    = (const float*)d_in[5];
    const float* bk    = (const float*)d_in[6];
    const float* wq    = (const float*)d_in[7];
    const float* bq    = (const float*)d_in[8];
    const float* wv    = (const float*)d_in[9];
    const float* bv    = (const float*)d_in[10];
    const float* fv_w1 = (const float*)d_in[11];
    const float* fv_b1 = (const float*)d_in[12];
    const float* fv_w2 = (const float*)d_in[13];
    const float* fv_b2 = (const float*)d_in[14];
    const float* fe_w1 = (const float*)d_in[15];
    const float* fe_b1 = (const float*)d_in[16];
    const float* fe_w2 = (const float*)d_in[17];
    const float* fe_b2 = (const float*)d_in[18];

    float* scratch = nullptr;
    cudaGetSymbolAddress((void**)&scratch, g_scratch);
    float* tmp  = scratch + OFF_TMP;
    float* h    = scratch + OFF_H;
    float* S    = scratch + OFF_S;
    float* P    = scratch + OFF_S;    // split partials while S dead
    float* t2   = scratch + OFF_T2;
    float* ABuf = scratch + OFF_AB;
    __nv_bfloat16* attcb = (__nv_bfloat16*)(scratch + OFF_ATTC);
    __nv_bfloat16* hb  = (__nv_bfloat16*)(scratch + OFF_HB);
    __nv_bfloat16* wtb = (__nv_bfloat16*)(scratch + OFF_WTB);
    __nv_bfloat16* Kb  = (__nv_bfloat16*)(scratch + OFF_KB);
    __nv_bfloat16* Qb  = (__nv_bfloat16*)(scratch + OFF_QB);
    __nv_bfloat16* Vtb = (__nv_bfloat16*)(scratch + OFF_VTB);
    __nv_bfloat16* alb = (__nv_bfloat16*)(scratch + OFF_ALB);
    __nv_bfloat16* fvwt = (__nv_bfloat16*)(scratch + OFF_FVWT);

    float* x2   = (float*)d_out;
    float* edge = (float*)d_out + NM * DD;

    dim3 gb(128);
    const int MN4  = NM * DD / 4;
    const int MN24 = NM * 2 * DD / 4;
    const int NC4  = DD / 4;
    const int NC24 = 2 * DD / 4;

    // 1) f_node hidden (scalar, K-split 2 + reduce)
    gemm_k<F_TE, 2><<<dim3(2, 16, 2), gb>>>(
        x, fn_w1, nullptr, nullptr, P, DIN, 2 * DD, 2 * DD, 0, 0, 0, 1, 0, 0,
        (int64_t)NM * 2 * DD);
    reduce_k<F_BIAS | F_RELU, 2><<<256, 256>>>(
        (const float4*)P, fn_b1, nullptr, (float4*)tmp, MN24, NC24);
    // 2) h (scalar, K-split 8) then fused reduce + coalesced bf16 prep
    float* Ph = P + NM * 2 * DD * 2;
    gemm_k<0, 8><<<dim3(1, 16, 8), gb>>>(
        tmp, fn_w2, nullptr, nullptr, Ph, 2 * DD, DD, DD, 0, 0, 0, 1, 0, 0,
        (int64_t)NM * DD);
    fuse_prep_k<<<640, 256>>>((const float4*)Ph, fn_b2, (float4*)h, hb,
                              wk, wq, wv, fv_w1, wtb, fvwt);
    // 3) K/Q/V via mma.sync
    kqv_mma_k<<<dim3(1, 8, 24), 256>>>(hb, wtb, bk, bq, bv, Kb, Qb, Vtb);
    // 4) scores via mma.sync (leaky)
    scores_mma_k<<<dim3(4, 4, 16), 256>>>(Kb, Qb, S);
    // 5) softmax -> bf16 alpha
    softmax_k<<<HH * NB * MM, 256>>>(S, alb);
    // 6) attV via mma.sync, M64 tiles, fused leaky+concat epilogue -> bf16 attc
    attv_mma_k<<<dim3(1, 8, 16), 256>>>(alb, Vtb, attcb);
    // 7) f_v hidden via mma.sync (K-split 8) + reduce (bias+relu)
    fv1_mma_k<<<dim3(1, 8, 8), 256>>>(attcb, fvwt, P);
    reduce_k<F_BIAS | F_RELU, 8><<<128, 256>>>(
        (const float4*)P, fv_b1, nullptr, (float4*)t2, MN4, NC4);
    // 8) x2 (scalar, K-split 4 + reduce add h)
    gemm_k<0, 4><<<dim3(1, 16, 4), gb>>>(
        t2, fv_w2, nullptr, nullptr, P, DD, DD, DD, 0, 0, 0, 1, 0, 0,
        (int64_t)NM * DD);
    reduce_k<F_BIAS | F_ADD, 4><<<128, 256>>>(
        (const float4*)P, fv_b2, (const float4*)h, (float4*)x2, MN4, NC4);
    // 9) A/B for edges (scalar, K-split 2 + reduce)
    gemm_k<0, 2><<<dim3(1, 16, 4), gb>>>(
        x2, fe_w1, nullptr, nullptr, P, DD, DD, DD,
        0, (int64_t)DD * DD, 0, 1, (int64_t)NM * DD, 0, (int64_t)2 * NM * DD);
    reduce_k<0, 2><<<256, 256>>>(
        (const float4*)P, nullptr, nullptr, (float4*)ABuf, 2 * MN4, NC4);
    // 10) edge
    edge_k<<<dim3(16, 16, NB), 256>>>(ABuf, fe_b1, fe_w2, fe_b2, edge);
}

// round 10
// speedup vs baseline: 2.9220x; 1.0121x over previous
#include <cuda_runtime.h>
#include <cuda_bf16.h>
#include <math.h>
#include <stdint.h>

#define NB 2
#define MM 512
#define DD 128
#define HH 8
#define DIN 64
#define NM (NB*MM)   // 1024

typedef unsigned long long u64;

// ================= packed f32x2 helpers ===========================================
__device__ __forceinline__ u64 pk2(float lo, float hi) {
    u64 r; asm("mov.b64 %0, {%1,%2};" : "=l"(r) : "f"(lo), "f"(hi)); return r;
}
__device__ __forceinline__ void fma2(u64& d, u64 a, u64 b) {
    asm("fma.rn.f32x2 %0, %1, %2, %0;" : "+l"(d) : "l"(a), "l"(b));
}
__device__ __forceinline__ u64 add2(u64 a, u64 b) {
    u64 r; asm("add.rn.f32x2 %0, %1, %2;" : "=l"(r) : "l"(a), "l"(b)); return r;
}
__device__ __forceinline__ float2 up2(u64 v) {
    float lo, hi; asm("mov.b64 {%0,%1}, %2;" : "=f"(lo), "=f"(hi) : "l"(v));
    return make_float2(lo, hi);
}

// ================= mma.sync helpers ================================================
__device__ __forceinline__ uint32_t smem_to_u32(const void* p) {
    uint32_t a;
    asm("{ .reg .u64 t; cvta.to.shared.u64 t, %1; cvt.u32.u64 %0, t; }" : "=r"(a) : "l"(p));
    return a;
}
__device__ __forceinline__ void ldsm4(uint32_t& r0, uint32_t& r1, uint32_t& r2,
                                      uint32_t& r3, uint32_t addr) {
    asm volatile("ldmatrix.sync.aligned.m8n8.x4.shared.b16 {%0,%1,%2,%3}, [%4];"
                 : "=r"(r0), "=r"(r1), "=r"(r2), "=r"(r3) : "r"(addr));
}
__device__ __forceinline__ void mma16816(float* d, uint32_t a0, uint32_t a1,
                                         uint32_t a2, uint32_t a3,
                                         uint32_t b0, uint32_t b1) {
    asm volatile("mma.sync.aligned.m16n8k16.row.col.f32.bf16.bf16.f32 "
                 "{%0,%1,%2,%3},{%4,%5,%6,%7},{%8,%9},{%0,%1,%2,%3};"
                 : "+f"(d[0]), "+f"(d[1]), "+f"(d[2]), "+f"(d[3])
                 : "r"(a0), "r"(a1), "r"(a2), "r"(a3), "r"(b0), "r"(b1));
}

#define KT 32
#define SPAD 40

// C[128,128] += A[128,K] @ B[128,K]^T. 256 thr, 8 warps (2x4), warp tile 64x32.
__device__ __forceinline__ void mma_loop(
    const __nv_bfloat16* __restrict__ A, int lda,
    const __nv_bfloat16* __restrict__ B, int ldb,
    int nkt, float acc[4][4][4])
{
    __shared__ __nv_bfloat16 As[128][SPAD];
    __shared__ __nv_bfloat16 Bs[128][SPAD];
    int tid = threadIdx.x, lane = tid & 31, wid = tid >> 5;
    int wm = wid >> 2, wn = wid & 3;

    int lrow = tid >> 1, lcol = (tid & 1) << 4;
    const __nv_bfloat16* Ag = A + (int64_t)lrow * lda + lcol;
    const __nv_bfloat16* Bg = B + (int64_t)lrow * ldb + lcol;

    uint32_t asb = smem_to_u32(As), bsb = smem_to_u32(Bs);
    int arow = ((lane >> 3) & 1) * 8 + (lane & 7);
    int acol = ((lane >> 4) & 1) * 8;
    int brow = ((lane >> 4) & 1) * 8 + (lane & 7);
    int bcol = ((lane >> 3) & 1) * 8;

    for (int kt = 0; kt < nkt; kt++) {
        __syncthreads();
        *(uint4*)&As[lrow][lcol]     = *(const uint4*)(Ag + kt * KT);
        *(uint4*)&As[lrow][lcol + 8] = *(const uint4*)(Ag + kt * KT + 8);
        *(uint4*)&Bs[lrow][lcol]     = *(const uint4*)(Bg + kt * KT);
        *(uint4*)&Bs[lrow][lcol + 8] = *(const uint4*)(Bg + kt * KT + 8);
        __syncthreads();
        #pragma unroll
        for (int kf = 0; kf < 2; kf++) {
            uint32_t a[4][4];
            #pragma unroll
            for (int mf = 0; mf < 4; mf++)
                ldsm4(a[mf][0], a[mf][1], a[mf][2], a[mf][3],
                      asb + ((wm * 64 + mf * 16 + arow) * SPAD + kf * 16 + acol) * 2);
            uint32_t b[2][4];
            #pragma unroll
            for (int p = 0; p < 2; p++)
                ldsm4(b[p][0], b[p][1], b[p][2], b[p][3],
                      bsb + ((wn * 32 + p * 16 + brow) * SPAD + kf * 16 + bcol) * 2);
            #pragma unroll
            for (int mf = 0; mf < 4; mf++)
                #pragma unroll
                for (int nf = 0; nf < 4; nf++)
                    mma16816(acc[mf][nf], a[mf][0], a[mf][1], a[mf][2], a[mf][3],
                             b[nf >> 1][(nf & 1) * 2], b[nf >> 1][(nf & 1) * 2 + 1]);
        }
    }
}

// C[64,128] += A[64,K] @ B[128,K]^T. 256 thr, 8 warps (2x4), warp tile 32x32.
__device__ __forceinline__ void mma_loop64(
    const __nv_bfloat16* __restrict__ A, int lda,
    const __nv_bfloat16* __restrict__ B, int ldb,
    int nkt, float acc[2][4][4])
{
    __shared__ __nv_bfloat16 As[64][SPAD];
    __shared__ __nv_bfloat16 Bs[128][SPAD];
    int tid = threadIdx.x, lane = tid & 31, wid = tid >> 5;
    int wm = wid >> 2, wn = wid & 3;

    int arow_l = tid >> 2, acol_l = (tid & 3) << 3;
    int lrow = tid >> 1, lcol = (tid & 1) << 4;
    const __nv_bfloat16* Ag = A + (int64_t)arow_l * lda + acol_l;
    const __nv_bfloat16* Bg = B + (int64_t)lrow * ldb + lcol;

    uint32_t asb = smem_to_u32(As), bsb = smem_to_u32(Bs);
    int arow = ((lane >> 3) & 1) * 8 + (lane & 7);
    int acol = ((lane >> 4) & 1) * 8;
    int brow = ((lane >> 4) & 1) * 8 + (lane & 7);
    int bcol = ((lane >> 3) & 1) * 8;

    for (int kt = 0; kt < nkt; kt++) {
        __syncthreads();
        *(uint4*)&As[arow_l][acol_l] = *(const uint4*)(Ag + kt * KT);
        *(uint4*)&Bs[lrow][lcol]     = *(const uint4*)(Bg + kt * KT);
        *(uint4*)&Bs[lrow][lcol + 8] = *(const uint4*)(Bg + kt * KT + 8);
        __syncthreads();
        #pragma unroll
        for (int kf = 0; kf < 2; kf++) {
            uint32_t a[2][4];
            #pragma unroll
            for (int mf = 0; mf < 2; mf++)
                ldsm4(a[mf][0], a[mf][1], a[mf][2], a[mf][3],
                      asb + ((wm * 32 + mf * 16 + arow) * SPAD + kf * 16 + acol) * 2);
            uint32_t b[2][4];
            #pragma unroll
            for (int p = 0; p < 2; p++)
                ldsm4(b[p][0], b[p][1], b[p][2], b[p][3],
                      bsb + ((wn * 32 + p * 16 + brow) * SPAD + kf * 16 + bcol) * 2);
            #pragma unroll
            for (int mf = 0; mf < 2; mf++)
                #pragma unroll
                for (int nf = 0; nf < 4; nf++)
                    mma16816(acc[mf][nf], a[mf][0], a[mf][1], a[mf][2], a[mf][3],
                             b[nf >> 1][(nf & 1) * 2], b[nf >> 1][(nf & 1) * 2 + 1]);
        }
    }
}

// ================= scratch =========================================================
#define OFF_TMP   0
#define OFF_H     (OFF_TMP + NM*2*DD)
#define OFF_S     (OFF_H   + NM*DD)
#define OFF_ATTC  (OFF_S   + HH*NB*MM*MM)
#define OFF_T2    (OFF_ATTC+ HH*NM*DD)
#define OFF_AB    (OFF_T2  + NM*DD)
#define OFF_HB    (OFF_AB  + 2*NM*DD)
#define OFF_WTB   (OFF_HB  + NM*DD/2)
#define OFF_KB    (OFF_WTB + 3*HH*DD*DD/2)
#define OFF_QB    (OFF_KB  + HH*NM*DD/2)
#define OFF_VTB   (OFF_QB  + HH*NM*DD/2)
#define OFF_ALB   (OFF_VTB + HH*NM*DD/2)
#define OFF_FVWT  (OFF_ALB + HH*NB*MM*MM/2)
#define SCRATCH_TOTAL (OFF_FVWT + NM*DD/8)

__device__ float g_scratch[SCRATCH_TOTAL];

#define F_TRANSB 1
#define F_RELU   2
#define F_LEAKY  4
#define F_TE     8
#define F_BIAS   16
#define F_ADD    32

// ================= scalar FFMA2 GEMM (proven) ======================================
template<int F>
__device__ __forceinline__ void gemm_body(
    const float* __restrict__ A, const float* __restrict__ B,
    const float* __restrict__ bias, const float* __restrict__ addsrc,
    float* __restrict__ C, int Kd, int Nc, int ldc, int ktb, int kte)
{
    __shared__ float As[2][16][128];
    __shared__ float Bs[2][16][128];
    int tid = threadIdx.x;
    int tx = tid & 15, ty = tid >> 4;
    int m0 = blockIdx.y << 6, n0 = blockIdx.x << 7;

    int ar = tid >> 1, ac = (tid & 1) << 3;
    const float* Ap = A + (int64_t)(m0 + ar) * Kd + ac;
    int bk = tid >> 3, bc = (tid & 7) << 4;
    const float* Bp = (F & F_TRANSB)
        ? B + (int64_t)(n0 + tid) * Kd
        : B + (int64_t)bk * Nc + n0 + bc;

    u64 acc[8][4];
    #pragma unroll
    for (int i = 0; i < 8; i++)
        #pragma unroll
        for (int p = 0; p < 4; p++) acc[i][p] = 0ull;

    float4 la0, la1, lb[4];
    auto loadG = [&](int kt) {
        la0 = *(const float4*)(Ap + kt * 16);
        la1 = *(const float4*)(Ap + kt * 16 + 4);
        if (F & F_TE) {
            int kb = kt * 16 + ac;
            la0.x += sinf((float)(kb + 0) * (5.0f / 63.0f));
            la0.y += sinf((float)(kb + 1) * (5.0f / 63.0f));
            la0.z += sinf((float)(kb + 2) * (5.0f / 63.0f));
            la0.w += sinf((float)(kb + 3) * (5.0f / 63.0f));
            la1.x += sinf((float)(kb + 4) * (5.0f / 63.0f));
            la1.y += sinf((float)(kb + 5) * (5.0f / 63.0f));
            la1.z += sinf((float)(kb + 6) * (5.0f / 63.0f));
            la1.w += sinf((float)(kb + 7) * (5.0f / 63.0f));
        }
        if (F & F_TRANSB) {
            #pragma unroll
            for (int u = 0; u < 4; u++) lb[u] = *(const float4*)(Bp + kt * 16 + 4 * u);
        } else {
            #pragma unroll
            for (int u = 0; u < 4; u++) lb[u] = *(const float4*)(Bp + (int64_t)(kt * 16) * Nc + 4 * u);
        }
    };
    auto storeS = [&](int bf) {
        *(u64*)&As[bf][ac + 0][2 * ar] = pk2(la0.x, la0.x);
        *(u64*)&As[bf][ac + 1][2 * ar] = pk2(la0.y, la0.y);
        *(u64*)&As[bf][ac + 2][2 * ar] = pk2(la0.z, la0.z);
        *(u64*)&As[bf][ac + 3][2 * ar] = pk2(la0.w, la0.w);
        *(u64*)&As[bf][ac + 4][2 * ar] = pk2(la1.x, la1.x);
        *(u64*)&As[bf][ac + 5][2 * ar] = pk2(la1.y, la1.y);
        *(u64*)&As[bf][ac + 6][2 * ar] = pk2(la1.z, la1.z);
        *(u64*)&As[bf][ac + 7][2 * ar] = pk2(la1.w, la1.w);
        if (F & F_TRANSB) {
            #pragma unroll
            for (int u = 0; u < 4; u++) {
                Bs[bf][4 * u + 0][tid] = lb[u].x; Bs[bf][4 * u + 1][tid] = lb[u].y;
                Bs[bf][4 * u + 2][tid] = lb[u].z; Bs[bf][4 * u + 3][tid] = lb[u].w;
            }
        } else {
            #pragma unroll
            for (int u = 0; u < 4; u++) *(float4*)&Bs[bf][bk][bc + 4 * u] = lb[u];
        }
    };

    loadG(ktb); storeS(0); __syncthreads();
    int buf = 0;
    for (int kt = ktb; kt < kte; kt++) {
        bool more = (kt + 1 < kte);
        if (more) loadG(kt + 1);
        #pragma unroll
        for (int kk = 0; kk < 16; kk++) {
            ulonglong2 aL0 = *(const ulonglong2*)&As[buf][kk][(ty << 3)];
            ulonglong2 aL1 = *(const ulonglong2*)&As[buf][kk][(ty << 3) + 4];
            ulonglong2 aH0 = *(const ulonglong2*)&As[buf][kk][64 + (ty << 3)];
            ulonglong2 aH1 = *(const ulonglong2*)&As[buf][kk][64 + (ty << 3) + 4];
            ulonglong2 b0  = *(const ulonglong2*)&Bs[buf][kk][(tx << 2)];
            ulonglong2 b1  = *(const ulonglong2*)&Bs[buf][kk][64 + (tx << 2)];
            u64 ad[8] = {aL0.x, aL0.y, aL1.x, aL1.y, aH0.x, aH0.y, aH1.x, aH1.y};
            u64 bd[4] = {b0.x, b0.y, b1.x, b1.y};
            #pragma unroll
            for (int i = 0; i < 8; i++) {
                fma2(acc[i][0], ad[i], bd[0]);
                fma2(acc[i][1], ad[i], bd[1]);
                fma2(acc[i][2], ad[i], bd[2]);
                fma2(acc[i][3], ad[i], bd[3]);
            }
        }
        if (more) { storeS(buf ^ 1); __syncthreads(); buf ^= 1; }
    }

    #pragma unroll
    for (int i = 0; i < 8; i++) {
        int row = m0 + ((i < 4) ? ((ty << 2) + i) : (32 + (ty << 2) + i - 4));
        float2 q0 = up2(acc[i][0]), q1 = up2(acc[i][1]);
        float2 q2 = up2(acc[i][2]), q3 = up2(acc[i][3]);
        float o[8] = {q0.x, q0.y, q1.x, q1.y, q2.x, q2.y, q3.x, q3.y};
        #pragma unroll
        for (int j = 0; j < 8; j++) {
            int col = n0 + ((j < 4) ? ((tx << 2) + j) : (64 + (tx << 2) + j - 4));
            float v = o[j];
            if (F & F_BIAS)  v += bias[col];
            if (F & F_RELU)  v = fmaxf(v, 0.0f);
            if (F & F_LEAKY) v = (v >= 0.0f) ? v : 0.2f * v;
            if (F & F_ADD)   v += addsrc[(int64_t)row * ldc + col];
            o[j] = v;
        }
        *(float4*)&C[(int64_t)row * ldc + n0 + (tx << 2)]      = make_float4(o[0], o[1], o[2], o[3]);
        *(float4*)&C[(int64_t)row * ldc + n0 + 64 + (tx << 2)] = make_float4(o[4], o[5], o[6], o[7]);
    }
}

template<int F, int NKS>
__global__ __launch_bounds__(128, 4)
void gemm_k(const float* __restrict__ A, const float* __restrict__ B,
            const float* __restrict__ bias, const float* __restrict__ addsrc,
            float* __restrict__ C, int Kd, int Nc, int ldc,
            int64_t sA, int64_t sB, int64_t sBias,
            int zdiv, int64_t sC1, int64_t sC2, int64_t sPart)
{
    int zz = blockIdx.z;
    int z = zz / NKS, ks = zz % NKS;
    int ktn = Kd >> 4;
    int ktb = ks * (ktn / NKS), kte = ktb + ktn / NKS;
    const float* bz = (F & F_BIAS) ? bias + sBias * z : nullptr;
    float* Cz = C + (int64_t)(z / zdiv) * sC1 + (int64_t)(z % zdiv) * sC2
                  + (int64_t)ks * sPart;
    gemm_body<F>(A + sA * z, B + sB * z, bz, addsrc, Cz, Kd, Nc, ldc, ktb, kte);
}

// ================= float2-granularity K-split reduce ===============================
template<int F, int NKS>
__global__ __launch_bounds__(256)
void reduce_k(const float2* __restrict__ P, const float* __restrict__ bias,
              const float2* __restrict__ addsrc, float2* __restrict__ C,
              int totalf2, int ncf2)
{
    int idx = blockIdx.x * 256 + threadIdx.x;
    if (idx >= totalf2) return;
    float2 s = P[idx];
    #pragma unroll
    for (int k = 1; k < NKS; k++) {
        float2 t = P[idx + (int64_t)k * totalf2];
        s.x += t.x; s.y += t.y;
    }
    if (F & F_BIAS) {
        float2 b = ((const float2*)bias)[idx % ncf2];
        s.x += b.x; s.y += b.y;
    }
    if (F & F_RELU) { s.x = fmaxf(s.x, 0.f); s.y = fmaxf(s.y, 0.f); }
    if (F & F_ADD)  { float2 a = addsrc[idx]; s.x += a.x; s.y += a.y; }
    C[idx] = s;
}

// ================= fused prep: h reduce (f2) + coalesced weight transposes =========
// grid: [0,256) h-reduce; [256,640) wtb tiles; [640,768) fvwt tiles
__global__ __launch_bounds__(256)
void fuse_prep_k(const float2* __restrict__ Ph, const float* __restrict__ fn_b2,
                 float2* __restrict__ h, __nv_bfloat16* __restrict__ hb,
                 const float* __restrict__ wk, const float* __restrict__ wq,
                 const float* __restrict__ wv, const float* __restrict__ fv_w1,
                 __nv_bfloat16* __restrict__ wtb, __nv_bfloat16* __restrict__ fvwt)
{
    int b = blockIdx.x, t = threadIdx.x;
    if (b < 256) {
        int idx = b * 256 + t;           // 65536 float2
        float2 s = Ph[idx];
        #pragma unroll
        for (int k = 1; k < 8; k++) {
            float2 v = Ph[idx + k * (NM * DD / 2)];
            s.x += v.x; s.y += v.y;
        }
        float2 bb = ((const float2*)fn_b2)[idx & 63];
        s.x += bb.x; s.y += bb.y;
        h[idx] = s;
        __nv_bfloat162 p = __floats2bfloat162_rn(s.x, s.y);
        *(uint32_t*)&hb[idx * 2] = *(uint32_t*)&p;
        return;
    }
    __shared__ float ts[32][33];
    int c = t & 31, r0 = t >> 5;
    if (b < 640) {        // wtb: mat mi of 24, tile ti of 16 (kb x nb)
        int q = b - 256;
        int mi = q >> 4, ti = q & 15;
        int kb = ti >> 2, nb = ti & 3;
        int w = mi / 8, hd = mi & 7;
        const float* src = ((w == 0) ? wk : (w == 1) ? wq : wv) + hd * 16384;
        #pragma unroll
        for (int i = 0; i < 4; i++) {
            int r = r0 + 8 * i;
            ts[r][c] = src[(kb * 32 + r) * 128 + nb * 32 + c];
        }
        __syncthreads();
        int ck = (t & 15) << 1, rn0 = t >> 4;
        __nv_bfloat16* dst = wtb + (int64_t)mi * 16384;
        #pragma unroll
        for (int i = 0; i < 2; i++) {
            int rn = rn0 + 16 * i;
            __nv_bfloat162 p = __floats2bfloat162_rn(ts[ck][rn], ts[ck + 1][rn]);
            *(uint32_t*)&dst[(nb * 32 + rn) * 128 + kb * 32 + ck] = *(uint32_t*)&p;
        }
    } else {              // fvwt: fv_w1 [1024k x 128n] -> [128n x 1024k]
        int q = b - 640;
        int kb = q >> 2, nb = q & 3;
        #pragma unroll
        for (int i = 0; i < 4; i++) {
            int r = r0 + 8 * i;
            ts[r][c] = fv_w1[(kb * 32 + r) * 128 + nb * 32 + c];
        }
        __syncthreads();
        int ck = (t & 15) << 1, rn0 = t >> 4;
        #pragma unroll
        for (int i = 0; i < 2; i++) {
            int rn = rn0 + 16 * i;
            __nv_bfloat162 p = __floats2bfloat162_rn(ts[ck][rn], ts[ck + 1][rn]);
            *(uint32_t*)&fvwt[(int64_t)(nb * 32 + rn) * 1024 + kb * 32 + ck] = *(uint32_t*)&p;
        }
    }
}

// ================= KQV via mma.sync ================================================
__global__ __launch_bounds__(256)
void kqv_mma_k(const __nv_bfloat16* __restrict__ hb, const __nv_bfloat16* __restrict__ wtb,
               const float* __restrict__ bk, const float* __restrict__ bq,
               const float* __restrict__ bv,
               __nv_bfloat16* __restrict__ Kb, __nv_bfloat16* __restrict__ Qb,
               __nv_bfloat16* __restrict__ Vtb)
{
    int z = blockIdx.z, which = z >> 3, head = z & 7;
    int m0 = blockIdx.y << 7;
    float acc[4][4][4] = {};
    mma_loop(hb + (int64_t)m0 * DD, DD,
             wtb + (int64_t)z * DD * DD, DD, DD / KT, acc);

    int lane = threadIdx.x & 31, wid = threadIdx.x >> 5;
    int wm = wid >> 2, wn = wid & 3;
    const float* bias = ((which == 0) ? bk : (which == 1) ? bq : bv) + head * DD;

    #pragma unroll
    for (int mf = 0; mf < 4; mf++) {
        #pragma unroll
        for (int nf = 0; nf < 4; nf++) {
            int r   = wm * 64 + mf * 16 + (lane >> 2);
            int col = wn * 32 + nf * 8 + ((lane & 3) << 1);
            float b0 = bias[col], b1 = bias[col + 1];
            float v00 = acc[mf][nf][0] + b0, v01 = acc[mf][nf][1] + b1;
            float v10 = acc[mf][nf][2] + b0, v11 = acc[mf][nf][3] + b1;
            if (which < 2) {
                __nv_bfloat16* out = ((which == 0) ? Kb : Qb) + (int64_t)head * NM * DD;
                __nv_bfloat162 p0 = __floats2bfloat162_rn(v00, v01);
                __nv_bfloat162 p1 = __floats2bfloat162_rn(v10, v11);
                *(uint32_t*)&out[(int64_t)(m0 + r) * DD + col]     = *(uint32_t*)&p0;
                *(uint32_t*)&out[(int64_t)(m0 + r + 8) * DD + col] = *(uint32_t*)&p1;
            } else {
                int node0 = m0 + r, node1 = m0 + r + 8;
                __nv_bfloat16* vt0 = Vtb + (int64_t)(head * 2 + (node0 >> 9)) * DD * MM;
                __nv_bfloat16* vt1 = Vtb + (int64_t)(head * 2 + (node1 >> 9)) * DD * MM;
                vt0[(int64_t)col * MM + (node0 & 511)]       = __float2bfloat16(v00);
                vt0[(int64_t)(col + 1) * MM + (node0 & 511)] = __float2bfloat16(v01);
                vt1[(int64_t)col * MM + (node1 & 511)]       = __float2bfloat16(v10);
                vt1[(int64_t)(col + 1) * MM + (node1 & 511)] = __float2bfloat16(v11);
            }
        }
    }
}

// ================= scores via mma.sync: S = leaky(K @ Q^T) =========================
__global__ __launch_bounds__(256)
void scores_mma_k(const __nv_bfloat16* __restrict__ Kb, const __nv_bfloat16* __restrict__ Qb,
                  float* __restrict__ S)
{
    int z = blockIdx.z, h = z >> 1, n = z & 1;
    int m0 = blockIdx.y << 7, n0 = blockIdx.x << 7;
    float acc[4][4][4] = {};
    mma_loop(Kb + ((int64_t)h * NM + n * MM + m0) * DD, DD,
             Qb + ((int64_t)h * NM + n * MM + n0) * DD, DD, DD / KT, acc);

    int lane = threadIdx.x & 31, wid = threadIdx.x >> 5;
    int wm = wid >> 2, wn = wid & 3;
    float* out = S + (int64_t)z * MM * MM;
    #pragma unroll
    for (int mf = 0; mf < 4; mf++) {
        #pragma unroll
        for (int nf = 0; nf < 4; nf++) {
            int r   = m0 + wm * 64 + mf * 16 + (lane >> 2);
            int col = n0 + wn * 32 + nf * 8 + ((lane & 3) << 1);
            float v0 = acc[mf][nf][0]; v0 = (v0 >= 0.f) ? v0 : 0.2f * v0;
            float v1 = acc[mf][nf][1]; v1 = (v1 >= 0.f) ? v1 : 0.2f * v1;
            float v2 = acc[mf][nf][2]; v2 = (v2 >= 0.f) ? v2 : 0.2f * v2;
            float v3 = acc[mf][nf][3]; v3 = (v3 >= 0.f) ? v3 : 0.2f * v3;
            *(float2*)&out[(int64_t)r * MM + col]       = make_float2(v0, v1);
            *(float2*)&out[(int64_t)(r + 8) * MM + col] = make_float2(v2, v3);
        }
    }
}

// ================= softmax: warp-per-row, no block barriers ========================
__global__ __launch_bounds__(256)
void softmax_k(const float* __restrict__ data, __nv_bfloat16* __restrict__ ab)
{
    int w = threadIdx.x >> 5, lane = threadIdx.x & 31;
    int64_t row = (int64_t)blockIdx.x * 8 + w;
    const float* p = data + row * MM + lane * 16;
    float4 v[4];
    #pragma unroll
    for (int i = 0; i < 4; i++) v[i] = *(const float4*)(p + 4 * i);

    float m = v[0].x;
    #pragma unroll
    for (int i = 0; i < 4; i++) {
        m = fmaxf(m, fmaxf(fmaxf(v[i].x, v[i].y), fmaxf(v[i].z, v[i].w)));
    }
    #pragma unroll
    for (int o = 16; o; o >>= 1) m = fmaxf(m, __shfl_xor_sync(0xffffffffu, m, o));

    float e[16];
    float s = 0.f;
    #pragma unroll
    for (int i = 0; i < 4; i++) {
        e[4 * i + 0] = __expf(v[i].x - m);
        e[4 * i + 1] = __expf(v[i].y - m);
        e[4 * i + 2] = __expf(v[i].z - m);
        e[4 * i + 3] = __expf(v[i].w - m);
        s += e[4 * i] + e[4 * i + 1] + e[4 * i + 2] + e[4 * i + 3];
    }
    #pragma unroll
    for (int o = 16; o; o >>= 1) s += __shfl_xor_sync(0xffffffffu, s, o);
    float inv = 1.0f / s;

    uint32_t pkd[8];
    #pragma unroll
    for (int i = 0; i < 8; i++) {
        __nv_bfloat162 pb = __floats2bfloat162_rn(e[2 * i] * inv, e[2 * i + 1] * inv);
        pkd[i] = *(uint32_t*)&pb;
    }
    __nv_bfloat16* o = ab + row * MM + lane * 16;
    *(uint4*)(o)     = *(uint4*)&pkd[0];
    *(uint4*)(o + 8) = *(uint4*)&pkd[4];
}

// ================= attV via mma.sync, M-tile 64, fused epilogue ====================
__global__ __launch_bounds__(256)
void attv_mma_k(const __nv_bfloat16* __restrict__ ab, const __nv_bfloat16* __restrict__ Vtb,
                __nv_bfloat16* __restrict__ attc)
{
    int z = blockIdx.z, h = z >> 1, n = z & 1;
    int m0 = blockIdx.y << 6;
    float acc[2][4][4] = {};
    mma_loop64(ab  + (int64_t)z * MM * MM + (int64_t)m0 * MM, MM,
               Vtb + (int64_t)z * DD * MM, MM, MM / KT, acc);

    int lane = threadIdx.x & 31, wid = threadIdx.x >> 5;
    int wm = wid >> 2, wn = wid & 3;
    #pragma unroll
    for (int mf = 0; mf < 2; mf++) {
        #pragma unroll
        for (int nf = 0; nf < 4; nf++) {
            int r   = m0 + wm * 32 + mf * 16 + (lane >> 2);
            int col = wn * 32 + nf * 8 + ((lane & 3) << 1);
            float v0 = acc[mf][nf][0]; v0 = (v0 >= 0.f) ? v0 : 0.2f * v0;
            float v1 = acc[mf][nf][1]; v1 = (v1 >= 0.f) ? v1 : 0.2f * v1;
            float v2 = acc[mf][nf][2]; v2 = (v2 >= 0.f) ? v2 : 0.2f * v2;
            float v3 = acc[mf][nf][3]; v3 = (v3 >= 0.f) ? v3 : 0.2f * v3;
            __nv_bfloat162 p0 = __floats2bfloat162_rn(v0, v1);
            __nv_bfloat162 p1 = __floats2bfloat162_rn(v2, v3);
            __nv_bfloat16* o0 = attc + (int64_t)(n * MM + r) * (HH * DD) + h * DD + col;
            __nv_bfloat16* o1 = attc + (int64_t)(n * MM + r + 8) * (HH * DD) + h * DD + col;
            *(uint32_t*)o0 = *(uint32_t*)&p0;
            *(uint32_t*)o1 = *(uint32_t*)&p1;
        }
    }
}

// ================= f_v hidden via mma.sync (K-split 8) =============================
__global__ __launch_bounds__(256)
void fv1_mma_k(const __nv_bfloat16* __restrict__ attcb, const __nv_bfloat16* __restrict__ fvwt,
               float* __restrict__ P)
{
    int ks = blockIdx.z;
    int m0 = blockIdx.y << 7;
    float acc[4][4][4] = {};
    mma_loop(attcb + (int64_t)m0 * (HH * DD) + ks * 128, HH * DD,
             fvwt + ks * 128, HH * DD, 128 / KT, acc);

    int lane = threadIdx.x & 31, wid = threadIdx.x >> 5;
    int wm = wid >> 2, wn = wid & 3;
    float* out = P + (int64_t)ks * NM * DD;
    #pragma unroll
    for (int mf = 0; mf < 4; mf++) {
        #pragma unroll
        for (int nf = 0; nf < 4; nf++) {
            int r   = m0 + wm * 64 + mf * 16 + (lane >> 2);
            int col = wn * 32 + nf * 8 + ((lane & 3) << 1);
            *(float2*)&out[(int64_t)r * DD + col]       = make_float2(acc[mf][nf][0], acc[mf][nf][1]);
            *(float2*)&out[(int64_t)(r + 8) * DD + col] = make_float2(acc[mf][nf][2], acc[mf][nf][3]);
        }
    }
}

// ================= edge kernel: packed f32x2 + abs-trick ===========================
// w*relu(s) = (w/2)*s + (w/2)*|s|  (exact 0 for s<0)
__global__ __launch_bounds__(256)
void edge_k(const float* __restrict__ AB, const float* __restrict__ b1,
            const float* __restrict__ w2, const float* __restrict__ b2,
            float* __restrict__ out)
{
    __shared__ float Ast[DD][68];    // duplicated pairs: [d][2i],[2i+1] = A[i][d]
    __shared__ float Bst[DD][36];    // natural: [d][j] (b1 folded)
    __shared__ u64 w2d[DD];          // (w/2, w/2) pairs
    int n  = blockIdx.z;
    int i0 = blockIdx.y << 5, j0 = blockIdx.x << 5;
    const float* Ab = AB + ((int64_t)n * MM + i0) * DD;
    const float* Bb = AB + (int64_t)NM * DD + ((int64_t)n * MM + j0) * DD;
    int t = threadIdx.x;
    if (t < DD) { float w = w2[t] * 0.5f; w2d[t] = pk2(w, w); }
    #pragma unroll
    for (int c = 0; c < 4; c++) {
        int idx = t + (c << 8);
        int r  = idx >> 5;
        int d4 = (idx & 31) << 2;
        float4 a = *(const float4*)(Ab + r * DD + d4);
        *(u64*)&Ast[d4 + 0][2 * r] = pk2(a.x, a.x);
        *(u64*)&Ast[d4 + 1][2 * r] = pk2(a.y, a.y);
        *(u64*)&Ast[d4 + 2][2 * r] = pk2(a.z, a.z);
        *(u64*)&Ast[d4 + 3][2 * r] = pk2(a.w, a.w);
        float4 bvl = *(const float4*)(Bb + r * DD + d4);
        float4 bb  = *(const float4*)(b1 + d4);
        Bst[d4 + 0][r] = bvl.x + bb.x; Bst[d4 + 1][r] = bvl.y + bb.y;
        Bst[d4 + 2][r] = bvl.z + bb.z; Bst[d4 + 3][r] = bvl.w + bb.w;
    }
    __syncthreads();
    int tx = t & 15, ty = t >> 4;
    const u64 MASK = 0x7FFFFFFF7FFFFFFFull;
    u64 acc0 = 0ull, acc1 = 0ull;    // (i=2ty, j-pair), (i=2ty+1, j-pair)
    #pragma unroll 4
    for (int d = 0; d < DD; d++) {
        u64 a0 = *(const u64*)&Ast[d][ty << 2];
        u64 a1 = *(const u64*)&Ast[d][(ty << 2) + 2];
        u64 bp = *(const u64*)&Bst[d][tx << 1];
        u64 wd = w2d[d];
        u64 s0 = add2(a0, bp);
        u64 s1 = add2(a1, bp);
        u64 t0 = s0 & MASK;
        u64 t1 = s1 & MASK;
        fma2(acc0, s0, wd); fma2(acc0, t0, wd);
        fma2(acc1, s1, wd); fma2(acc1, t1, wd);
    }
    float bb = b2[0];
    const float sc = 1.0f / (float)MM;
    int i = i0 + (ty << 1), j = j0 + (tx << 1);
    float2 q0 = up2(acc0), q1 = up2(acc1);
    float* o = out + ((int64_t)n * MM + i) * MM + j;
    *(float2*)o        = make_float2((q0.x + bb) * sc, (q0.y + bb) * sc);
    *(float2*)(o + MM) = make_float2((q1.x + bb) * sc, (q1.y + bb) * sc);
}

// ================= host launcher ===================================================
extern "C" void kernel_launch(void* const* d_in, const int* in_sizes, int n_in,
                              void* d_out, int out_size)
{
    const float* x     = (const float*)d_in[0];
    const float* fn_w1 = (const float*)d_in[1];
    const float* fn_b1 = (const float*)d_in[2];
    const float* fn_w2 = (const float*)d_in[3];
    const float* fn_b2 = (const float*)d_in[4];
    const float* wk    = (const float*)d_in[5];
    const float* bk    = (const float*)d_in[6];
    const float* wq    = (const float*)d_in[7];
    const float* bq    = (const float*)d_in[8];
    const float* wv    = (const float*)d_in[9];
    const float* bv    = (const float*)d_in[10];
    const float* fv_w1 = (const float*)d_in[11];
    const float* fv_b1 = (const float*)d_in[12];
    const float* fv_w2 = (const float*)d_in[13];
    const float* fv_b2 = (const float*)d_in[14];
    const float* fe_w1 = (const float*)d_in[15];
    const float* fe_b1 = (const float*)d_in[16];
    const float* fe_w2 = (const float*)d_in[17];
    const float* fe_b2 = (const float*)d_in[18];

    float* scratch = nullptr;
    cudaGetSymbolAddress((void**)&scratch, g_scratch);
    float* tmp  = scratch + OFF_TMP;
    float* h    = scratch + OFF_H;
    float* S    = scratch + OFF_S;
    float* P    = scratch + OFF_S;    // split partials while S dead
    float* t2   = scratch + OFF_T2;
    float* ABuf = scratch + OFF_AB;
    __nv_bfloat16* attcb = (__nv_bfloat16*)(scratch + OFF_ATTC);
    __nv_bfloat16* hb  = (__nv_bfloat16*)(scratch + OFF_HB);
    __nv_bfloat16* wtb = (__nv_bfloat16*)(scratch + OFF_WTB);
    __nv_bfloat16* Kb  = (__nv_bfloat16*)(scratch + OFF_KB);
    __nv_bfloat16* Qb  = (__nv_bfloat16*)(scratch + OFF_QB);
    __nv_bfloat16* Vtb = (__nv_bfloat16*)(scratch + OFF_VTB);
    __nv_bfloat16* alb = (__nv_bfloat16*)(scratch + OFF_ALB);
    __nv_bfloat16* fvwt = (__nv_bfloat16*)(scratch + OFF_FVWT);

    float* x2   = (float*)d_out;
    float* edge = (float*)d_out + NM * DD;

    dim3 gb(128);
    const int MN2  = NM * DD / 2;       // 65536 float2
    const int MN22 = NM * 2 * DD / 2;   // 131072 float2
    const int NC2  = DD / 2;            // 64
    const int NC22 = 2 * DD / 2;        // 128

    // 1) f_node hidden (scalar, K-split 2 + reduce)
    gemm_k<F_TE, 2><<<dim3(2, 16, 2), gb>>>(
        x, fn_w1, nullptr, nullptr, P, DIN, 2 * DD, 2 * DD, 0, 0, 0, 1, 0, 0,
        (int64_t)NM * 2 * DD);
    reduce_k<F_BIAS | F_RELU, 2><<<512, 256>>>(
        (const float2*)P, fn_b1, nullptr, (float2*)tmp, MN22, NC22);
    // 2) h (scalar, K-split 8) then fused reduce + bf16 prep
    float* Ph = P + NM * 2 * DD * 2;
    gemm_k<0, 8><<<dim3(1, 16, 8), gb>>>(
        tmp, fn_w2, nullptr, nullptr, Ph, 2 * DD, DD, DD, 0, 0, 0, 1, 0, 0,
        (int64_t)NM * DD);
    fuse_prep_k<<<768, 256>>>((const float2*)Ph, fn_b2, (float2*)h, hb,
                              wk, wq, wv, fv_w1, wtb, fvwt);
    // 3) K/Q/V via mma.sync
    kqv_mma_k<<<dim3(1, 8, 24), 256>>>(hb, wtb, bk, bq, bv, Kb, Qb, Vtb);
    // 4) scores via mma.sync (leaky)
    scores_mma_k<<<dim3(4, 4, 16), 256>>>(Kb, Qb, S);
    // 5) softmax (warp-per-row) -> bf16 alpha
    softmax_k<<<1024, 256>>>(S, alb);
    // 6) attV via mma.sync, M64 tiles, fused leaky+concat epilogue -> bf16 attc
    attv_mma_k<<<dim3(1, 8, 16), 256>>>(alb, Vtb, attcb);
    // 7) f_v hidden via mma.sync (K-split 8) + reduce (bias+relu)
    fv1_mma_k<<<dim3(1, 8, 8), 256>>>(attcb, fvwt, P);
    reduce_k<F_BIAS | F_RELU, 8><<<256, 256>>>(
        (const float2*)P, fv_b1, nullptr, (float2*)t2, MN2, NC2);
    // 8) x2 (scalar, K-split 4 + reduce add h)
    gemm_k<0, 4><<<dim3(1, 16, 4), gb>>>(
        t2, fv_w2, nullptr, nullptr, P, DD, DD, DD, 0, 0, 0, 1, 0, 0,
        (int64_t)NM * DD);
    reduce_k<F_BIAS | F_ADD, 4><<<256, 256>>>(
        (const float2*)P, fv_b2, (const float2*)h, (float2*)x2, MN2, NC2);
    // 9) A/B for edges (scalar, K-split 2 + reduce)
    gemm_k<0, 2><<<dim3(1, 16, 4), gb>>>(
        x2, fe_w1, nullptr, nullptr, P, DD, DD, DD,
        0, (int64_t)DD * DD, 0, 1, (int64_t)NM * DD, 0, (int64_t)2 * NM * DD);
    reduce_k<0, 2><<<512, 256>>>(
        (const float2*)P, nullptr, nullptr, (float2*)ABuf, 2 * MN2, NC2);
    // 10) edge (packed f32x2)
    edge_k<<<dim3(16, 16, NB), 256>>>(ABuf, fe_b1, fe_w2, fe_b2, edge);
}

// round 11
// speedup vs baseline: 3.0118x; 1.0308x over previous
#include <cuda_runtime.h>
#include <cuda_bf16.h>
#include <math.h>
#include <stdint.h>

#define NB 2
#define MM 512
#define DD 128
#define HH 8
#define DIN 64
#define NM (NB*MM)   // 1024

typedef unsigned long long u64;

// ================= packed f32x2 helpers ===========================================
__device__ __forceinline__ u64 pk2(float lo, float hi) {
    u64 r; asm("mov.b64 %0, {%1,%2};" : "=l"(r) : "f"(lo), "f"(hi)); return r;
}
__device__ __forceinline__ void fma2(u64& d, u64 a, u64 b) {
    asm("fma.rn.f32x2 %0, %1, %2, %0;" : "+l"(d) : "l"(a), "l"(b));
}
__device__ __forceinline__ u64 add2(u64 a, u64 b) {
    u64 r; asm("add.rn.f32x2 %0, %1, %2;" : "=l"(r) : "l"(a), "l"(b)); return r;
}
__device__ __forceinline__ float2 up2(u64 v) {
    float lo, hi; asm("mov.b64 {%0,%1}, %2;" : "=f"(lo), "=f"(hi) : "l"(v));
    return make_float2(lo, hi);
}

// ================= mma.sync helpers ================================================
__device__ __forceinline__ uint32_t smem_to_u32(const void* p) {
    uint32_t a;
    asm("{ .reg .u64 t; cvta.to.shared.u64 t, %1; cvt.u32.u64 %0, t; }" : "=r"(a) : "l"(p));
    return a;
}
__device__ __forceinline__ void ldsm4(uint32_t& r0, uint32_t& r1, uint32_t& r2,
                                      uint32_t& r3, uint32_t addr) {
    asm volatile("ldmatrix.sync.aligned.m8n8.x4.shared.b16 {%0,%1,%2,%3}, [%4];"
                 : "=r"(r0), "=r"(r1), "=r"(r2), "=r"(r3) : "r"(addr));
}
__device__ __forceinline__ void mma16816(float* d, uint32_t a0, uint32_t a1,
                                         uint32_t a2, uint32_t a3,
                                         uint32_t b0, uint32_t b1) {
    asm volatile("mma.sync.aligned.m16n8k16.row.col.f32.bf16.bf16.f32 "
                 "{%0,%1,%2,%3},{%4,%5,%6,%7},{%8,%9},{%0,%1,%2,%3};"
                 : "+f"(d[0]), "+f"(d[1]), "+f"(d[2]), "+f"(d[3])
                 : "r"(a0), "r"(a1), "r"(a2), "r"(a3), "r"(b0), "r"(b1));
}

#define KT 32
#define SPAD 40

// C[128,128] += A[128,K] @ B[128,K]^T. 256 thr, 8 warps (2x4). Double-buffered.
__device__ __forceinline__ void mma_loop(
    const __nv_bfloat16* __restrict__ A, int lda,
    const __nv_bfloat16* __restrict__ B, int ldb,
    int nkt, float acc[4][4][4])
{
    __shared__ __nv_bfloat16 As[2][128][SPAD];
    __shared__ __nv_bfloat16 Bs[2][128][SPAD];
    int tid = threadIdx.x, lane = tid & 31, wid = tid >> 5;
    int wm = wid >> 2, wn = wid & 3;

    int lrow = tid >> 1, lcol = (tid & 1) << 4;
    const __nv_bfloat16* Ag = A + (int64_t)lrow * lda + lcol;
    const __nv_bfloat16* Bg = B + (int64_t)lrow * ldb + lcol;

    uint32_t asb = smem_to_u32(As), bsb = smem_to_u32(Bs);
    int arow = ((lane >> 3) & 1) * 8 + (lane & 7);
    int acol = ((lane >> 4) & 1) * 8;
    int brow = ((lane >> 4) & 1) * 8 + (lane & 7);
    int bcol = ((lane >> 3) & 1) * 8;

    uint4 ra0, ra1, rb0, rb1;
    auto loadG = [&](int kt) {
        ra0 = *(const uint4*)(Ag + kt * KT);
        ra1 = *(const uint4*)(Ag + kt * KT + 8);
        rb0 = *(const uint4*)(Bg + kt * KT);
        rb1 = *(const uint4*)(Bg + kt * KT + 8);
    };
    auto storeS = [&](int bf) {
        *(uint4*)&As[bf][lrow][lcol]     = ra0;
        *(uint4*)&As[bf][lrow][lcol + 8] = ra1;
        *(uint4*)&Bs[bf][lrow][lcol]     = rb0;
        *(uint4*)&Bs[bf][lrow][lcol + 8] = rb1;
    };

    loadG(0); storeS(0); __syncthreads();
    int buf = 0;
    for (int kt = 0; kt < nkt; kt++) {
        bool more = (kt + 1 < nkt);
        if (more) loadG(kt + 1);
        #pragma unroll
        for (int kf = 0; kf < 2; kf++) {
            uint32_t a[4][4];
            #pragma unroll
            for (int mf = 0; mf < 4; mf++)
                ldsm4(a[mf][0], a[mf][1], a[mf][2], a[mf][3],
                      asb + (((buf * 128) + wm * 64 + mf * 16 + arow) * SPAD + kf * 16 + acol) * 2);
            uint32_t b[2][4];
            #pragma unroll
            for (int p = 0; p < 2; p++)
                ldsm4(b[p][0], b[p][1], b[p][2], b[p][3],
                      bsb + (((buf * 128) + wn * 32 + p * 16 + brow) * SPAD + kf * 16 + bcol) * 2);
            #pragma unroll
            for (int mf = 0; mf < 4; mf++)
                #pragma unroll
                for (int nf = 0; nf < 4; nf++)
                    mma16816(acc[mf][nf], a[mf][0], a[mf][1], a[mf][2], a[mf][3],
                             b[nf >> 1][(nf & 1) * 2], b[nf >> 1][(nf & 1) * 2 + 1]);
        }
        if (more) { storeS(buf ^ 1); __syncthreads(); buf ^= 1; }
    }
}

// C[64,128] += A[64,K] @ B[128,K]^T. 256 thr, 8 warps (2x4). Double-buffered.
__device__ __forceinline__ void mma_loop64(
    const __nv_bfloat16* __restrict__ A, int lda,
    const __nv_bfloat16* __restrict__ B, int ldb,
    int nkt, float acc[2][4][4])
{
    __shared__ __nv_bfloat16 As[2][64][SPAD];
    __shared__ __nv_bfloat16 Bs[2][128][SPAD];
    int tid = threadIdx.x, lane = tid & 31, wid = tid >> 5;
    int wm = wid >> 2, wn = wid & 3;

    int arow_l = tid >> 2, acol_l = (tid & 3) << 3;
    int lrow = tid >> 1, lcol = (tid & 1) << 4;
    const __nv_bfloat16* Ag = A + (int64_t)arow_l * lda + acol_l;
    const __nv_bfloat16* Bg = B + (int64_t)lrow * ldb + lcol;

    uint32_t asb = smem_to_u32(As), bsb = smem_to_u32(Bs);
    int arow = ((lane >> 3) & 1) * 8 + (lane & 7);
    int acol = ((lane >> 4) & 1) * 8;
    int brow = ((lane >> 4) & 1) * 8 + (lane & 7);
    int bcol = ((lane >> 3) & 1) * 8;

    uint4 ra, rb0, rb1;
    auto loadG = [&](int kt) {
        ra  = *(const uint4*)(Ag + kt * KT);
        rb0 = *(const uint4*)(Bg + kt * KT);
        rb1 = *(const uint4*)(Bg + kt * KT + 8);
    };
    auto storeS = [&](int bf) {
        *(uint4*)&As[bf][arow_l][acol_l] = ra;
        *(uint4*)&Bs[bf][lrow][lcol]     = rb0;
        *(uint4*)&Bs[bf][lrow][lcol + 8] = rb1;
    };

    loadG(0); storeS(0); __syncthreads();
    int buf = 0;
    for (int kt = 0; kt < nkt; kt++) {
        bool more = (kt + 1 < nkt);
        if (more) loadG(kt + 1);
        #pragma unroll
        for (int kf = 0; kf < 2; kf++) {
            uint32_t a[2][4];
            #pragma unroll
            for (int mf = 0; mf < 2; mf++)
                ldsm4(a[mf][0], a[mf][1], a[mf][2], a[mf][3],
                      asb + (((buf * 64) + wm * 32 + mf * 16 + arow) * SPAD + kf * 16 + acol) * 2);
            uint32_t b[2][4];
            #pragma unroll
            for (int p = 0; p < 2; p++)
                ldsm4(b[p][0], b[p][1], b[p][2], b[p][3],
                      bsb + (((buf * 128) + wn * 32 + p * 16 + brow) * SPAD + kf * 16 + bcol) * 2);
            #pragma unroll
            for (int mf = 0; mf < 2; mf++)
                #pragma unroll
                for (int nf = 0; nf < 4; nf++)
                    mma16816(acc[mf][nf], a[mf][0], a[mf][1], a[mf][2], a[mf][3],
                             b[nf >> 1][(nf & 1) * 2], b[nf >> 1][(nf & 1) * 2 + 1]);
        }
        if (more) { storeS(buf ^ 1); __syncthreads(); buf ^= 1; }
    }
}

// ================= scratch =========================================================
#define OFF_TMP   0
#define OFF_H     (OFF_TMP + NM*2*DD)
#define OFF_S     (OFF_H   + NM*DD)
#define OFF_ATTC  (OFF_S   + HH*NB*MM*MM)
#define OFF_T2    (OFF_ATTC+ HH*NM*DD)
#define OFF_AB    (OFF_T2  + NM*DD)
#define OFF_HB    (OFF_AB  + 2*NM*DD)
#define OFF_WTB   (OFF_HB  + NM*DD/2)
#define OFF_KB    (OFF_WTB + 3*HH*DD*DD/2)
#define OFF_QB    (OFF_KB  + HH*NM*DD/2)
#define OFF_VTB   (OFF_QB  + HH*NM*DD/2)
#define OFF_ALB   (OFF_VTB + HH*NM*DD/2)
#define OFF_FVWT  (OFF_ALB + HH*NB*MM*MM/2)
#define SCRATCH_TOTAL (OFF_FVWT + NM*DD/8)

__device__ float g_scratch[SCRATCH_TOTAL];

#define F_TRANSB 1
#define F_RELU   2
#define F_LEAKY  4
#define F_TE     8
#define F_BIAS   16
#define F_ADD    32
#define F_AR     64   // A = relu(sum_{r<nra} A[r*strideAR] + abias[kcol])

// ================= scalar FFMA2 GEMM ===============================================
template<int F>
__device__ __forceinline__ void gemm_body(
    const float* __restrict__ A, const float* __restrict__ B,
    const float* __restrict__ bias, const float* __restrict__ addsrc,
    float* __restrict__ C, int Kd, int Nc, int ldc, int ktb, int kte,
    const float* __restrict__ abias, int nra, int64_t strideAR)
{
    __shared__ float As[2][16][128];
    __shared__ float Bs[2][16][128];
    int tid = threadIdx.x;
    int tx = tid & 15, ty = tid >> 4;
    int m0 = blockIdx.y << 6, n0 = blockIdx.x << 7;

    int ar = tid >> 1, ac = (tid & 1) << 3;
    const float* Ap = A + (int64_t)(m0 + ar) * Kd + ac;
    int bk = tid >> 3, bc = (tid & 7) << 4;
    const float* Bp = (F & F_TRANSB)
        ? B + (int64_t)(n0 + tid) * Kd
        : B + (int64_t)bk * Nc + n0 + bc;

    u64 acc[8][4];
    #pragma unroll
    for (int i = 0; i < 8; i++)
        #pragma unroll
        for (int p = 0; p < 4; p++) acc[i][p] = 0ull;

    float4 la0, la1, lb[4];
    auto loadG = [&](int kt) {
        la0 = *(const float4*)(Ap + kt * 16);
        la1 = *(const float4*)(Ap + kt * 16 + 4);
        if (F & F_AR) {
            for (int r = 1; r < nra; r++) {
                float4 u0 = *(const float4*)(Ap + r * strideAR + kt * 16);
                float4 u1 = *(const float4*)(Ap + r * strideAR + kt * 16 + 4);
                la0.x += u0.x; la0.y += u0.y; la0.z += u0.z; la0.w += u0.w;
                la1.x += u1.x; la1.y += u1.y; la1.z += u1.z; la1.w += u1.w;
            }
            float4 b0 = *(const float4*)(abias + kt * 16 + ac);
            float4 b1 = *(const float4*)(abias + kt * 16 + ac + 4);
            la0.x = fmaxf(la0.x + b0.x, 0.f); la0.y = fmaxf(la0.y + b0.y, 0.f);
            la0.z = fmaxf(la0.z + b0.z, 0.f); la0.w = fmaxf(la0.w + b0.w, 0.f);
            la1.x = fmaxf(la1.x + b1.x, 0.f); la1.y = fmaxf(la1.y + b1.y, 0.f);
            la1.z = fmaxf(la1.z + b1.z, 0.f); la1.w = fmaxf(la1.w + b1.w, 0.f);
        }
        if (F & F_TE) {
            int kb = kt * 16 + ac;
            la0.x += sinf((float)(kb + 0) * (5.0f / 63.0f));
            la0.y += sinf((float)(kb + 1) * (5.0f / 63.0f));
            la0.z += sinf((float)(kb + 2) * (5.0f / 63.0f));
            la0.w += sinf((float)(kb + 3) * (5.0f / 63.0f));
            la1.x += sinf((float)(kb + 4) * (5.0f / 63.0f));
            la1.y += sinf((float)(kb + 5) * (5.0f / 63.0f));
            la1.z += sinf((float)(kb + 6) * (5.0f / 63.0f));
            la1.w += sinf((float)(kb + 7) * (5.0f / 63.0f));
        }
        if (F & F_TRANSB) {
            #pragma unroll
            for (int u = 0; u < 4; u++) lb[u] = *(const float4*)(Bp + kt * 16 + 4 * u);
        } else {
            #pragma unroll
            for (int u = 0; u < 4; u++) lb[u] = *(const float4*)(Bp + (int64_t)(kt * 16) * Nc + 4 * u);
        }
    };
    auto storeS = [&](int bf) {
        *(u64*)&As[bf][ac + 0][2 * ar] = pk2(la0.x, la0.x);
        *(u64*)&As[bf][ac + 1][2 * ar] = pk2(la0.y, la0.y);
        *(u64*)&As[bf][ac + 2][2 * ar] = pk2(la0.z, la0.z);
        *(u64*)&As[bf][ac + 3][2 * ar] = pk2(la0.w, la0.w);
        *(u64*)&As[bf][ac + 4][2 * ar] = pk2(la1.x, la1.x);
        *(u64*)&As[bf][ac + 5][2 * ar] = pk2(la1.y, la1.y);
        *(u64*)&As[bf][ac + 6][2 * ar] = pk2(la1.z, la1.z);
        *(u64*)&As[bf][ac + 7][2 * ar] = pk2(la1.w, la1.w);
        if (F & F_TRANSB) {
            #pragma unroll
            for (int u = 0; u < 4; u++) {
                Bs[bf][4 * u + 0][tid] = lb[u].x; Bs[bf][4 * u + 1][tid] = lb[u].y;
                Bs[bf][4 * u + 2][tid] = lb[u].z; Bs[bf][4 * u + 3][tid] = lb[u].w;
            }
        } else {
            #pragma unroll
            for (int u = 0; u < 4; u++) *(float4*)&Bs[bf][bk][bc + 4 * u] = lb[u];
        }
    };

    loadG(ktb); storeS(0); __syncthreads();
    int buf = 0;
    for (int kt = ktb; kt < kte; kt++) {
        bool more = (kt + 1 < kte);
        if (more) loadG(kt + 1);
        #pragma unroll
        for (int kk = 0; kk < 16; kk++) {
            ulonglong2 aL0 = *(const ulonglong2*)&As[buf][kk][(ty << 3)];
            ulonglong2 aL1 = *(const ulonglong2*)&As[buf][kk][(ty << 3) + 4];
            ulonglong2 aH0 = *(const ulonglong2*)&As[buf][kk][64 + (ty << 3)];
            ulonglong2 aH1 = *(const ulonglong2*)&As[buf][kk][64 + (ty << 3) + 4];
            ulonglong2 b0  = *(const ulonglong2*)&Bs[buf][kk][(tx << 2)];
            ulonglong2 b1  = *(const ulonglong2*)&Bs[buf][kk][64 + (tx << 2)];
            u64 ad[8] = {aL0.x, aL0.y, aL1.x, aL1.y, aH0.x, aH0.y, aH1.x, aH1.y};
            u64 bd[4] = {b0.x, b0.y, b1.x, b1.y};
            #pragma unroll
            for (int i = 0; i < 8; i++) {
                fma2(acc[i][0], ad[i], bd[0]);
                fma2(acc[i][1], ad[i], bd[1]);
                fma2(acc[i][2], ad[i], bd[2]);
                fma2(acc[i][3], ad[i], bd[3]);
            }
        }
        if (more) { storeS(buf ^ 1); __syncthreads(); buf ^= 1; }
    }

    #pragma unroll
    for (int i = 0; i < 8; i++) {
        int row = m0 + ((i < 4) ? ((ty << 2) + i) : (32 + (ty << 2) + i - 4));
        float2 q0 = up2(acc[i][0]), q1 = up2(acc[i][1]);
        float2 q2 = up2(acc[i][2]), q3 = up2(acc[i][3]);
        float o[8] = {q0.x, q0.y, q1.x, q1.y, q2.x, q2.y, q3.x, q3.y};
        #pragma unroll
        for (int j = 0; j < 8; j++) {
            int col = n0 + ((j < 4) ? ((tx << 2) + j) : (64 + (tx << 2) + j - 4));
            float v = o[j];
            if (F & F_BIAS)  v += bias[col];
            if (F & F_RELU)  v = fmaxf(v, 0.0f);
            if (F & F_LEAKY) v = (v >= 0.0f) ? v : 0.2f * v;
            if (F & F_ADD)   v += addsrc[(int64_t)row * ldc + col];
            o[j] = v;
        }
        *(float4*)&C[(int64_t)row * ldc + n0 + (tx << 2)]      = make_float4(o[0], o[1], o[2], o[3]);
        *(float4*)&C[(int64_t)row * ldc + n0 + 64 + (tx << 2)] = make_float4(o[4], o[5], o[6], o[7]);
    }
}

template<int F, int NKS>
__global__ __launch_bounds__(128, 4)
void gemm_k(const float* __restrict__ A, const float* __restrict__ B,
            const float* __restrict__ bias, const float* __restrict__ addsrc,
            float* __restrict__ C, int Kd, int Nc, int ldc,
            int64_t sA, int64_t sB, int64_t sBias,
            int zdiv, int64_t sC1, int64_t sC2, int64_t sPart,
            const float* abias, int nra, int64_t strideAR)
{
    int zz = blockIdx.z;
    int z = zz / NKS, ks = zz % NKS;
    int ktn = Kd >> 4;
    int ktb = ks * (ktn / NKS), kte = ktb + ktn / NKS;
    const float* bz = (F & F_BIAS) ? bias + sBias * z : nullptr;
    float* Cz = C + (int64_t)(z / zdiv) * sC1 + (int64_t)(z % zdiv) * sC2
                  + (int64_t)ks * sPart;
    gemm_body<F>(A + sA * z, B + sB * z, bz, addsrc, Cz, Kd, Nc, ldc, ktb, kte,
                 abias, nra, strideAR);
}

// ================= float2-granularity K-split reduce ===============================
template<int F, int NKS>
__global__ __launch_bounds__(256)
void reduce_k(const float2* __restrict__ P, const float* __restrict__ bias,
              const float2* __restrict__ addsrc, float2* __restrict__ C,
              int totalf2, int ncf2)
{
    int idx = blockIdx.x * 256 + threadIdx.x;
    if (idx >= totalf2) return;
    float2 s = P[idx];
    #pragma unroll
    for (int k = 1; k < NKS; k++) {
        float2 t = P[idx + (int64_t)k * totalf2];
        s.x += t.x; s.y += t.y;
    }
    if (F & F_BIAS) {
        float2 b = ((const float2*)bias)[idx % ncf2];
        s.x += b.x; s.y += b.y;
    }
    if (F & F_RELU) { s.x = fmaxf(s.x, 0.f); s.y = fmaxf(s.y, 0.f); }
    if (F & F_ADD)  { float2 a = addsrc[idx]; s.x += a.x; s.y += a.y; }
    C[idx] = s;
}

// ================= fused prep: h reduce (f2) + coalesced weight transposes =========
__global__ __launch_bounds__(256)
void fuse_prep_k(const float2* __restrict__ Ph, const float* __restrict__ fn_b2,
                 float2* __restrict__ h, __nv_bfloat16* __restrict__ hb,
                 const float* __restrict__ wk, const float* __restrict__ wq,
                 const float* __restrict__ wv, const float* __restrict__ fv_w1,
                 __nv_bfloat16* __restrict__ wtb, __nv_bfloat16* __restrict__ fvwt)
{
    int b = blockIdx.x, t = threadIdx.x;
    if (b < 256) {
        int idx = b * 256 + t;
        float2 s = Ph[idx];
        #pragma unroll
        for (int k = 1; k < 8; k++) {
            float2 v = Ph[idx + k * (NM * DD / 2)];
            s.x += v.x; s.y += v.y;
        }
        float2 bb = ((const float2*)fn_b2)[idx & 63];
        s.x += bb.x; s.y += bb.y;
        h[idx] = s;
        __nv_bfloat162 p = __floats2bfloat162_rn(s.x, s.y);
        *(uint32_t*)&hb[idx * 2] = *(uint32_t*)&p;
        return;
    }
    __shared__ float ts[32][33];
    int c = t & 31, r0 = t >> 5;
    if (b < 640) {
        int q = b - 256;
        int mi = q >> 4, ti = q & 15;
        int kb = ti >> 2, nb = ti & 3;
        int w = mi / 8, hd = mi & 7;
        const float* src = ((w == 0) ? wk : (w == 1) ? wq : wv) + hd * 16384;
        #pragma unroll
        for (int i = 0; i < 4; i++) {
            int r = r0 + 8 * i;
            ts[r][c] = src[(kb * 32 + r) * 128 + nb * 32 + c];
        }
        __syncthreads();
        int ck = (t & 15) << 1, rn0 = t >> 4;
        __nv_bfloat16* dst = wtb + (int64_t)mi * 16384;
        #pragma unroll
        for (int i = 0; i < 2; i++) {
            int rn = rn0 + 16 * i;
            __nv_bfloat162 p = __floats2bfloat162_rn(ts[ck][rn], ts[ck + 1][rn]);
            *(uint32_t*)&dst[(nb * 32 + rn) * 128 + kb * 32 + ck] = *(uint32_t*)&p;
        }
    } else {
        int q = b - 640;
        int kb = q >> 2, nb = q & 3;
        #pragma unroll
        for (int i = 0; i < 4; i++) {
            int r = r0 + 8 * i;
            ts[r][c] = fv_w1[(kb * 32 + r) * 128 + nb * 32 + c];
        }
        __syncthreads();
        int ck = (t & 15) << 1, rn0 = t >> 4;
        #pragma unroll
        for (int i = 0; i < 2; i++) {
            int rn = rn0 + 16 * i;
            __nv_bfloat162 p = __floats2bfloat162_rn(ts[ck][rn], ts[ck + 1][rn]);
            *(uint32_t*)&fvwt[(int64_t)(nb * 32 + rn) * 1024 + kb * 32 + ck] = *(uint32_t*)&p;
        }
    }
}

// ================= KQV via mma.sync ================================================
__global__ __launch_bounds__(256)
void kqv_mma_k(const __nv_bfloat16* __restrict__ hb, const __nv_bfloat16* __restrict__ wtb,
               const float* __restrict__ bk, const float* __restrict__ bq,
               const float* __restrict__ bv,
               __nv_bfloat16* __restrict__ Kb, __nv_bfloat16* __restrict__ Qb,
               __nv_bfloat16* __restrict__ Vtb)
{
    int z = blockIdx.z, which = z >> 3, head = z & 7;
    int m0 = blockIdx.y << 7;
    float acc[4][4][4] = {};
    mma_loop(hb + (int64_t)m0 * DD, DD,
             wtb + (int64_t)z * DD * DD, DD, DD / KT, acc);

    int lane = threadIdx.x & 31, wid = threadIdx.x >> 5;
    int wm = wid >> 2, wn = wid & 3;
    const float* bias = ((which == 0) ? bk : (which == 1) ? bq : bv) + head * DD;

    #pragma unroll
    for (int mf = 0; mf < 4; mf++) {
        #pragma unroll
        for (int nf = 0; nf < 4; nf++) {
            int r   = wm * 64 + mf * 16 + (lane >> 2);
            int col = wn * 32 + nf * 8 + ((lane & 3) << 1);
            float b0 = bias[col], b1 = bias[col + 1];
            float v00 = acc[mf][nf][0] + b0, v01 = acc[mf][nf][1] + b1;
            float v10 = acc[mf][nf][2] + b0, v11 = acc[mf][nf][3] + b1;
            if (which < 2) {
                __nv_bfloat16* out = ((which == 0) ? Kb : Qb) + (int64_t)head * NM * DD;
                __nv_bfloat162 p0 = __floats2bfloat162_rn(v00, v01);
                __nv_bfloat162 p1 = __floats2bfloat162_rn(v10, v11);
                *(uint32_t*)&out[(int64_t)(m0 + r) * DD + col]     = *(uint32_t*)&p0;
                *(uint32_t*)&out[(int64_t)(m0 + r + 8) * DD + col] = *(uint32_t*)&p1;
            } else {
                int node0 = m0 + r, node1 = m0 + r + 8;
                __nv_bfloat16* vt0 = Vtb + (int64_t)(head * 2 + (node0 >> 9)) * DD * MM;
                __nv_bfloat16* vt1 = Vtb + (int64_t)(head * 2 + (node1 >> 9)) * DD * MM;
                vt0[(int64_t)col * MM + (node0 & 511)]       = __float2bfloat16(v00);
                vt0[(int64_t)(col + 1) * MM + (node0 & 511)] = __float2bfloat16(v01);
                vt1[(int64_t)col * MM + (node1 & 511)]       = __float2bfloat16(v10);
                vt1[(int64_t)(col + 1) * MM + (node1 & 511)] = __float2bfloat16(v11);
            }
        }
    }
}

// ================= scores via mma.sync: S = leaky(K @ Q^T) =========================
__global__ __launch_bounds__(256)
void scores_mma_k(const __nv_bfloat16* __restrict__ Kb, const __nv_bfloat16* __restrict__ Qb,
                  float* __restrict__ S)
{
    int z = blockIdx.z, h = z >> 1, n = z & 1;
    int m0 = blockIdx.y << 7, n0 = blockIdx.x << 7;
    float acc[4][4][4] = {};
    mma_loop(Kb + ((int64_t)h * NM + n * MM + m0) * DD, DD,
             Qb + ((int64_t)h * NM + n * MM + n0) * DD, DD, DD / KT, acc);

    int lane = threadIdx.x & 31, wid = threadIdx.x >> 5;
    int wm = wid >> 2, wn = wid & 3;
    float* out = S + (int64_t)z * MM * MM;
    #pragma unroll
    for (int mf = 0; mf < 4; mf++) {
        #pragma unroll
        for (int nf = 0; nf < 4; nf++) {
            int r   = m0 + wm * 64 + mf * 16 + (lane >> 2);
            int col = n0 + wn * 32 + nf * 8 + ((lane & 3) << 1);
            float v0 = acc[mf][nf][0]; v0 = (v0 >= 0.f) ? v0 : 0.2f * v0;
            float v1 = acc[mf][nf][1]; v1 = (v1 >= 0.f) ? v1 : 0.2f * v1;
            float v2 = acc[mf][nf][2]; v2 = (v2 >= 0.f) ? v2 : 0.2f * v2;
            float v3 = acc[mf][nf][3]; v3 = (v3 >= 0.f) ? v3 : 0.2f * v3;
            *(float2*)&out[(int64_t)r * MM + col]       = make_float2(v0, v1);
            *(float2*)&out[(int64_t)(r + 8) * MM + col] = make_float2(v2, v3);
        }
    }
}

// ================= softmax: warp-per-row ===========================================
__global__ __launch_bounds__(256)
void softmax_k(const float* __restrict__ data, __nv_bfloat16* __restrict__ ab)
{
    int w = threadIdx.x >> 5, lane = threadIdx.x & 31;
    int64_t row = (int64_t)blockIdx.x * 8 + w;
    const float* p = data + row * MM + lane * 16;
    float4 v[4];
    #pragma unroll
    for (int i = 0; i < 4; i++) v[i] = *(const float4*)(p + 4 * i);

    float m = v[0].x;
    #pragma unroll
    for (int i = 0; i < 4; i++) {
        m = fmaxf(m, fmaxf(fmaxf(v[i].x, v[i].y), fmaxf(v[i].z, v[i].w)));
    }
    #pragma unroll
    for (int o = 16; o; o >>= 1) m = fmaxf(m, __shfl_xor_sync(0xffffffffu, m, o));

    float e[16];
    float s = 0.f;
    #pragma unroll
    for (int i = 0; i < 4; i++) {
        e[4 * i + 0] = __expf(v[i].x - m);
        e[4 * i + 1] = __expf(v[i].y - m);
        e[4 * i + 2] = __expf(v[i].z - m);
        e[4 * i + 3] = __expf(v[i].w - m);
        s += e[4 * i] + e[4 * i + 1] + e[4 * i + 2] + e[4 * i + 3];
    }
    #pragma unroll
    for (int o = 16; o; o >>= 1) s += __shfl_xor_sync(0xffffffffu, s, o);
    float inv = 1.0f / s;

    uint32_t pkd[8];
    #pragma unroll
    for (int i = 0; i < 8; i++) {
        __nv_bfloat162 pb = __floats2bfloat162_rn(e[2 * i] * inv, e[2 * i + 1] * inv);
        pkd[i] = *(uint32_t*)&pb;
    }
    __nv_bfloat16* o = ab + row * MM + lane * 16;
    *(uint4*)(o)     = *(uint4*)&pkd[0];
    *(uint4*)(o + 8) = *(uint4*)&pkd[4];
}

// ================= attV via mma.sync, M-tile 64, fused epilogue ====================
__global__ __launch_bounds__(256)
void attv_mma_k(const __nv_bfloat16* __restrict__ ab, const __nv_bfloat16* __restrict__ Vtb,
                __nv_bfloat16* __restrict__ attc)
{
    int z = blockIdx.z, h = z >> 1, n = z & 1;
    int m0 = blockIdx.y << 6;
    float acc[2][4][4] = {};
    mma_loop64(ab  + (int64_t)z * MM * MM + (int64_t)m0 * MM, MM,
               Vtb + (int64_t)z * DD * MM, MM, MM / KT, acc);

    int lane = threadIdx.x & 31, wid = threadIdx.x >> 5;
    int wm = wid >> 2, wn = wid & 3;
    #pragma unroll
    for (int mf = 0; mf < 2; mf++) {
        #pragma unroll
        for (int nf = 0; nf < 4; nf++) {
            int r   = m0 + wm * 32 + mf * 16 + (lane >> 2);
            int col = wn * 32 + nf * 8 + ((lane & 3) << 1);
            float v0 = acc[mf][nf][0]; v0 = (v0 >= 0.f) ? v0 : 0.2f * v0;
            float v1 = acc[mf][nf][1]; v1 = (v1 >= 0.f) ? v1 : 0.2f * v1;
            float v2 = acc[mf][nf][2]; v2 = (v2 >= 0.f) ? v2 : 0.2f * v2;
            float v3 = acc[mf][nf][3]; v3 = (v3 >= 0.f) ? v3 : 0.2f * v3;
            __nv_bfloat162 p0 = __floats2bfloat162_rn(v0, v1);
            __nv_bfloat162 p1 = __floats2bfloat162_rn(v2, v3);
            __nv_bfloat16* o0 = attc + (int64_t)(n * MM + r) * (HH * DD) + h * DD + col;
            __nv_bfloat16* o1 = attc + (int64_t)(n * MM + r + 8) * (HH * DD) + h * DD + col;
            *(uint32_t*)o0 = *(uint32_t*)&p0;
            *(uint32_t*)o1 = *(uint32_t*)&p1;
        }
    }
}

// ================= f_v hidden via mma.sync (K-split 8) =============================
__global__ __launch_bounds__(256)
void fv1_mma_k(const __nv_bfloat16* __restrict__ attcb, const __nv_bfloat16* __restrict__ fvwt,
               float* __restrict__ P)
{
    int ks = blockIdx.z;
    int m0 = blockIdx.y << 7;
    float acc[4][4][4] = {};
    mma_loop(attcb + (int64_t)m0 * (HH * DD) + ks * 128, HH * DD,
             fvwt + ks * 128, HH * DD, 128 / KT, acc);

    int lane = threadIdx.x & 31, wid = threadIdx.x >> 5;
    int wm = wid >> 2, wn = wid & 3;
    float* out = P + (int64_t)ks * NM * DD;
    #pragma unroll
    for (int mf = 0; mf < 4; mf++) {
        #pragma unroll
        for (int nf = 0; nf < 4; nf++) {
            int r   = m0 + wm * 64 + mf * 16 + (lane >> 2);
            int col = wn * 32 + nf * 8 + ((lane & 3) << 1);
            *(float2*)&out[(int64_t)r * DD + col]       = make_float2(acc[mf][nf][0], acc[mf][nf][1]);
            *(float2*)&out[(int64_t)(r + 8) * DD + col] = make_float2(acc[mf][nf][2], acc[mf][nf][3]);
        }
    }
}

// ================= edge kernel: packed f32x2 + abs-trick ===========================
__global__ __launch_bounds__(256)
void edge_k(const float* __restrict__ AB, const float* __restrict__ b1,
            const float* __restrict__ w2, const float* __restrict__ b2,
            float* __restrict__ out)
{
    __shared__ float Ast[DD][68];
    __shared__ float Bst[DD][36];
    __shared__ u64 w2d[DD];
    int n  = blockIdx.z;
    int i0 = blockIdx.y << 5, j0 = blockIdx.x << 5;
    const float* Ab = AB + ((int64_t)n * MM + i0) * DD;
    const float* Bb = AB + (int64_t)NM * DD + ((int64_t)n * MM + j0) * DD;
    int t = threadIdx.x;
    if (t < DD) { float w = w2[t] * 0.5f; w2d[t] = pk2(w, w); }
    #pragma unroll
    for (int c = 0; c < 4; c++) {
        int idx = t + (c << 8);
        int r  = idx >> 5;
        int d4 = (idx & 31) << 2;
        float4 a = *(const float4*)(Ab + r * DD + d4);
        *(u64*)&Ast[d4 + 0][2 * r] = pk2(a.x, a.x);
        *(u64*)&Ast[d4 + 1][2 * r] = pk2(a.y, a.y);
        *(u64*)&Ast[d4 + 2][2 * r] = pk2(a.z, a.z);
        *(u64*)&Ast[d4 + 3][2 * r] = pk2(a.w, a.w);
        float4 bvl = *(const float4*)(Bb + r * DD + d4);
        float4 bb  = *(const float4*)(b1 + d4);
        Bst[d4 + 0][r] = bvl.x + bb.x; Bst[d4 + 1][r] = bvl.y + bb.y;
        Bst[d4 + 2][r] = bvl.z + bb.z; Bst[d4 + 3][r] = bvl.w + bb.w;
    }
    __syncthreads();
    int tx = t & 15, ty = t >> 4;
    const u64 MASK = 0x7FFFFFFF7FFFFFFFull;
    u64 acc0 = 0ull, acc1 = 0ull;
    #pragma unroll 4
    for (int d = 0; d < DD; d++) {
        u64 a0 = *(const u64*)&Ast[d][ty << 2];
        u64 a1 = *(const u64*)&Ast[d][(ty << 2) + 2];
        u64 bp = *(const u64*)&Bst[d][tx << 1];
        u64 wd = w2d[d];
        u64 s0 = add2(a0, bp);
        u64 s1 = add2(a1, bp);
        u64 t0 = s0 & MASK;
        u64 t1 = s1 & MASK;
        fma2(acc0, s0, wd); fma2(acc0, t0, wd);
        fma2(acc1, s1, wd); fma2(acc1, t1, wd);
    }
    float bb = b2[0];
    const float sc = 1.0f / (float)MM;
    int i = i0 + (ty << 1), j = j0 + (tx << 1);
    float2 q0 = up2(acc0), q1 = up2(acc1);
    float* o = out + ((int64_t)n * MM + i) * MM + j;
    *(float2*)o        = make_float2((q0.x + bb) * sc, (q0.y + bb) * sc);
    *(float2*)(o + MM) = make_float2((q1.x + bb) * sc, (q1.y + bb) * sc);
}

// ================= host launcher ===================================================
extern "C" void kernel_launch(void* const* d_in, const int* in_sizes, int n_in,
                              void* d_out, int out_size)
{
    const float* x     = (const float*)d_in[0];
    const float* fn_w1 = (const float*)d_in[1];
    const float* fn_b1 = (const float*)d_in[2];
    const float* fn_w2 = (const float*)d_in[3];
    const float* fn_b2 = (const float*)d_in[4];
    const float* wk    = (const float*)d_in[5];
    const float* bk    = (const float*)d_in[6];
    const float* wq    = (const float*)d_in[7];
    const float* bq    = (const float*)d_in[8];
    const float* wv    = (const float*)d_in[9];
    const float* bv    = (const float*)d_in[10];
    const float* fv_w1 = (const float*)d_in[11];
    const float* fv_b1 = (const float*)d_in[12];
    const float* fv_w2 = (const float*)d_in[13];
    const float* fv_b2 = (const float*)d_in[14];
    const float* fe_w1 = (const float*)d_in[15];
    const float* fe_b1 = (const float*)d_in[16];
    const float* fe_w2 = (const float*)d_in[17];
    const float* fe_b2 = (const float*)d_in[18];

    float* scratch = nullptr;
    cudaGetSymbolAddress((void**)&scratch, g_scratch);
    float* h    = scratch + OFF_H;
    float* S    = scratch + OFF_S;
    float* P    = scratch + OFF_S;               // K-split partials while S dead
    float* ABuf = scratch + OFF_AB;
    __nv_bfloat16* attcb = (__nv_bfloat16*)(scratch + OFF_ATTC);
    __nv_bfloat16* hb  = (__nv_bfloat16*)(scratch + OFF_HB);
    __nv_bfloat16* wtb = (__nv_bfloat16*)(scratch + OFF_WTB);
    __nv_bfloat16* Kb  = (__nv_bfloat16*)(scratch + OFF_KB);
    __nv_bfloat16* Qb  = (__nv_bfloat16*)(scratch + OFF_QB);
    __nv_bfloat16* Vtb = (__nv_bfloat16*)(scratch + OFF_VTB);
    __nv_bfloat16* alb = (__nv_bfloat16*)(scratch + OFF_ALB);
    __nv_bfloat16* fvwt = (__nv_bfloat16*)(scratch + OFF_FVWT);

    float* x2   = (float*)d_out;
    float* edge = (float*)d_out + NM * DD;

    dim3 gb(128);
    const int MN2 = NM * DD / 2;     // 65536 float2
    const int NC2 = DD / 2;          // 64

    // 1) f_node hidden (scalar, K-split 2) -> partials at P (no reduce; fused into 2)
    gemm_k<F_TE, 2><<<dim3(2, 16, 2), gb>>>(
        x, fn_w1, nullptr, nullptr, P, DIN, 2 * DD, 2 * DD, 0, 0, 0, 1, 0, 0,
        (int64_t)NM * 2 * DD, nullptr, 1, 0);
    // 2) h (scalar, K-split 8); A-loader reduces f_node1 partials (sum2+fn_b1+relu)
    float* Ph = P + NM * 2 * DD * 2;
    gemm_k<F_AR, 8><<<dim3(1, 16, 8), gb>>>(
        P, fn_w2, nullptr, nullptr, Ph, 2 * DD, DD, DD, 0, 0, 0, 1, 0, 0,
        (int64_t)NM * DD, fn_b1, 2, (int64_t)NM * 2 * DD);
    fuse_prep_k<<<768, 256>>>((const float2*)Ph, fn_b2, (float2*)h, hb,
                              wk, wq, wv, fv_w1, wtb, fvwt);
    // 3) K/Q/V via mma.sync
    kqv_mma_k<<<dim3(1, 8, 24), 256>>>(hb, wtb, bk, bq, bv, Kb, Qb, Vtb);
    // 4) scores via mma.sync (leaky)
    scores_mma_k<<<dim3(4, 4, 16), 256>>>(Kb, Qb, S);
    // 5) softmax (warp-per-row) -> bf16 alpha
    softmax_k<<<1024, 256>>>(S, alb);
    // 6) attV via mma.sync, M64 tiles, fused leaky+concat epilogue -> bf16 attc
    attv_mma_k<<<dim3(1, 8, 16), 256>>>(alb, Vtb, attcb);
    // 7) f_v hidden via mma.sync (K-split 8) -> partials at P (reduce fused into 8)
    fv1_mma_k<<<dim3(1, 8, 8), 256>>>(attcb, fvwt, P);
    // 8) x2 (scalar, K-split 4); A-loader reduces fv1 partials (sum8+fv_b1+relu)
    float* P8 = P + 8 * NM * DD;
    gemm_k<F_AR, 4><<<dim3(1, 16, 4), gb>>>(
        P, fv_w2, nullptr, nullptr, P8, DD, DD, DD, 0, 0, 0, 1, 0, 0,
        (int64_t)NM * DD, fv_b1, 8, (int64_t)NM * DD);
    reduce_k<F_BIAS | F_ADD, 4><<<256, 256>>>(
        (const float2*)P8, fv_b2, (const float2*)h, (float2*)x2, MN2, NC2);
    // 9) A/B for edges (scalar, K-split 2 + reduce)
    float* P9 = P8 + 4 * NM * DD;
    gemm_k<0, 2><<<dim3(1, 16, 4), gb>>>(
        x2, fe_w1, nullptr, nullptr, P9, DD, DD, DD,
        0, (int64_t)DD * DD, 0, 1, (int64_t)NM * DD, 0, (int64_t)2 * NM * DD,
        nullptr, 1, 0);
    reduce_k<0, 2><<<512, 256>>>(
        (const float2*)P9, nullptr, nullptr, (float2*)ABuf, 2 * MN2, NC2);
    // 10) edge (packed f32x2)
    edge_k<<<dim3(16, 16, NB), 256>>>(ABuf, fe_b1, fe_w2, fe_b2, edge);
}

// round 12
// speedup vs baseline: 3.1336x; 1.0404x over previous
#include <cuda_runtime.h>
#include <cuda_bf16.h>
#include <math.h>
#include <stdint.h>

#define NB 2
#define MM 512
#define DD 128
#define HH 8
#define DIN 64
#define NM (NB*MM)   // 1024

typedef unsigned long long u64;

// ================= packed f32x2 helpers ===========================================
__device__ __forceinline__ u64 pk2(float lo, float hi) {
    u64 r; asm("mov.b64 %0, {%1,%2};" : "=l"(r) : "f"(lo), "f"(hi)); return r;
}
__device__ __forceinline__ void fma2(u64& d, u64 a, u64 b) {
    asm("fma.rn.f32x2 %0, %1, %2, %0;" : "+l"(d) : "l"(a), "l"(b));
}
__device__ __forceinline__ u64 add2(u64 a, u64 b) {
    u64 r; asm("add.rn.f32x2 %0, %1, %2;" : "=l"(r) : "l"(a), "l"(b)); return r;
}
__device__ __forceinline__ float2 up2(u64 v) {
    float lo, hi; asm("mov.b64 {%0,%1}, %2;" : "=f"(lo), "=f"(hi) : "l"(v));
    return make_float2(lo, hi);
}

// ================= mma.sync / cp.async helpers =====================================
__device__ __forceinline__ uint32_t smem_to_u32(const void* p) {
    uint32_t a;
    asm("{ .reg .u64 t; cvta.to.shared.u64 t, %1; cvt.u32.u64 %0, t; }" : "=r"(a) : "l"(p));
    return a;
}
__device__ __forceinline__ void ldsm4(uint32_t& r0, uint32_t& r1, uint32_t& r2,
                                      uint32_t& r3, uint32_t addr) {
    asm volatile("ldmatrix.sync.aligned.m8n8.x4.shared.b16 {%0,%1,%2,%3}, [%4];"
                 : "=r"(r0), "=r"(r1), "=r"(r2), "=r"(r3) : "r"(addr));
}
__device__ __forceinline__ void mma16816(float* d, uint32_t a0, uint32_t a1,
                                         uint32_t a2, uint32_t a3,
                                         uint32_t b0, uint32_t b1) {
    asm volatile("mma.sync.aligned.m16n8k16.row.col.f32.bf16.bf16.f32 "
                 "{%0,%1,%2,%3},{%4,%5,%6,%7},{%8,%9},{%0,%1,%2,%3};"
                 : "+f"(d[0]), "+f"(d[1]), "+f"(d[2]), "+f"(d[3])
                 : "r"(a0), "r"(a1), "r"(a2), "r"(a3), "r"(b0), "r"(b1));
}
__device__ __forceinline__ void cp16(uint32_t s, const void* g) {
    asm volatile("cp.async.cg.shared.global [%0], [%1], 16;" :: "r"(s), "l"(g));
}
#define CP_COMMIT() asm volatile("cp.async.commit_group;" ::: "memory")
#define CP_WAIT0()  asm volatile("cp.async.wait_group 0;" ::: "memory")

#define KT 32
#define SPAD 40

// C[128,128] += A[128,K] @ B[128,K]^T. 256 thr, 8 warps (2x4). cp.async 2-stage.
__device__ __forceinline__ void mma_loop(
    const __nv_bfloat16* __restrict__ A, int lda,
    const __nv_bfloat16* __restrict__ B, int ldb,
    int nkt, float acc[4][4][4])
{
    __shared__ __nv_bfloat16 As[2][128][SPAD];
    __shared__ __nv_bfloat16 Bs[2][128][SPAD];
    int tid = threadIdx.x, lane = tid & 31, wid = tid >> 5;
    int wm = wid >> 2, wn = wid & 3;

    int lrow = tid >> 1, lcol = (tid & 1) << 4;
    const __nv_bfloat16* Ag = A + (int64_t)lrow * lda + lcol;
    const __nv_bfloat16* Bg = B + (int64_t)lrow * ldb + lcol;

    uint32_t asb = smem_to_u32(As), bsb = smem_to_u32(Bs);
    int arow = ((lane >> 3) & 1) * 8 + (lane & 7);
    int acol = ((lane >> 4) & 1) * 8;
    int brow = ((lane >> 4) & 1) * 8 + (lane & 7);
    int bcol = ((lane >> 3) & 1) * 8;

    uint32_t adst = asb + (lrow * SPAD + lcol) * 2;
    uint32_t bdst = bsb + (lrow * SPAD + lcol) * 2;
    const uint32_t BUFB = 128 * SPAD * 2;

    auto issue = [&](int kt, int bf) {
        cp16(adst + bf * BUFB,      Ag + kt * KT);
        cp16(adst + bf * BUFB + 16, Ag + kt * KT + 8);
        cp16(bdst + bf * BUFB,      Bg + kt * KT);
        cp16(bdst + bf * BUFB + 16, Bg + kt * KT + 8);
        CP_COMMIT();
    };

    issue(0, 0);
    int buf = 0;
    for (int kt = 0; kt < nkt; kt++) {
        CP_WAIT0();
        __syncthreads();
        if (kt + 1 < nkt) issue(kt + 1, buf ^ 1);
        #pragma unroll
        for (int kf = 0; kf < 2; kf++) {
            uint32_t a[4][4];
            #pragma unroll
            for (int mf = 0; mf < 4; mf++)
                ldsm4(a[mf][0], a[mf][1], a[mf][2], a[mf][3],
                      asb + buf * BUFB + ((wm * 64 + mf * 16 + arow) * SPAD + kf * 16 + acol) * 2);
            uint32_t b[2][4];
            #pragma unroll
            for (int p = 0; p < 2; p++)
                ldsm4(b[p][0], b[p][1], b[p][2], b[p][3],
                      bsb + buf * BUFB + ((wn * 32 + p * 16 + brow) * SPAD + kf * 16 + bcol) * 2);
            #pragma unroll
            for (int mf = 0; mf < 4; mf++)
                #pragma unroll
                for (int nf = 0; nf < 4; nf++)
                    mma16816(acc[mf][nf], a[mf][0], a[mf][1], a[mf][2], a[mf][3],
                             b[nf >> 1][(nf & 1) * 2], b[nf >> 1][(nf & 1) * 2 + 1]);
        }
        buf ^= 1;
    }
}

// C[64,128] += A[64,K] @ B[128,K]^T. 256 thr, 8 warps (2x4). cp.async 2-stage.
__device__ __forceinline__ void mma_loop64(
    const __nv_bfloat16* __restrict__ A, int lda,
    const __nv_bfloat16* __restrict__ B, int ldb,
    int nkt, float acc[2][4][4])
{
    __shared__ __nv_bfloat16 As[2][64][SPAD];
    __shared__ __nv_bfloat16 Bs[2][128][SPAD];
    int tid = threadIdx.x, lane = tid & 31, wid = tid >> 5;
    int wm = wid >> 2, wn = wid & 3;

    int arow_l = tid >> 2, acol_l = (tid & 3) << 3;
    int lrow = tid >> 1, lcol = (tid & 1) << 4;
    const __nv_bfloat16* Ag = A + (int64_t)arow_l * lda + acol_l;
    const __nv_bfloat16* Bg = B + (int64_t)lrow * ldb + lcol;

    uint32_t asb = smem_to_u32(As), bsb = smem_to_u32(Bs);
    int arow = ((lane >> 3) & 1) * 8 + (lane & 7);
    int acol = ((lane >> 4) & 1) * 8;
    int brow = ((lane >> 4) & 1) * 8 + (lane & 7);
    int bcol = ((lane >> 3) & 1) * 8;

    uint32_t adst = asb + (arow_l * SPAD + acol_l) * 2;
    uint32_t bdst = bsb + (lrow * SPAD + lcol) * 2;
    const uint32_t ABUF = 64 * SPAD * 2;
    const uint32_t BBUF = 128 * SPAD * 2;

    auto issue = [&](int kt, int bf) {
        cp16(adst + bf * ABUF,      Ag + kt * KT);
        cp16(bdst + bf * BBUF,      Bg + kt * KT);
        cp16(bdst + bf * BBUF + 16, Bg + kt * KT + 8);
        CP_COMMIT();
    };

    issue(0, 0);
    int buf = 0;
    for (int kt = 0; kt < nkt; kt++) {
        CP_WAIT0();
        __syncthreads();
        if (kt + 1 < nkt) issue(kt + 1, buf ^ 1);
        #pragma unroll
        for (int kf = 0; kf < 2; kf++) {
            uint32_t a[2][4];
            #pragma unroll
            for (int mf = 0; mf < 2; mf++)
                ldsm4(a[mf][0], a[mf][1], a[mf][2], a[mf][3],
                      asb + buf * ABUF + ((wm * 32 + mf * 16 + arow) * SPAD + kf * 16 + acol) * 2);
            uint32_t b[2][4];
            #pragma unroll
            for (int p = 0; p < 2; p++)
                ldsm4(b[p][0], b[p][1], b[p][2], b[p][3],
                      bsb + buf * BBUF + ((wn * 32 + p * 16 + brow) * SPAD + kf * 16 + bcol) * 2);
            #pragma unroll
            for (int mf = 0; mf < 2; mf++)
                #pragma unroll
                for (int nf = 0; nf < 4; nf++)
                    mma16816(acc[mf][nf], a[mf][0], a[mf][1], a[mf][2], a[mf][3],
                             b[nf >> 1][(nf & 1) * 2], b[nf >> 1][(nf & 1) * 2 + 1]);
        }
        buf ^= 1;
    }
}

// ================= scratch =========================================================
#define OFF_TMP   0
#define OFF_H     (OFF_TMP + NM*2*DD)
#define OFF_S     (OFF_H   + NM*DD)
#define OFF_ATTC  (OFF_S   + HH*NB*MM*MM)
#define OFF_T2    (OFF_ATTC+ HH*NM*DD)
#define OFF_AB    (OFF_T2  + NM*DD)
#define OFF_HB    (OFF_AB  + 2*NM*DD)
#define OFF_WTB   (OFF_HB  + NM*DD/2)
#define OFF_KB    (OFF_WTB + 3*HH*DD*DD/2)
#define OFF_QB    (OFF_KB  + HH*NM*DD/2)
#define OFF_VTB   (OFF_QB  + HH*NM*DD/2)
#define OFF_ALB   (OFF_VTB + HH*NM*DD/2)
#define OFF_FVWT  (OFF_ALB + HH*NB*MM*MM/2)
#define SCRATCH_TOTAL (OFF_FVWT + NM*DD/8)

__device__ float g_scratch[SCRATCH_TOTAL];

#define F_TRANSB 1
#define F_RELU   2
#define F_LEAKY  4
#define F_TE     8
#define F_BIAS   16
#define F_ADD    32
#define F_AR     64

// ================= scalar FFMA2 GEMM ===============================================
template<int F>
__device__ __forceinline__ void gemm_body(
    const float* __restrict__ A, const float* __restrict__ B,
    const float* __restrict__ bias, const float* __restrict__ addsrc,
    float* __restrict__ C, int Kd, int Nc, int ldc, int ktb, int kte,
    const float* __restrict__ abias, int nra, int64_t strideAR)
{
    __shared__ float As[2][16][128];
    __shared__ float Bs[2][16][128];
    int tid = threadIdx.x;
    int tx = tid & 15, ty = tid >> 4;
    int m0 = blockIdx.y << 6, n0 = blockIdx.x << 7;

    int ar = tid >> 1, ac = (tid & 1) << 3;
    const float* Ap = A + (int64_t)(m0 + ar) * Kd + ac;
    int bk = tid >> 3, bc = (tid & 7) << 4;
    const float* Bp = (F & F_TRANSB)
        ? B + (int64_t)(n0 + tid) * Kd
        : B + (int64_t)bk * Nc + n0 + bc;

    u64 acc[8][4];
    #pragma unroll
    for (int i = 0; i < 8; i++)
        #pragma unroll
        for (int p = 0; p < 4; p++) acc[i][p] = 0ull;

    float4 la0, la1, lb[4];
    auto loadG = [&](int kt) {
        la0 = *(const float4*)(Ap + kt * 16);
        la1 = *(const float4*)(Ap + kt * 16 + 4);
        if (F & F_AR) {
            for (int r = 1; r < nra; r++) {
                float4 u0 = *(const float4*)(Ap + r * strideAR + kt * 16);
                float4 u1 = *(const float4*)(Ap + r * strideAR + kt * 16 + 4);
                la0.x += u0.x; la0.y += u0.y; la0.z += u0.z; la0.w += u0.w;
                la1.x += u1.x; la1.y += u1.y; la1.z += u1.z; la1.w += u1.w;
            }
            float4 b0 = *(const float4*)(abias + kt * 16 + ac);
            float4 b1 = *(const float4*)(abias + kt * 16 + ac + 4);
            la0.x = fmaxf(la0.x + b0.x, 0.f); la0.y = fmaxf(la0.y + b0.y, 0.f);
            la0.z = fmaxf(la0.z + b0.z, 0.f); la0.w = fmaxf(la0.w + b0.w, 0.f);
            la1.x = fmaxf(la1.x + b1.x, 0.f); la1.y = fmaxf(la1.y + b1.y, 0.f);
            la1.z = fmaxf(la1.z + b1.z, 0.f); la1.w = fmaxf(la1.w + b1.w, 0.f);
        }
        if (F & F_TE) {
            int kb = kt * 16 + ac;
            la0.x += sinf((float)(kb + 0) * (5.0f / 63.0f));
            la0.y += sinf((float)(kb + 1) * (5.0f / 63.0f));
            la0.z += sinf((float)(kb + 2) * (5.0f / 63.0f));
            la0.w += sinf((float)(kb + 3) * (5.0f / 63.0f));
            la1.x += sinf((float)(kb + 4) * (5.0f / 63.0f));
            la1.y += sinf((float)(kb + 5) * (5.0f / 63.0f));
            la1.z += sinf((float)(kb + 6) * (5.0f / 63.0f));
            la1.w += sinf((float)(kb + 7) * (5.0f / 63.0f));
        }
        if (F & F_TRANSB) {
            #pragma unroll
            for (int u = 0; u < 4; u++) lb[u] = *(const float4*)(Bp + kt * 16 + 4 * u);
        } else {
            #pragma unroll
            for (int u = 0; u < 4; u++) lb[u] = *(const float4*)(Bp + (int64_t)(kt * 16) * Nc + 4 * u);
        }
    };
    auto storeS = [&](int bf) {
        *(u64*)&As[bf][ac + 0][2 * ar] = pk2(la0.x, la0.x);
        *(u64*)&As[bf][ac + 1][2 * ar] = pk2(la0.y, la0.y);
        *(u64*)&As[bf][ac + 2][2 * ar] = pk2(la0.z, la0.z);
        *(u64*)&As[bf][ac + 3][2 * ar] = pk2(la0.w, la0.w);
        *(u64*)&As[bf][ac + 4][2 * ar] = pk2(la1.x, la1.x);
        *(u64*)&As[bf][ac + 5][2 * ar] = pk2(la1.y, la1.y);
        *(u64*)&As[bf][ac + 6][2 * ar] = pk2(la1.z, la1.z);
        *(u64*)&As[bf][ac + 7][2 * ar] = pk2(la1.w, la1.w);
        if (F & F_TRANSB) {
            #pragma unroll
            for (int u = 0; u < 4; u++) {
                Bs[bf][4 * u + 0][tid] = lb[u].x; Bs[bf][4 * u + 1][tid] = lb[u].y;
                Bs[bf][4 * u + 2][tid] = lb[u].z; Bs[bf][4 * u + 3][tid] = lb[u].w;
            }
        } else {
            #pragma unroll
            for (int u = 0; u < 4; u++) *(float4*)&Bs[bf][bk][bc + 4 * u] = lb[u];
        }
    };

    loadG(ktb); storeS(0); __syncthreads();
    int buf = 0;
    for (int kt = ktb; kt < kte; kt++) {
        bool more = (kt + 1 < kte);
        if (more) loadG(kt + 1);
        #pragma unroll
        for (int kk = 0; kk < 16; kk++) {
            ulonglong2 aL0 = *(const ulonglong2*)&As[buf][kk][(ty << 3)];
            ulonglong2 aL1 = *(const ulonglong2*)&As[buf][kk][(ty << 3) + 4];
            ulonglong2 aH0 = *(const ulonglong2*)&As[buf][kk][64 + (ty << 3)];
            ulonglong2 aH1 = *(const ulonglong2*)&As[buf][kk][64 + (ty << 3) + 4];
            ulonglong2 b0  = *(const ulonglong2*)&Bs[buf][kk][(tx << 2)];
            ulonglong2 b1  = *(const ulonglong2*)&Bs[buf][kk][64 + (tx << 2)];
            u64 ad[8] = {aL0.x, aL0.y, aL1.x, aL1.y, aH0.x, aH0.y, aH1.x, aH1.y};
            u64 bd[4] = {b0.x, b0.y, b1.x, b1.y};
            #pragma unroll
            for (int i = 0; i < 8; i++) {
                fma2(acc[i][0], ad[i], bd[0]);
                fma2(acc[i][1], ad[i], bd[1]);
                fma2(acc[i][2], ad[i], bd[2]);
                fma2(acc[i][3], ad[i], bd[3]);
            }
        }
        if (more) { storeS(buf ^ 1); __syncthreads(); buf ^= 1; }
    }

    #pragma unroll
    for (int i = 0; i < 8; i++) {
        int row = m0 + ((i < 4) ? ((ty << 2) + i) : (32 + (ty << 2) + i - 4));
        float2 q0 = up2(acc[i][0]), q1 = up2(acc[i][1]);
        float2 q2 = up2(acc[i][2]), q3 = up2(acc[i][3]);
        float o[8] = {q0.x, q0.y, q1.x, q1.y, q2.x, q2.y, q3.x, q3.y};
        #pragma unroll
        for (int j = 0; j < 8; j++) {
            int col = n0 + ((j < 4) ? ((tx << 2) + j) : (64 + (tx << 2) + j - 4));
            float v = o[j];
            if (F & F_BIAS)  v += bias[col];
            if (F & F_RELU)  v = fmaxf(v, 0.0f);
            if (F & F_LEAKY) v = (v >= 0.0f) ? v : 0.2f * v;
            if (F & F_ADD)   v += addsrc[(int64_t)row * ldc + col];
            o[j] = v;
        }
        *(float4*)&C[(int64_t)row * ldc + n0 + (tx << 2)]      = make_float4(o[0], o[1], o[2], o[3]);
        *(float4*)&C[(int64_t)row * ldc + n0 + 64 + (tx << 2)] = make_float4(o[4], o[5], o[6], o[7]);
    }
}

template<int F, int NKS>
__global__ __launch_bounds__(128, 4)
void gemm_k(const float* __restrict__ A, const float* __restrict__ B,
            const float* __restrict__ bias, const float* __restrict__ addsrc,
            float* __restrict__ C, int Kd, int Nc, int ldc,
            int64_t sA, int64_t sB, int64_t sBias,
            int zdiv, int64_t sC1, int64_t sC2, int64_t sPart,
            const float* abias, int nra, int64_t strideAR)
{
    int zz = blockIdx.z;
    int z = zz / NKS, ks = zz % NKS;
    int ktn = Kd >> 4;
    int ktb = ks * (ktn / NKS), kte = ktb + ktn / NKS;
    const float* bz = (F & F_BIAS) ? bias + sBias * z : nullptr;
    float* Cz = C + (int64_t)(z / zdiv) * sC1 + (int64_t)(z % zdiv) * sC2
                  + (int64_t)ks * sPart;
    gemm_body<F>(A + sA * z, B + sB * z, bz, addsrc, Cz, Kd, Nc, ldc, ktb, kte,
                 abias, nra, strideAR);
}

// ================= float2-granularity K-split reduce ===============================
template<int F, int NKS>
__global__ __launch_bounds__(256)
void reduce_k(const float2* __restrict__ P, const float* __restrict__ bias,
              const float2* __restrict__ addsrc, float2* __restrict__ C,
              int totalf2, int ncf2)
{
    int idx = blockIdx.x * 256 + threadIdx.x;
    if (idx >= totalf2) return;
    float2 s = P[idx];
    #pragma unroll
    for (int k = 1; k < NKS; k++) {
        float2 t = P[idx + (int64_t)k * totalf2];
        s.x += t.x; s.y += t.y;
    }
    if (F & F_BIAS) {
        float2 b = ((const float2*)bias)[idx % ncf2];
        s.x += b.x; s.y += b.y;
    }
    if (F & F_RELU) { s.x = fmaxf(s.x, 0.f); s.y = fmaxf(s.y, 0.f); }
    if (F & F_ADD)  { float2 a = addsrc[idx]; s.x += a.x; s.y += a.y; }
    C[idx] = s;
}

// ================= fused prep ======================================================
__global__ __launch_bounds__(256)
void fuse_prep_k(const float2* __restrict__ Ph, const float* __restrict__ fn_b2,
                 float2* __restrict__ h, __nv_bfloat16* __restrict__ hb,
                 const float* __restrict__ wk, const float* __restrict__ wq,
                 const float* __restrict__ wv, const float* __restrict__ fv_w1,
                 __nv_bfloat16* __restrict__ wtb, __nv_bfloat16* __restrict__ fvwt)
{
    int b = blockIdx.x, t = threadIdx.x;
    if (b < 256) {
        int idx = b * 256 + t;
        float2 s = Ph[idx];
        #pragma unroll
        for (int k = 1; k < 8; k++) {
            float2 v = Ph[idx + k * (NM * DD / 2)];
            s.x += v.x; s.y += v.y;
        }
        float2 bb = ((const float2*)fn_b2)[idx & 63];
        s.x += bb.x; s.y += bb.y;
        h[idx] = s;
        __nv_bfloat162 p = __floats2bfloat162_rn(s.x, s.y);
        *(uint32_t*)&hb[idx * 2] = *(uint32_t*)&p;
        return;
    }
    __shared__ float ts[32][33];
    int c = t & 31, r0 = t >> 5;
    if (b < 640) {
        int q = b - 256;
        int mi = q >> 4, ti = q & 15;
        int kb = ti >> 2, nb = ti & 3;
        int w = mi / 8, hd = mi & 7;
        const float* src = ((w == 0) ? wk : (w == 1) ? wq : wv) + hd * 16384;
        #pragma unroll
        for (int i = 0; i < 4; i++) {
            int r = r0 + 8 * i;
            ts[r][c] = src[(kb * 32 + r) * 128 + nb * 32 + c];
        }
        __syncthreads();
        int ck = (t & 15) << 1, rn0 = t >> 4;
        __nv_bfloat16* dst = wtb + (int64_t)mi * 16384;
        #pragma unroll
        for (int i = 0; i < 2; i++) {
            int rn = rn0 + 16 * i;
            __nv_bfloat162 p = __floats2bfloat162_rn(ts[ck][rn], ts[ck + 1][rn]);
            *(uint32_t*)&dst[(nb * 32 + rn) * 128 + kb * 32 + ck] = *(uint32_t*)&p;
        }
    } else {
        int q = b - 640;
        int kb = q >> 2, nb = q & 3;
        #pragma unroll
        for (int i = 0; i < 4; i++) {
            int r = r0 + 8 * i;
            ts[r][c] = fv_w1[(kb * 32 + r) * 128 + nb * 32 + c];
        }
        __syncthreads();
        int ck = (t & 15) << 1, rn0 = t >> 4;
        #pragma unroll
        for (int i = 0; i < 2; i++) {
            int rn = rn0 + 16 * i;
            __nv_bfloat162 p = __floats2bfloat162_rn(ts[ck][rn], ts[ck + 1][rn]);
            *(uint32_t*)&fvwt[(int64_t)(nb * 32 + rn) * 1024 + kb * 32 + ck] = *(uint32_t*)&p;
        }
    }
}

// ================= KQV via mma.sync (coalesced V^T epilogue) =======================
__global__ __launch_bounds__(256)
void kqv_mma_k(const __nv_bfloat16* __restrict__ hb, const __nv_bfloat16* __restrict__ wtb,
               const float* __restrict__ bk, const float* __restrict__ bq,
               const float* __restrict__ bv,
               __nv_bfloat16* __restrict__ Kb, __nv_bfloat16* __restrict__ Qb,
               __nv_bfloat16* __restrict__ Vtb)
{
    __shared__ __nv_bfloat16 Vs[128][136];
    int z = blockIdx.z, which = z >> 3, head = z & 7;
    int m0 = blockIdx.y << 7;
    float acc[4][4][4] = {};
    mma_loop(hb + (int64_t)m0 * DD, DD,
             wtb + (int64_t)z * DD * DD, DD, DD / KT, acc);

    int tid = threadIdx.x;
    int lane = tid & 31, wid = tid >> 5;
    int wm = wid >> 2, wn = wid & 3;
    const float* bias = ((which == 0) ? bk : (which == 1) ? bq : bv) + head * DD;

    if (which < 2) {
        __nv_bfloat16* out = ((which == 0) ? Kb : Qb) + (int64_t)head * NM * DD;
        #pragma unroll
        for (int mf = 0; mf < 4; mf++) {
            #pragma unroll
            for (int nf = 0; nf < 4; nf++) {
                int r   = wm * 64 + mf * 16 + (lane >> 2);
                int col = wn * 32 + nf * 8 + ((lane & 3) << 1);
                float b0 = bias[col], b1 = bias[col + 1];
                __nv_bfloat162 p0 = __floats2bfloat162_rn(acc[mf][nf][0] + b0, acc[mf][nf][1] + b1);
                __nv_bfloat162 p1 = __floats2bfloat162_rn(acc[mf][nf][2] + b0, acc[mf][nf][3] + b1);
                *(uint32_t*)&out[(int64_t)(m0 + r) * DD + col]     = *(uint32_t*)&p0;
                *(uint32_t*)&out[(int64_t)(m0 + r + 8) * DD + col] = *(uint32_t*)&p1;
            }
        }
    } else {
        __syncthreads();   // mma_loop smem reads done before Vs reuse? (separate array) — barrier for Vs fill order
        #pragma unroll
        for (int mf = 0; mf < 4; mf++) {
            #pragma unroll
            for (int nf = 0; nf < 4; nf++) {
                int r   = wm * 64 + mf * 16 + (lane >> 2);
                int col = wn * 32 + nf * 8 + ((lane & 3) << 1);
                float b0 = bias[col], b1 = bias[col + 1];
                Vs[col][r]         = __float2bfloat16(acc[mf][nf][0] + b0);
                Vs[col + 1][r]     = __float2bfloat16(acc[mf][nf][1] + b1);
                Vs[col][r + 8]     = __float2bfloat16(acc[mf][nf][2] + b0);
                Vs[col + 1][r + 8] = __float2bfloat16(acc[mf][nf][3] + b1);
            }
        }
        __syncthreads();
        int d = tid >> 1, half = tid & 1;
        int n = m0 >> 9;
        __nv_bfloat16* vt = Vtb + ((int64_t)(head * 2 + n) * DD + d) * MM
                            + (m0 & 511) + half * 64;
        #pragma unroll
        for (int q = 0; q < 8; q++)
            *(uint4*)(vt + 8 * q) = *(const uint4*)&Vs[d][half * 64 + 8 * q];
    }
}

// ================= scores via mma.sync: S = leaky(K @ Q^T) =========================
__global__ __launch_bounds__(256)
void scores_mma_k(const __nv_bfloat16* __restrict__ Kb, const __nv_bfloat16* __restrict__ Qb,
                  float* __restrict__ S)
{
    int z = blockIdx.z, h = z >> 1, n = z & 1;
    int m0 = blockIdx.y << 7, n0 = blockIdx.x << 7;
    float acc[4][4][4] = {};
    mma_loop(Kb + ((int64_t)h * NM + n * MM + m0) * DD, DD,
             Qb + ((int64_t)h * NM + n * MM + n0) * DD, DD, DD / KT, acc);

    int lane = threadIdx.x & 31, wid = threadIdx.x >> 5;
    int wm = wid >> 2, wn = wid & 3;
    float* out = S + (int64_t)z * MM * MM;
    #pragma unroll
    for (int mf = 0; mf < 4; mf++) {
        #pragma unroll
        for (int nf = 0; nf < 4; nf++) {
            int r   = m0 + wm * 64 + mf * 16 + (lane >> 2);
            int col = n0 + wn * 32 + nf * 8 + ((lane & 3) << 1);
            float v0 = acc[mf][nf][0]; v0 = (v0 >= 0.f) ? v0 : 0.2f * v0;
            float v1 = acc[mf][nf][1]; v1 = (v1 >= 0.f) ? v1 : 0.2f * v1;
            float v2 = acc[mf][nf][2]; v2 = (v2 >= 0.f) ? v2 : 0.2f * v2;
            float v3 = acc[mf][nf][3]; v3 = (v3 >= 0.f) ? v3 : 0.2f * v3;
            *(float2*)&out[(int64_t)r * MM + col]       = make_float2(v0, v1);
            *(float2*)&out[(int64_t)(r + 8) * MM + col] = make_float2(v2, v3);
        }
    }
}

// ================= softmax: warp-per-row ===========================================
__global__ __launch_bounds__(256)
void softmax_k(const float* __restrict__ data, __nv_bfloat16* __restrict__ ab)
{
    int w = threadIdx.x >> 5, lane = threadIdx.x & 31;
    int64_t row = (int64_t)blockIdx.x * 8 + w;
    const float* p = data + row * MM + lane * 16;
    float4 v[4];
    #pragma unroll
    for (int i = 0; i < 4; i++) v[i] = *(const float4*)(p + 4 * i);

    float m = v[0].x;
    #pragma unroll
    for (int i = 0; i < 4; i++) {
        m = fmaxf(m, fmaxf(fmaxf(v[i].x, v[i].y), fmaxf(v[i].z, v[i].w)));
    }
    #pragma unroll
    for (int o = 16; o; o >>= 1) m = fmaxf(m, __shfl_xor_sync(0xffffffffu, m, o));

    float e[16];
    float s = 0.f;
    #pragma unroll
    for (int i = 0; i < 4; i++) {
        e[4 * i + 0] = __expf(v[i].x - m);
        e[4 * i + 1] = __expf(v[i].y - m);
        e[4 * i + 2] = __expf(v[i].z - m);
        e[4 * i + 3] = __expf(v[i].w - m);
        s += e[4 * i] + e[4 * i + 1] + e[4 * i + 2] + e[4 * i + 3];
    }
    #pragma unroll
    for (int o = 16; o; o >>= 1) s += __shfl_xor_sync(0xffffffffu, s, o);
    float inv = 1.0f / s;

    uint32_t pkd[8];
    #pragma unroll
    for (int i = 0; i < 8; i++) {
        __nv_bfloat162 pb = __floats2bfloat162_rn(e[2 * i] * inv, e[2 * i + 1] * inv);
        pkd[i] = *(uint32_t*)&pb;
    }
    __nv_bfloat16* o = ab + row * MM + lane * 16;
    *(uint4*)(o)     = *(uint4*)&pkd[0];
    *(uint4*)(o + 8) = *(uint4*)&pkd[4];
}

// ================= attV via mma.sync, M-tile 64, fused epilogue ====================
__global__ __launch_bounds__(256)
void attv_mma_k(const __nv_bfloat16* __restrict__ ab, const __nv_bfloat16* __restrict__ Vtb,
                __nv_bfloat16* __restrict__ attc)
{
    int z = blockIdx.z, h = z >> 1, n = z & 1;
    int m0 = blockIdx.y << 6;
    float acc[2][4][4] = {};
    mma_loop64(ab  + (int64_t)z * MM * MM + (int64_t)m0 * MM, MM,
               Vtb + (int64_t)z * DD * MM, MM, MM / KT, acc);

    int lane = threadIdx.x & 31, wid = threadIdx.x >> 5;
    int wm = wid >> 2, wn = wid & 3;
    #pragma unroll
    for (int mf = 0; mf < 2; mf++) {
        #pragma unroll
        for (int nf = 0; nf < 4; nf++) {
            int r   = m0 + wm * 32 + mf * 16 + (lane >> 2);
            int col = wn * 32 + nf * 8 + ((lane & 3) << 1);
            float v0 = acc[mf][nf][0]; v0 = (v0 >= 0.f) ? v0 : 0.2f * v0;
            float v1 = acc[mf][nf][1]; v1 = (v1 >= 0.f) ? v1 : 0.2f * v1;
            float v2 = acc[mf][nf][2]; v2 = (v2 >= 0.f) ? v2 : 0.2f * v2;
            float v3 = acc[mf][nf][3]; v3 = (v3 >= 0.f) ? v3 : 0.2f * v3;
            __nv_bfloat162 p0 = __floats2bfloat162_rn(v0, v1);
            __nv_bfloat162 p1 = __floats2bfloat162_rn(v2, v3);
            __nv_bfloat16* o0 = attc + (int64_t)(n * MM + r) * (HH * DD) + h * DD + col;
            __nv_bfloat16* o1 = attc + (int64_t)(n * MM + r + 8) * (HH * DD) + h * DD + col;
            *(uint32_t*)o0 = *(uint32_t*)&p0;
            *(uint32_t*)o1 = *(uint32_t*)&p1;
        }
    }
}

// ================= f_v hidden via mma.sync (K-split 8) =============================
__global__ __launch_bounds__(256)
void fv1_mma_k(const __nv_bfloat16* __restrict__ attcb, const __nv_bfloat16* __restrict__ fvwt,
               float* __restrict__ P)
{
    int ks = blockIdx.z;
    int m0 = blockIdx.y << 7;
    float acc[4][4][4] = {};
    mma_loop(attcb + (int64_t)m0 * (HH * DD) + ks * 128, HH * DD,
             fvwt + ks * 128, HH * DD, 128 / KT, acc);

    int lane = threadIdx.x & 31, wid = threadIdx.x >> 5;
    int wm = wid >> 2, wn = wid & 3;
    float* out = P + (int64_t)ks * NM * DD;
    #pragma unroll
    for (int mf = 0; mf < 4; mf++) {
        #pragma unroll
        for (int nf = 0; nf < 4; nf++) {
            int r   = m0 + wm * 64 + mf * 16 + (lane >> 2);
            int col = wn * 32 + nf * 8 + ((lane & 3) << 1);
            *(float2*)&out[(int64_t)r * DD + col]       = make_float2(acc[mf][nf][0], acc[mf][nf][1]);
            *(float2*)&out[(int64_t)(r + 8) * DD + col] = make_float2(acc[mf][nf][2], acc[mf][nf][3]);
        }
    }
}

// ================= edge kernel: packed f32x2 + abs-trick ===========================
__global__ __launch_bounds__(256)
void edge_k(const float* __restrict__ AB, const float* __restrict__ b1,
            const float* __restrict__ w2, const float* __restrict__ b2,
            float* __restrict__ out)
{
    __shared__ float Ast[DD][68];
    __shared__ float Bst[DD][36];
    __shared__ u64 w2d[DD];
    int n  = blockIdx.z;
    int i0 = blockIdx.y << 5, j0 = blockIdx.x << 5;
    const float* Ab = AB + ((int64_t)n * MM + i0) * DD;
    const float* Bb = AB + (int64_t)NM * DD + ((int64_t)n * MM + j0) * DD;
    int t = threadIdx.x;
    if (t < DD) { float w = w2[t] * 0.5f; w2d[t] = pk2(w, w); }
    #pragma unroll
    for (int c = 0; c < 4; c++) {
        int idx = t + (c << 8);
        int r  = idx >> 5;
        int d4 = (idx & 31) << 2;
        float4 a = *(const float4*)(Ab + r * DD + d4);
        *(u64*)&Ast[d4 + 0][2 * r] = pk2(a.x, a.x);
        *(u64*)&Ast[d4 + 1][2 * r] = pk2(a.y, a.y);
        *(u64*)&Ast[d4 + 2][2 * r] = pk2(a.z, a.z);
        *(u64*)&Ast[d4 + 3][2 * r] = pk2(a.w, a.w);
        float4 bvl = *(const float4*)(Bb + r * DD + d4);
        float4 bb  = *(const float4*)(b1 + d4);
        Bst[d4 + 0][r] = bvl.x + bb.x; Bst[d4 + 1][r] = bvl.y + bb.y;
        Bst[d4 + 2][r] = bvl.z + bb.z; Bst[d4 + 3][r] = bvl.w + bb.w;
    }
    __syncthreads();
    int tx = t & 15, ty = t >> 4;
    const u64 MASK = 0x7FFFFFFF7FFFFFFFull;
    u64 acc0 = 0ull, acc1 = 0ull;
    #pragma unroll 4
    for (int d = 0; d < DD; d++) {
        u64 a0 = *(const u64*)&Ast[d][ty << 2];
        u64 a1 = *(const u64*)&Ast[d][(ty << 2) + 2];
        u64 bp = *(const u64*)&Bst[d][tx << 1];
        u64 wd = w2d[d];
        u64 s0 = add2(a0, bp);
        u64 s1 = add2(a1, bp);
        u64 t0 = s0 & MASK;
        u64 t1 = s1 & MASK;
        fma2(acc0, s0, wd); fma2(acc0, t0, wd);
        fma2(acc1, s1, wd); fma2(acc1, t1, wd);
    }
    float bb = b2[0];
    const float sc = 1.0f / (float)MM;
    int i = i0 + (ty << 1), j = j0 + (tx << 1);
    float2 q0 = up2(acc0), q1 = up2(acc1);
    float* o = out + ((int64_t)n * MM + i) * MM + j;
    *(float2*)o        = make_float2((q0.x + bb) * sc, (q0.y + bb) * sc);
    *(float2*)(o + MM) = make_float2((q1.x + bb) * sc, (q1.y + bb) * sc);
}

// ================= host launcher ===================================================
extern "C" void kernel_launch(void* const* d_in, const int* in_sizes, int n_in,
                              void* d_out, int out_size)
{
    const float* x     = (const float*)d_in[0];
    const float* fn_w1 = (const float*)d_in[1];
    const float* fn_b1 = (const float*)d_in[2];
    const float* fn_w2 = (const float*)d_in[3];
    const float* fn_b2 = (const float*)d_in[4];
    const float* wk    = (const float*)d_in[5];
    const float* bk    = (const float*)d_in[6];
    const float* wq    = (const float*)d_in[7];
    const float* bq    = (const float*)d_in[8];
    const float* wv    = (const float*)d_in[9];
    const float* bv    = (const float*)d_in[10];
    const float* fv_w1 = (const float*)d_in[11];
    const float* fv_b1 = (const float*)d_in[12];
    const float* fv_w2 = (const float*)d_in[13];
    const float* fv_b2 = (const float*)d_in[14];
    const float* fe_w1 = (const float*)d_in[15];
    const float* fe_b1 = (const float*)d_in[16];
    const float* fe_w2 = (const float*)d_in[17];
    const float* fe_b2 = (const float*)d_in[18];

    float* scratch = nullptr;
    cudaGetSymbolAddress((void**)&scratch, g_scratch);
    float* h    = scratch + OFF_H;
    float* S    = scratch + OFF_S;
    float* P    = scratch + OFF_S;
    float* ABuf = scratch + OFF_AB;
    __nv_bfloat16* attcb = (__nv_bfloat16*)(scratch + OFF_ATTC);
    __nv_bfloat16* hb  = (__nv_bfloat16*)(scratch + OFF_HB);
    __nv_bfloat16* wtb = (__nv_bfloat16*)(scratch + OFF_WTB);
    __nv_bfloat16* Kb  = (__nv_bfloat16*)(scratch + OFF_KB);
    __nv_bfloat16* Qb  = (__nv_bfloat16*)(scratch + OFF_QB);
    __nv_bfloat16* Vtb = (__nv_bfloat16*)(scratch + OFF_VTB);
    __nv_bfloat16* alb = (__nv_bfloat16*)(scratch + OFF_ALB);
    __nv_bfloat16* fvwt = (__nv_bfloat16*)(scratch + OFF_FVWT);

    float* x2   = (float*)d_out;
    float* edge = (float*)d_out + NM * DD;

    dim3 gb(128);
    const int MN2 = NM * DD / 2;
    const int NC2 = DD / 2;

    // 1) f_node hidden (scalar, K-split 2) -> partials
    gemm_k<F_TE, 2><<<dim3(2, 16, 2), gb>>>(
        x, fn_w1, nullptr, nullptr, P, DIN, 2 * DD, 2 * DD, 0, 0, 0, 1, 0, 0,
        (int64_t)NM * 2 * DD, nullptr, 1, 0);
    // 2) h (scalar, K-split 8); A-loader reduces f_node1 partials
    float* Ph = P + NM * 2 * DD * 2;
    gemm_k<F_AR, 8><<<dim3(1, 16, 8), gb>>>(
        P, fn_w2, nullptr, nullptr, Ph, 2 * DD, DD, DD, 0, 0, 0, 1, 0, 0,
        (int64_t)NM * DD, fn_b1, 2, (int64_t)NM * 2 * DD);
    fuse_prep_k<<<768, 256>>>((const float2*)Ph, fn_b2, (float2*)h, hb,
                              wk, wq, wv, fv_w1, wtb, fvwt);
    // 3) K/Q/V via mma.sync
    kqv_mma_k<<<dim3(1, 8, 24), 256>>>(hb, wtb, bk, bq, bv, Kb, Qb, Vtb);
    // 4) scores via mma.sync (leaky)
    scores_mma_k<<<dim3(4, 4, 16), 256>>>(Kb, Qb, S);
    // 5) softmax (warp-per-row) -> bf16 alpha
    softmax_k<<<1024, 256>>>(S, alb);
    // 6) attV via mma.sync -> bf16 attc (leaky + concat in epilogue)
    attv_mma_k<<<dim3(1, 8, 16), 256>>>(alb, Vtb, attcb);
    // 7) f_v hidden via mma.sync (K-split 8) -> partials
    fv1_mma_k<<<dim3(1, 8, 8), 256>>>(attcb, fvwt, P);
    // 8) x2 (scalar, K-split 4); A-loader reduces fv1 partials
    float* P8 = P + 8 * NM * DD;
    gemm_k<F_AR, 4><<<dim3(1, 16, 4), gb>>>(
        P, fv_w2, nullptr, nullptr, P8, DD, DD, DD, 0, 0, 0, 1, 0, 0,
        (int64_t)NM * DD, fv_b1, 8, (int64_t)NM * DD);
    reduce_k<F_BIAS | F_ADD, 4><<<256, 256>>>(
        (const float2*)P8, fv_b2, (const float2*)h, (float2*)x2, MN2, NC2);
    // 9) A/B for edges (scalar, K-split 2 + reduce)
    float* P9 = P8 + 4 * NM * DD;
    gemm_k<0, 2><<<dim3(1, 16, 4), gb>>>(
        x2, fe_w1, nullptr, nullptr, P9, DD, DD, DD,
        0, (int64_t)DD * DD, 0, 1, (int64_t)NM * DD, 0, (int64_t)2 * NM * DD,
        nullptr, 1, 0);
    reduce_k<0, 2><<<512, 256>>>(
        (const float2*)P9, nullptr, nullptr, (float2*)ABuf, 2 * MN2, NC2);
    // 10) edge (packed f32x2)
    edge_k<<<dim3(16, 16, NB), 256>>>(ABuf, fe_b1, fe_w2, fe_b2, edge);
}

// round 13
// speedup vs baseline: 3.1469x; 1.0042x over previous
#include <cuda_runtime.h>
#include <cuda_bf16.h>
#include <math.h>
#include <stdint.h>

#define NB 2
#define MM 512
#define DD 128
#define HH 8
#define DIN 64
#define NM (NB*MM)   // 1024

typedef unsigned long long u64;

// ================= packed f32x2 helpers ===========================================
__device__ __forceinline__ u64 pk2(float lo, float hi) {
    u64 r; asm("mov.b64 %0, {%1,%2};" : "=l"(r) : "f"(lo), "f"(hi)); return r;
}
__device__ __forceinline__ void fma2(u64& d, u64 a, u64 b) {
    asm("fma.rn.f32x2 %0, %1, %2, %0;" : "+l"(d) : "l"(a), "l"(b));
}
__device__ __forceinline__ u64 add2(u64 a, u64 b) {
    u64 r; asm("add.rn.f32x2 %0, %1, %2;" : "=l"(r) : "l"(a), "l"(b)); return r;
}
__device__ __forceinline__ float2 up2(u64 v) {
    float lo, hi; asm("mov.b64 {%0,%1}, %2;" : "=f"(lo), "=f"(hi) : "l"(v));
    return make_float2(lo, hi);
}

// ================= mma.sync / cp.async helpers =====================================
__device__ __forceinline__ uint32_t smem_to_u32(const void* p) {
    uint32_t a;
    asm("{ .reg .u64 t; cvta.to.shared.u64 t, %1; cvt.u32.u64 %0, t; }" : "=r"(a) : "l"(p));
    return a;
}
__device__ __forceinline__ void ldsm4(uint32_t& r0, uint32_t& r1, uint32_t& r2,
                                      uint32_t& r3, uint32_t addr) {
    asm volatile("ldmatrix.sync.aligned.m8n8.x4.shared.b16 {%0,%1,%2,%3}, [%4];"
                 : "=r"(r0), "=r"(r1), "=r"(r2), "=r"(r3) : "r"(addr));
}
__device__ __forceinline__ void mma16816(float* d, uint32_t a0, uint32_t a1,
                                         uint32_t a2, uint32_t a3,
                                         uint32_t b0, uint32_t b1) {
    asm volatile("mma.sync.aligned.m16n8k16.row.col.f32.bf16.bf16.f32 "
                 "{%0,%1,%2,%3},{%4,%5,%6,%7},{%8,%9},{%0,%1,%2,%3};"
                 : "+f"(d[0]), "+f"(d[1]), "+f"(d[2]), "+f"(d[3])
                 : "r"(a0), "r"(a1), "r"(a2), "r"(a3), "r"(b0), "r"(b1));
}
__device__ __forceinline__ void cp16(uint32_t s, const void* g) {
    asm volatile("cp.async.cg.shared.global [%0], [%1], 16;" :: "r"(s), "l"(g));
}
#define CP_COMMIT() asm volatile("cp.async.commit_group;" ::: "memory")
#define CP_WAIT0()  asm volatile("cp.async.wait_group 0;" ::: "memory")

#define KT 32
#define SPAD 40

// C[128,128] += A[128,K] @ B[128,K]^T. 256 thr, 8 warps (2x4). cp.async 2-stage.
__device__ __forceinline__ void mma_loop(
    const __nv_bfloat16* __restrict__ A, int lda,
    const __nv_bfloat16* __restrict__ B, int ldb,
    int nkt, float acc[4][4][4])
{
    __shared__ __nv_bfloat16 As[2][128][SPAD];
    __shared__ __nv_bfloat16 Bs[2][128][SPAD];
    int tid = threadIdx.x, lane = tid & 31, wid = tid >> 5;
    int wm = wid >> 2, wn = wid & 3;

    int lrow = tid >> 1, lcol = (tid & 1) << 4;
    const __nv_bfloat16* Ag = A + (int64_t)lrow * lda + lcol;
    const __nv_bfloat16* Bg = B + (int64_t)lrow * ldb + lcol;

    uint32_t asb = smem_to_u32(As), bsb = smem_to_u32(Bs);
    int arow = ((lane >> 3) & 1) * 8 + (lane & 7);
    int acol = ((lane >> 4) & 1) * 8;
    int brow = ((lane >> 4) & 1) * 8 + (lane & 7);
    int bcol = ((lane >> 3) & 1) * 8;

    uint32_t adst = asb + (lrow * SPAD + lcol) * 2;
    uint32_t bdst = bsb + (lrow * SPAD + lcol) * 2;
    const uint32_t BUFB = 128 * SPAD * 2;

    auto issue = [&](int kt, int bf) {
        cp16(adst + bf * BUFB,      Ag + kt * KT);
        cp16(adst + bf * BUFB + 16, Ag + kt * KT + 8);
        cp16(bdst + bf * BUFB,      Bg + kt * KT);
        cp16(bdst + bf * BUFB + 16, Bg + kt * KT + 8);
        CP_COMMIT();
    };

    issue(0, 0);
    int buf = 0;
    for (int kt = 0; kt < nkt; kt++) {
        CP_WAIT0();
        __syncthreads();
        if (kt + 1 < nkt) issue(kt + 1, buf ^ 1);
        #pragma unroll
        for (int kf = 0; kf < 2; kf++) {
            uint32_t a[4][4];
            #pragma unroll
            for (int mf = 0; mf < 4; mf++)
                ldsm4(a[mf][0], a[mf][1], a[mf][2], a[mf][3],
                      asb + buf * BUFB + ((wm * 64 + mf * 16 + arow) * SPAD + kf * 16 + acol) * 2);
            uint32_t b[2][4];
            #pragma unroll
            for (int p = 0; p < 2; p++)
                ldsm4(b[p][0], b[p][1], b[p][2], b[p][3],
                      bsb + buf * BUFB + ((wn * 32 + p * 16 + brow) * SPAD + kf * 16 + bcol) * 2);
            #pragma unroll
            for (int mf = 0; mf < 4; mf++)
                #pragma unroll
                for (int nf = 0; nf < 4; nf++)
                    mma16816(acc[mf][nf], a[mf][0], a[mf][1], a[mf][2], a[mf][3],
                             b[nf >> 1][(nf & 1) * 2], b[nf >> 1][(nf & 1) * 2 + 1]);
        }
        buf ^= 1;
    }
}

// C[64,128] += A[64,K] @ B[128,K]^T. 256 thr, 8 warps (2x4). cp.async 2-stage.
__device__ __forceinline__ void mma_loop64(
    const __nv_bfloat16* __restrict__ A, int lda,
    const __nv_bfloat16* __restrict__ B, int ldb,
    int nkt, float acc[2][4][4])
{
    __shared__ __nv_bfloat16 As[2][64][SPAD];
    __shared__ __nv_bfloat16 Bs[2][128][SPAD];
    int tid = threadIdx.x, lane = tid & 31, wid = tid >> 5;
    int wm = wid >> 2, wn = wid & 3;

    int arow_l = tid >> 2, acol_l = (tid & 3) << 3;
    int lrow = tid >> 1, lcol = (tid & 1) << 4;
    const __nv_bfloat16* Ag = A + (int64_t)arow_l * lda + acol_l;
    const __nv_bfloat16* Bg = B + (int64_t)lrow * ldb + lcol;

    uint32_t asb = smem_to_u32(As), bsb = smem_to_u32(Bs);
    int arow = ((lane >> 3) & 1) * 8 + (lane & 7);
    int acol = ((lane >> 4) & 1) * 8;
    int brow = ((lane >> 4) & 1) * 8 + (lane & 7);
    int bcol = ((lane >> 3) & 1) * 8;

    uint32_t adst = asb + (arow_l * SPAD + acol_l) * 2;
    uint32_t bdst = bsb + (lrow * SPAD + lcol) * 2;
    const uint32_t ABUF = 64 * SPAD * 2;
    const uint32_t BBUF = 128 * SPAD * 2;

    auto issue = [&](int kt, int bf) {
        cp16(adst + bf * ABUF,      Ag + kt * KT);
        cp16(bdst + bf * BBUF,      Bg + kt * KT);
        cp16(bdst + bf * BBUF + 16, Bg + kt * KT + 8);
        CP_COMMIT();
    };

    issue(0, 0);
    int buf = 0;
    for (int kt = 0; kt < nkt; kt++) {
        CP_WAIT0();
        __syncthreads();
        if (kt + 1 < nkt) issue(kt + 1, buf ^ 1);
        #pragma unroll
        for (int kf = 0; kf < 2; kf++) {
            uint32_t a[2][4];
            #pragma unroll
            for (int mf = 0; mf < 2; mf++)
                ldsm4(a[mf][0], a[mf][1], a[mf][2], a[mf][3],
                      asb + buf * ABUF + ((wm * 32 + mf * 16 + arow) * SPAD + kf * 16 + acol) * 2);
            uint32_t b[2][4];
            #pragma unroll
            for (int p = 0; p < 2; p++)
                ldsm4(b[p][0], b[p][1], b[p][2], b[p][3],
                      bsb + buf * BBUF + ((wn * 32 + p * 16 + brow) * SPAD + kf * 16 + bcol) * 2);
            #pragma unroll
            for (int mf = 0; mf < 2; mf++)
                #pragma unroll
                for (int nf = 0; nf < 4; nf++)
                    mma16816(acc[mf][nf], a[mf][0], a[mf][1], a[mf][2], a[mf][3],
                             b[nf >> 1][(nf & 1) * 2], b[nf >> 1][(nf & 1) * 2 + 1]);
        }
        buf ^= 1;
    }
}

// ================= scratch =========================================================
#define OFF_TMP   0
#define OFF_H     (OFF_TMP + NM*2*DD)
#define OFF_S     (OFF_H   + NM*DD)              // K-split partials region
#define OFF_ATTC  (OFF_S   + HH*NB*MM*MM)
#define OFF_T2    (OFF_ATTC+ HH*NM*DD)
#define OFF_AB    (OFF_T2  + NM*DD)
#define OFF_HB    (OFF_AB  + 2*NM*DD)
#define OFF_WTB   (OFF_HB  + NM*DD/2)
#define OFF_KB    (OFF_WTB + 3*HH*DD*DD/2)
#define OFF_QB    (OFF_KB  + HH*NM*DD/2)
#define OFF_VTB   (OFF_QB  + HH*NM*DD/2)
#define OFF_ALB   (OFF_VTB + HH*NM*DD/2)
#define OFF_FVWT  (OFF_ALB + HH*NB*MM*MM/2)
#define SCRATCH_TOTAL (OFF_FVWT + NM*DD/8)

__device__ float g_scratch[SCRATCH_TOTAL];

#define F_TRANSB 1
#define F_RELU   2
#define F_LEAKY  4
#define F_TE     8
#define F_BIAS   16
#define F_ADD    32
#define F_AR     64

// ================= scalar FFMA2 GEMM ===============================================
template<int F>
__device__ __forceinline__ void gemm_body(
    const float* __restrict__ A, const float* __restrict__ B,
    const float* __restrict__ bias, const float* __restrict__ addsrc,
    float* __restrict__ C, int Kd, int Nc, int ldc, int ktb, int kte,
    const float* __restrict__ abias, int nra, int64_t strideAR)
{
    __shared__ float As[2][16][128];
    __shared__ float Bs[2][16][128];
    int tid = threadIdx.x;
    int tx = tid & 15, ty = tid >> 4;
    int m0 = blockIdx.y << 6, n0 = blockIdx.x << 7;

    int ar = tid >> 1, ac = (tid & 1) << 3;
    const float* Ap = A + (int64_t)(m0 + ar) * Kd + ac;
    int bk = tid >> 3, bc = (tid & 7) << 4;
    const float* Bp = (F & F_TRANSB)
        ? B + (int64_t)(n0 + tid) * Kd
        : B + (int64_t)bk * Nc + n0 + bc;

    u64 acc[8][4];
    #pragma unroll
    for (int i = 0; i < 8; i++)
        #pragma unroll
        for (int p = 0; p < 4; p++) acc[i][p] = 0ull;

    float4 la0, la1, lb[4];
    auto loadG = [&](int kt) {
        la0 = *(const float4*)(Ap + kt * 16);
        la1 = *(const float4*)(Ap + kt * 16 + 4);
        if (F & F_AR) {
            for (int r = 1; r < nra; r++) {
                float4 u0 = *(const float4*)(Ap + r * strideAR + kt * 16);
                float4 u1 = *(const float4*)(Ap + r * strideAR + kt * 16 + 4);
                la0.x += u0.x; la0.y += u0.y; la0.z += u0.z; la0.w += u0.w;
                la1.x += u1.x; la1.y += u1.y; la1.z += u1.z; la1.w += u1.w;
            }
            float4 b0 = *(const float4*)(abias + kt * 16 + ac);
            float4 b1 = *(const float4*)(abias + kt * 16 + ac + 4);
            la0.x = fmaxf(la0.x + b0.x, 0.f); la0.y = fmaxf(la0.y + b0.y, 0.f);
            la0.z = fmaxf(la0.z + b0.z, 0.f); la0.w = fmaxf(la0.w + b0.w, 0.f);
            la1.x = fmaxf(la1.x + b1.x, 0.f); la1.y = fmaxf(la1.y + b1.y, 0.f);
            la1.z = fmaxf(la1.z + b1.z, 0.f); la1.w = fmaxf(la1.w + b1.w, 0.f);
        }
        if (F & F_TE) {
            int kb = kt * 16 + ac;
            la0.x += sinf((float)(kb + 0) * (5.0f / 63.0f));
            la0.y += sinf((float)(kb + 1) * (5.0f / 63.0f));
            la0.z += sinf((float)(kb + 2) * (5.0f / 63.0f));
            la0.w += sinf((float)(kb + 3) * (5.0f / 63.0f));
            la1.x += sinf((float)(kb + 4) * (5.0f / 63.0f));
            la1.y += sinf((float)(kb + 5) * (5.0f / 63.0f));
            la1.z += sinf((float)(kb + 6) * (5.0f / 63.0f));
            la1.w += sinf((float)(kb + 7) * (5.0f / 63.0f));
        }
        if (F & F_TRANSB) {
            #pragma unroll
            for (int u = 0; u < 4; u++) lb[u] = *(const float4*)(Bp + kt * 16 + 4 * u);
        } else {
            #pragma unroll
            for (int u = 0; u < 4; u++) lb[u] = *(const float4*)(Bp + (int64_t)(kt * 16) * Nc + 4 * u);
        }
    };
    auto storeS = [&](int bf) {
        *(u64*)&As[bf][ac + 0][2 * ar] = pk2(la0.x, la0.x);
        *(u64*)&As[bf][ac + 1][2 * ar] = pk2(la0.y, la0.y);
        *(u64*)&As[bf][ac + 2][2 * ar] = pk2(la0.z, la0.z);
        *(u64*)&As[bf][ac + 3][2 * ar] = pk2(la0.w, la0.w);
        *(u64*)&As[bf][ac + 4][2 * ar] = pk2(la1.x, la1.x);
        *(u64*)&As[bf][ac + 5][2 * ar] = pk2(la1.y, la1.y);
        *(u64*)&As[bf][ac + 6][2 * ar] = pk2(la1.z, la1.z);
        *(u64*)&As[bf][ac + 7][2 * ar] = pk2(la1.w, la1.w);
        if (F & F_TRANSB) {
            #pragma unroll
            for (int u = 0; u < 4; u++) {
                Bs[bf][4 * u + 0][tid] = lb[u].x; Bs[bf][4 * u + 1][tid] = lb[u].y;
                Bs[bf][4 * u + 2][tid] = lb[u].z; Bs[bf][4 * u + 3][tid] = lb[u].w;
            }
        } else {
            #pragma unroll
            for (int u = 0; u < 4; u++) *(float4*)&Bs[bf][bk][bc + 4 * u] = lb[u];
        }
    };

    loadG(ktb); storeS(0); __syncthreads();
    int buf = 0;
    for (int kt = ktb; kt < kte; kt++) {
        bool more = (kt + 1 < kte);
        if (more) loadG(kt + 1);
        #pragma unroll
        for (int kk = 0; kk < 16; kk++) {
            ulonglong2 aL0 = *(const ulonglong2*)&As[buf][kk][(ty << 3)];
            ulonglong2 aL1 = *(const ulonglong2*)&As[buf][kk][(ty << 3) + 4];
            ulonglong2 aH0 = *(const ulonglong2*)&As[buf][kk][64 + (ty << 3)];
            ulonglong2 aH1 = *(const ulonglong2*)&As[buf][kk][64 + (ty << 3) + 4];
            ulonglong2 b0  = *(const ulonglong2*)&Bs[buf][kk][(tx << 2)];
            ulonglong2 b1  = *(const ulonglong2*)&Bs[buf][kk][64 + (tx << 2)];
            u64 ad[8] = {aL0.x, aL0.y, aL1.x, aL1.y, aH0.x, aH0.y, aH1.x, aH1.y};
            u64 bd[4] = {b0.x, b0.y, b1.x, b1.y};
            #pragma unroll
            for (int i = 0; i < 8; i++) {
                fma2(acc[i][0], ad[i], bd[0]);
                fma2(acc[i][1], ad[i], bd[1]);
                fma2(acc[i][2], ad[i], bd[2]);
                fma2(acc[i][3], ad[i], bd[3]);
            }
        }
        if (more) { storeS(buf ^ 1); __syncthreads(); buf ^= 1; }
    }

    #pragma unroll
    for (int i = 0; i < 8; i++) {
        int row = m0 + ((i < 4) ? ((ty << 2) + i) : (32 + (ty << 2) + i - 4));
        float2 q0 = up2(acc[i][0]), q1 = up2(acc[i][1]);
        float2 q2 = up2(acc[i][2]), q3 = up2(acc[i][3]);
        float o[8] = {q0.x, q0.y, q1.x, q1.y, q2.x, q2.y, q3.x, q3.y};
        #pragma unroll
        for (int j = 0; j < 8; j++) {
            int col = n0 + ((j < 4) ? ((tx << 2) + j) : (64 + (tx << 2) + j - 4));
            float v = o[j];
            if (F & F_BIAS)  v += bias[col];
            if (F & F_RELU)  v = fmaxf(v, 0.0f);
            if (F & F_LEAKY) v = (v >= 0.0f) ? v : 0.2f * v;
            if (F & F_ADD)   v += addsrc[(int64_t)row * ldc + col];
            o[j] = v;
        }
        *(float4*)&C[(int64_t)row * ldc + n0 + (tx << 2)]      = make_float4(o[0], o[1], o[2], o[3]);
        *(float4*)&C[(int64_t)row * ldc + n0 + 64 + (tx << 2)] = make_float4(o[4], o[5], o[6], o[7]);
    }
}

template<int F, int NKS>
__global__ __launch_bounds__(128, 4)
void gemm_k(const float* __restrict__ A, const float* __restrict__ B,
            const float* __restrict__ bias, const float* __restrict__ addsrc,
            float* __restrict__ C, int Kd, int Nc, int ldc,
            int64_t sA, int64_t sB, int64_t sBias,
            int zdiv, int64_t sC1, int64_t sC2, int64_t sPart,
            const float* abias, int nra, int64_t strideAR)
{
    int zz = blockIdx.z;
    int z = zz / NKS, ks = zz % NKS;
    int ktn = Kd >> 4;
    int ktb = ks * (ktn / NKS), kte = ktb + ktn / NKS;
    const float* bz = (F & F_BIAS) ? bias + sBias * z : nullptr;
    float* Cz = C + (int64_t)(z / zdiv) * sC1 + (int64_t)(z % zdiv) * sC2
                  + (int64_t)ks * sPart;
    gemm_body<F>(A + sA * z, B + sB * z, bz, addsrc, Cz, Kd, Nc, ldc, ktb, kte,
                 abias, nra, strideAR);
}

// ================= float2-granularity K-split reduce ===============================
template<int F, int NKS>
__global__ __launch_bounds__(256)
void reduce_k(const float2* __restrict__ P, const float* __restrict__ bias,
              const float2* __restrict__ addsrc, float2* __restrict__ C,
              int totalf2, int ncf2)
{
    int idx = blockIdx.x * 256 + threadIdx.x;
    if (idx >= totalf2) return;
    float2 s = P[idx];
    #pragma unroll
    for (int k = 1; k < NKS; k++) {
        float2 t = P[idx + (int64_t)k * totalf2];
        s.x += t.x; s.y += t.y;
    }
    if (F & F_BIAS) {
        float2 b = ((const float2*)bias)[idx % ncf2];
        s.x += b.x; s.y += b.y;
    }
    if (F & F_RELU) { s.x = fmaxf(s.x, 0.f); s.y = fmaxf(s.y, 0.f); }
    if (F & F_ADD)  { float2 a = addsrc[idx]; s.x += a.x; s.y += a.y; }
    C[idx] = s;
}

// ================= fused prep ======================================================
__global__ __launch_bounds__(256)
void fuse_prep_k(const float2* __restrict__ Ph, const float* __restrict__ fn_b2,
                 float2* __restrict__ h, __nv_bfloat16* __restrict__ hb,
                 const float* __restrict__ wk, const float* __restrict__ wq,
                 const float* __restrict__ wv, const float* __restrict__ fv_w1,
                 __nv_bfloat16* __restrict__ wtb, __nv_bfloat16* __restrict__ fvwt)
{
    int b = blockIdx.x, t = threadIdx.x;
    if (b < 256) {
        int idx = b * 256 + t;
        float2 s = Ph[idx];
        #pragma unroll
        for (int k = 1; k < 8; k++) {
            float2 v = Ph[idx + k * (NM * DD / 2)];
            s.x += v.x; s.y += v.y;
        }
        float2 bb = ((const float2*)fn_b2)[idx & 63];
        s.x += bb.x; s.y += bb.y;
        h[idx] = s;
        __nv_bfloat162 p = __floats2bfloat162_rn(s.x, s.y);
        *(uint32_t*)&hb[idx * 2] = *(uint32_t*)&p;
        return;
    }
    __shared__ float ts[32][33];
    int c = t & 31, r0 = t >> 5;
    if (b < 640) {
        int q = b - 256;
        int mi = q >> 4, ti = q & 15;
        int kb = ti >> 2, nb = ti & 3;
        int w = mi / 8, hd = mi & 7;
        const float* src = ((w == 0) ? wk : (w == 1) ? wq : wv) + hd * 16384;
        #pragma unroll
        for (int i = 0; i < 4; i++) {
            int r = r0 + 8 * i;
            ts[r][c] = src[(kb * 32 + r) * 128 + nb * 32 + c];
        }
        __syncthreads();
        int ck = (t & 15) << 1, rn0 = t >> 4;
        __nv_bfloat16* dst = wtb + (int64_t)mi * 16384;
        #pragma unroll
        for (int i = 0; i < 2; i++) {
            int rn = rn0 + 16 * i;
            __nv_bfloat162 p = __floats2bfloat162_rn(ts[ck][rn], ts[ck + 1][rn]);
            *(uint32_t*)&dst[(nb * 32 + rn) * 128 + kb * 32 + ck] = *(uint32_t*)&p;
        }
    } else {
        int q = b - 640;
        int kb = q >> 2, nb = q & 3;
        #pragma unroll
        for (int i = 0; i < 4; i++) {
            int r = r0 + 8 * i;
            ts[r][c] = fv_w1[(kb * 32 + r) * 128 + nb * 32 + c];
        }
        __syncthreads();
        int ck = (t & 15) << 1, rn0 = t >> 4;
        #pragma unroll
        for (int i = 0; i < 2; i++) {
            int rn = rn0 + 16 * i;
            __nv_bfloat162 p = __floats2bfloat162_rn(ts[ck][rn], ts[ck + 1][rn]);
            *(uint32_t*)&fvwt[(int64_t)(nb * 32 + rn) * 1024 + kb * 32 + ck] = *(uint32_t*)&p;
        }
    }
}

// ================= KQV via mma.sync (coalesced V^T epilogue) =======================
__global__ __launch_bounds__(256)
void kqv_mma_k(const __nv_bfloat16* __restrict__ hb, const __nv_bfloat16* __restrict__ wtb,
               const float* __restrict__ bk, const float* __restrict__ bq,
               const float* __restrict__ bv,
               __nv_bfloat16* __restrict__ Kb, __nv_bfloat16* __restrict__ Qb,
               __nv_bfloat16* __restrict__ Vtb)
{
    __shared__ __nv_bfloat16 Vs[128][136];
    int z = blockIdx.z, which = z >> 3, head = z & 7;
    int m0 = blockIdx.y << 7;
    float acc[4][4][4] = {};
    mma_loop(hb + (int64_t)m0 * DD, DD,
             wtb + (int64_t)z * DD * DD, DD, DD / KT, acc);

    int tid = threadIdx.x;
    int lane = tid & 31, wid = tid >> 5;
    int wm = wid >> 2, wn = wid & 3;
    const float* bias = ((which == 0) ? bk : (which == 1) ? bq : bv) + head * DD;

    if (which < 2) {
        __nv_bfloat16* out = ((which == 0) ? Kb : Qb) + (int64_t)head * NM * DD;
        #pragma unroll
        for (int mf = 0; mf < 4; mf++) {
            #pragma unroll
            for (int nf = 0; nf < 4; nf++) {
                int r   = wm * 64 + mf * 16 + (lane >> 2);
                int col = wn * 32 + nf * 8 + ((lane & 3) << 1);
                float b0 = bias[col], b1 = bias[col + 1];
                __nv_bfloat162 p0 = __floats2bfloat162_rn(acc[mf][nf][0] + b0, acc[mf][nf][1] + b1);
                __nv_bfloat162 p1 = __floats2bfloat162_rn(acc[mf][nf][2] + b0, acc[mf][nf][3] + b1);
                *(uint32_t*)&out[(int64_t)(m0 + r) * DD + col]     = *(uint32_t*)&p0;
                *(uint32_t*)&out[(int64_t)(m0 + r + 8) * DD + col] = *(uint32_t*)&p1;
            }
        }
    } else {
        __syncthreads();
        #pragma unroll
        for (int mf = 0; mf < 4; mf++) {
            #pragma unroll
            for (int nf = 0; nf < 4; nf++) {
                int r   = wm * 64 + mf * 16 + (lane >> 2);
                int col = wn * 32 + nf * 8 + ((lane & 3) << 1);
                float b0 = bias[col], b1 = bias[col + 1];
                Vs[col][r]         = __float2bfloat16(acc[mf][nf][0] + b0);
                Vs[col + 1][r]     = __float2bfloat16(acc[mf][nf][1] + b1);
                Vs[col][r + 8]     = __float2bfloat16(acc[mf][nf][2] + b0);
                Vs[col + 1][r + 8] = __float2bfloat16(acc[mf][nf][3] + b1);
            }
        }
        __syncthreads();
        int d = tid >> 1, half = tid & 1;
        int n = m0 >> 9;
        __nv_bfloat16* vt = Vtb + ((int64_t)(head * 2 + n) * DD + d) * MM
                            + (m0 & 511) + half * 64;
        #pragma unroll
        for (int q = 0; q < 8; q++)
            *(uint4*)(vt + 8 * q) = *(const uint4*)&Vs[d][half * 64 + 8 * q];
    }
}

// ================= fused scores+softmax: alpha = softmax(leaky(K @ Q^T)) ===========
// block: 64 K-rows x all 512 Q-cols; 8 warps, warp w owns cols [w*64, w*64+64).
// dynamic smem: A tile [2][64][SPAD], B tile [2][512][SPAD].
#define SS_SMEM (2*64*SPAD*2 + 2*512*SPAD*2)   // 92160 bytes
__global__ __launch_bounds__(256)
void scores_soft_k(const __nv_bfloat16* __restrict__ Kb,
                   const __nv_bfloat16* __restrict__ Qb,
                   __nv_bfloat16* __restrict__ ab)
{
    extern __shared__ char dsm[];
    int tid = threadIdx.x, lane = tid & 31, wid = tid >> 5;
    int z = blockIdx.z, h = z >> 1, n = z & 1;
    int m0 = blockIdx.y << 6;

    const __nv_bfloat16* Ag = Kb + ((int64_t)h * NM + n * MM + m0) * DD;
    const __nv_bfloat16* Bg = Qb + ((int64_t)h * NM + n * MM) * DD;

    uint32_t asb = smem_to_u32(dsm);
    uint32_t bsb = asb + 2 * 64 * SPAD * 2;
    const uint32_t ABUF = 64 * SPAD * 2;
    const uint32_t BBUF = 512 * SPAD * 2;

    int arow = ((lane >> 3) & 1) * 8 + (lane & 7);
    int acol = ((lane >> 4) & 1) * 8;
    int brow = ((lane >> 4) & 1) * 8 + (lane & 7);
    int bcol = ((lane >> 3) & 1) * 8;

    // loaders: A 64x32 (256 cp16), B 512x32 (2048 cp16)
    int ar_l = tid >> 2, ach = (tid & 3) << 3;
    auto issue = [&](int kt, int bf) {
        cp16(asb + bf * ABUF + (ar_l * SPAD + ach) * 2, Ag + (int64_t)ar_l * DD + kt * KT + ach);
        #pragma unroll
        for (int i = 0; i < 8; i++) {
            int id = tid + 256 * i;
            int br_l = id >> 2, bch = (id & 3) << 3;
            cp16(bsb + bf * BBUF + (br_l * SPAD + bch) * 2, Bg + (int64_t)br_l * DD + kt * KT + bch);
        }
        CP_COMMIT();
    };

    float acc[4][8][4];
    #pragma unroll
    for (int mf = 0; mf < 4; mf++)
        #pragma unroll
        for (int nf = 0; nf < 8; nf++)
            #pragma unroll
            for (int i = 0; i < 4; i++) acc[mf][nf][i] = 0.f;

    issue(0, 0);
    int buf = 0;
    for (int kt = 0; kt < 4; kt++) {
        CP_WAIT0();
        __syncthreads();
        if (kt + 1 < 4) issue(kt + 1, buf ^ 1);
        #pragma unroll
        for (int kf = 0; kf < 2; kf++) {
            uint32_t a[4][4];
            #pragma unroll
            for (int mf = 0; mf < 4; mf++)
                ldsm4(a[mf][0], a[mf][1], a[mf][2], a[mf][3],
                      asb + buf * ABUF + ((mf * 16 + arow) * SPAD + kf * 16 + acol) * 2);
            uint32_t b[4][4];
            #pragma unroll
            for (int p = 0; p < 4; p++)
                ldsm4(b[p][0], b[p][1], b[p][2], b[p][3],
                      bsb + buf * BBUF + ((wid * 64 + p * 16 + brow) * SPAD + kf * 16 + bcol) * 2);
            #pragma unroll
            for (int mf = 0; mf < 4; mf++)
                #pragma unroll
                for (int p = 0; p < 4; p++) {
                    mma16816(acc[mf][p * 2],     a[mf][0], a[mf][1], a[mf][2], a[mf][3],
                             b[p][0], b[p][1]);
                    mma16816(acc[mf][p * 2 + 1], a[mf][0], a[mf][1], a[mf][2], a[mf][3],
                             b[p][2], b[p][3]);
                }
        }
        buf ^= 1;
    }
    __syncthreads();   // smem now free for reductions

    float* pmax = (float*)dsm;         // [64][8]
    float* psum = pmax + 512;          // [64][8]
    int r4 = lane >> 2, q = lane & 3;

    // leaky + warp-local row max
    float mx[4][2];
    #pragma unroll
    for (int mf = 0; mf < 4; mf++) {
        float m0v = -1e30f, m1v = -1e30f;
        #pragma unroll
        for (int nf = 0; nf < 8; nf++) {
            #pragma unroll
            for (int i = 0; i < 4; i++) {
                float v = acc[mf][nf][i];
                v = (v >= 0.f) ? v : 0.2f * v;
                acc[mf][nf][i] = v;
            }
            m0v = fmaxf(m0v, fmaxf(acc[mf][nf][0], acc[mf][nf][1]));
            m1v = fmaxf(m1v, fmaxf(acc[mf][nf][2], acc[mf][nf][3]));
        }
        m0v = fmaxf(m0v, __shfl_xor_sync(0xffffffffu, m0v, 1));
        m0v = fmaxf(m0v, __shfl_xor_sync(0xffffffffu, m0v, 2));
        m1v = fmaxf(m1v, __shfl_xor_sync(0xffffffffu, m1v, 1));
        m1v = fmaxf(m1v, __shfl_xor_sync(0xffffffffu, m1v, 2));
        mx[mf][0] = m0v; mx[mf][1] = m1v;
        if (q == 0) {
            pmax[(mf * 16 + r4) * 8 + wid]     = m0v;
            pmax[(mf * 16 + 8 + r4) * 8 + wid] = m1v;
        }
    }
    __syncthreads();
    float gmx[4][2];
    #pragma unroll
    for (int mf = 0; mf < 4; mf++) {
        float g0 = pmax[(mf * 16 + r4) * 8];
        float g1 = pmax[(mf * 16 + 8 + r4) * 8];
        #pragma unroll
        for (int w = 1; w < 8; w++) {
            g0 = fmaxf(g0, pmax[(mf * 16 + r4) * 8 + w]);
            g1 = fmaxf(g1, pmax[(mf * 16 + 8 + r4) * 8 + w]);
        }
        gmx[mf][0] = g0; gmx[mf][1] = g1;
    }
    // exp + warp-local row sum
    #pragma unroll
    for (int mf = 0; mf < 4; mf++) {
        float s0 = 0.f, s1 = 0.f;
        #pragma unroll
        for (int nf = 0; nf < 8; nf++) {
            float e0 = __expf(acc[mf][nf][0] - gmx[mf][0]);
            float e1 = __expf(acc[mf][nf][1] - gmx[mf][0]);
            float e2 = __expf(acc[mf][nf][2] - gmx[mf][1]);
            float e3 = __expf(acc[mf][nf][3] - gmx[mf][1]);
            acc[mf][nf][0] = e0; acc[mf][nf][1] = e1;
            acc[mf][nf][2] = e2; acc[mf][nf][3] = e3;
            s0 += e0 + e1; s1 += e2 + e3;
        }
        s0 += __shfl_xor_sync(0xffffffffu, s0, 1);
        s0 += __shfl_xor_sync(0xffffffffu, s0, 2);
        s1 += __shfl_xor_sync(0xffffffffu, s1, 1);
        s1 += __shfl_xor_sync(0xffffffffu, s1, 2);
        if (q == 0) {
            psum[(mf * 16 + r4) * 8 + wid]     = s0;
            psum[(mf * 16 + 8 + r4) * 8 + wid] = s1;
        }
    }
    __syncthreads();
    __nv_bfloat16* out = ab + (int64_t)z * MM * MM;
    #pragma unroll
    for (int mf = 0; mf < 4; mf++) {
        float g0 = 0.f, g1 = 0.f;
        #pragma unroll
        for (int w = 0; w < 8; w++) {
            g0 += psum[(mf * 16 + r4) * 8 + w];
            g1 += psum[(mf * 16 + 8 + r4) * 8 + w];
        }
        float inv0 = 1.0f / g0, inv1 = 1.0f / g1;
        int row0 = m0 + mf * 16 + r4, row1 = row0 + 8;
        #pragma unroll
        for (int nf = 0; nf < 8; nf++) {
            int col = wid * 64 + nf * 8 + (q << 1);
            __nv_bfloat162 p0 = __floats2bfloat162_rn(acc[mf][nf][0] * inv0, acc[mf][nf][1] * inv0);
            __nv_bfloat162 p1 = __floats2bfloat162_rn(acc[mf][nf][2] * inv1, acc[mf][nf][3] * inv1);
            *(uint32_t*)&out[(int64_t)row0 * MM + col] = *(uint32_t*)&p0;
            *(uint32_t*)&out[(int64_t)row1 * MM + col] = *(uint32_t*)&p1;
        }
    }
}

// ================= attV via mma.sync, M-tile 64, fused epilogue ====================
__global__ __launch_bounds__(256)
void attv_mma_k(const __nv_bfloat16* __restrict__ ab, const __nv_bfloat16* __restrict__ Vtb,
                __nv_bfloat16* __restrict__ attc)
{
    int z = blockIdx.z, h = z >> 1, n = z & 1;
    int m0 = blockIdx.y << 6;
    float acc[2][4][4] = {};
    mma_loop64(ab  + (int64_t)z * MM * MM + (int64_t)m0 * MM, MM,
               Vtb + (int64_t)z * DD * MM, MM, MM / KT, acc);

    int lane = threadIdx.x & 31, wid = threadIdx.x >> 5;
    int wm = wid >> 2, wn = wid & 3;
    #pragma unroll
    for (int mf = 0; mf < 2; mf++) {
        #pragma unroll
        for (int nf = 0; nf < 4; nf++) {
            int r   = m0 + wm * 32 + mf * 16 + (lane >> 2);
            int col = wn * 32 + nf * 8 + ((lane & 3) << 1);
            float v0 = acc[mf][nf][0]; v0 = (v0 >= 0.f) ? v0 : 0.2f * v0;
            float v1 = acc[mf][nf][1]; v1 = (v1 >= 0.f) ? v1 : 0.2f * v1;
            float v2 = acc[mf][nf][2]; v2 = (v2 >= 0.f) ? v2 : 0.2f * v2;
            float v3 = acc[mf][nf][3]; v3 = (v3 >= 0.f) ? v3 : 0.2f * v3;
            __nv_bfloat162 p0 = __floats2bfloat162_rn(v0, v1);
            __nv_bfloat162 p1 = __floats2bfloat162_rn(v2, v3);
            __nv_bfloat16* o0 = attc + (int64_t)(n * MM + r) * (HH * DD) + h * DD + col;
            __nv_bfloat16* o1 = attc + (int64_t)(n * MM + r + 8) * (HH * DD) + h * DD + col;
            *(uint32_t*)o0 = *(uint32_t*)&p0;
            *(uint32_t*)o1 = *(uint32_t*)&p1;
        }
    }
}

// ================= f_v hidden via mma.sync (K-split 8) =============================
__global__ __launch_bounds__(256)
void fv1_mma_k(const __nv_bfloat16* __restrict__ attcb, const __nv_bfloat16* __restrict__ fvwt,
               float* __restrict__ P)
{
    int ks = blockIdx.z;
    int m0 = blockIdx.y << 7;
    float acc[4][4][4] = {};
    mma_loop(attcb + (int64_t)m0 * (HH * DD) + ks * 128, HH * DD,
             fvwt + ks * 128, HH * DD, 128 / KT, acc);

    int lane = threadIdx.x & 31, wid = threadIdx.x >> 5;
    int wm = wid >> 2, wn = wid & 3;
    float* out = P + (int64_t)ks * NM * DD;
    #pragma unroll
    for (int mf = 0; mf < 4; mf++) {
        #pragma unroll
        for (int nf = 0; nf < 4; nf++) {
            int r   = m0 + wm * 64 + mf * 16 + (lane >> 2);
            int col = wn * 32 + nf * 8 + ((lane & 3) << 1);
            *(float2*)&out[(int64_t)r * DD + col]       = make_float2(acc[mf][nf][0], acc[mf][nf][1]);
            *(float2*)&out[(int64_t)(r + 8) * DD + col] = make_float2(acc[mf][nf][2], acc[mf][nf][3]);
        }
    }
}

// ================= edge kernel: packed f32x2 + abs-trick ===========================
__global__ __launch_bounds__(256)
void edge_k(const float* __restrict__ AB, const float* __restrict__ b1,
            const float* __restrict__ w2, const float* __restrict__ b2,
            float* __restrict__ out)
{
    __shared__ float Ast[DD][68];
    __shared__ float Bst[DD][36];
    __shared__ u64 w2d[DD];
    int n  = blockIdx.z;
    int i0 = blockIdx.y << 5, j0 = blockIdx.x << 5;
    const float* Ab = AB + ((int64_t)n * MM + i0) * DD;
    const float* Bb = AB + (int64_t)NM * DD + ((int64_t)n * MM + j0) * DD;
    int t = threadIdx.x;
    if (t < DD) { float w = w2[t] * 0.5f; w2d[t] = pk2(w, w); }
    #pragma unroll
    for (int c = 0; c < 4; c++) {
        int idx = t + (c << 8);
        int r  = idx >> 5;
        int d4 = (idx & 31) << 2;
        float4 a = *(const float4*)(Ab + r * DD + d4);
        *(u64*)&Ast[d4 + 0][2 * r] = pk2(a.x, a.x);
        *(u64*)&Ast[d4 + 1][2 * r] = pk2(a.y, a.y);
        *(u64*)&Ast[d4 + 2][2 * r] = pk2(a.z, a.z);
        *(u64*)&Ast[d4 + 3][2 * r] = pk2(a.w, a.w);
        float4 bvl = *(const float4*)(Bb + r * DD + d4);
        float4 bb  = *(const float4*)(b1 + d4);
        Bst[d4 + 0][r] = bvl.x + bb.x; Bst[d4 + 1][r] = bvl.y + bb.y;
        Bst[d4 + 2][r] = bvl.z + bb.z; Bst[d4 + 3][r] = bvl.w + bb.w;
    }
    __syncthreads();
    int tx = t & 15, ty = t >> 4;
    const u64 MASK = 0x7FFFFFFF7FFFFFFFull;
    u64 acc0 = 0ull, acc1 = 0ull;
    #pragma unroll 4
    for (int d = 0; d < DD; d++) {
        u64 a0 = *(const u64*)&Ast[d][ty << 2];
        u64 a1 = *(const u64*)&Ast[d][(ty << 2) + 2];
        u64 bp = *(const u64*)&Bst[d][tx << 1];
        u64 wd = w2d[d];
        u64 s0 = add2(a0, bp);
        u64 s1 = add2(a1, bp);
        u64 t0 = s0 & MASK;
        u64 t1 = s1 & MASK;
        fma2(acc0, s0, wd); fma2(acc0, t0, wd);
        fma2(acc1, s1, wd); fma2(acc1, t1, wd);
    }
    float bb = b2[0];
    const float sc = 1.0f / (float)MM;
    int i = i0 + (ty << 1), j = j0 + (tx << 1);
    float2 q0 = up2(acc0), q1 = up2(acc1);
    float* o = out + ((int64_t)n * MM + i) * MM + j;
    *(float2*)o        = make_float2((q0.x + bb) * sc, (q0.y + bb) * sc);
    *(float2*)(o + MM) = make_float2((q1.x + bb) * sc, (q1.y + bb) * sc);
}

// ================= host launcher ===================================================
extern "C" void kernel_launch(void* const* d_in, const int* in_sizes, int n_in,
                              void* d_out, int out_size)
{
    const float* x     = (const float*)d_in[0];
    const float* fn_w1 = (const float*)d_in[1];
    const float* fn_b1 = (const float*)d_in[2];
    const float* fn_w2 = (const float*)d_in[3];
    const float* fn_b2 = (const float*)d_in[4];
    const float* wk    = (const float*)d_in[5];
    const float* bk    = (const float*)d_in[6];
    const float* wq    = (const float*)d_in[7];
    const float* bq    = (const float*)d_in[8];
    const float* wv    = (const float*)d_in[9];
    const float* bv    = (const float*)d_in[10];
    const float* fv_w1 = (const float*)d_in[11];
    const float* fv_b1 = (const float*)d_in[12];
    const float* fv_w2 = (const float*)d_in[13];
    const float* fv_b2 = (const float*)d_in[14];
    const float* fe_w1 = (const float*)d_in[15];
    const float* fe_b1 = (const float*)d_in[16];
    const float* fe_w2 = (const float*)d_in[17];
    const float* fe_b2 = (const float*)d_in[18];

    float* scratch = nullptr;
    cudaGetSymbolAddress((void**)&scratch, g_scratch);
    float* h    = scratch + OFF_H;
    float* P    = scratch + OFF_S;
    float* ABuf = scratch + OFF_AB;
    __nv_bfloat16* attcb = (__nv_bfloat16*)(scratch + OFF_ATTC);
    __nv_bfloat16* hb  = (__nv_bfloat16*)(scratch + OFF_HB);
    __nv_bfloat16* wtb = (__nv_bfloat16*)(scratch + OFF_WTB);
    __nv_bfloat16* Kb  = (__nv_bfloat16*)(scratch + OFF_KB);
    __nv_bfloat16* Qb  = (__nv_bfloat16*)(scratch + OFF_QB);
    __nv_bfloat16* Vtb = (__nv_bfloat16*)(scratch + OFF_VTB);
    __nv_bfloat16* alb = (__nv_bfloat16*)(scratch + OFF_ALB);
    __nv_bfloat16* fvwt = (__nv_bfloat16*)(scratch + OFF_FVWT);

    float* x2   = (float*)d_out;
    float* edge = (float*)d_out + NM * DD;

    cudaFuncSetAttribute(scores_soft_k,
                         cudaFuncAttributeMaxDynamicSharedMemorySize, SS_SMEM);

    dim3 gb(128);
    const int MN2 = NM * DD / 2;
    const int NC2 = DD / 2;

    // 1) f_node hidden (scalar, K-split 2) -> partials
    gemm_k<F_TE, 2><<<dim3(2, 16, 2), gb>>>(
        x, fn_w1, nullptr, nullptr, P, DIN, 2 * DD, 2 * DD, 0, 0, 0, 1, 0, 0,
        (int64_t)NM * 2 * DD, nullptr, 1, 0);
    // 2) h (scalar, K-split 8); A-loader reduces f_node1 partials
    float* Ph = P + NM * 2 * DD * 2;
    gemm_k<F_AR, 8><<<dim3(1, 16, 8), gb>>>(
        P, fn_w2, nullptr, nullptr, Ph, 2 * DD, DD, DD, 0, 0, 0, 1, 0, 0,
        (int64_t)NM * DD, fn_b1, 2, (int64_t)NM * 2 * DD);
    fuse_prep_k<<<768, 256>>>((const float2*)Ph, fn_b2, (float2*)h, hb,
                              wk, wq, wv, fv_w1, wtb, fvwt);
    // 3) K/Q/V via mma.sync
    kqv_mma_k<<<dim3(1, 8, 24), 256>>>(hb, wtb, bk, bq, bv, Kb, Qb, Vtb);
    // 4) fused scores + softmax -> bf16 alpha (no S buffer, no softmax kernel)
    scores_soft_k<<<dim3(1, 8, 16), 256, SS_SMEM>>>(Kb, Qb, alb);
    // 5) attV via mma.sync -> bf16 attc (leaky + concat in epilogue)
    attv_mma_k<<<dim3(1, 8, 16), 256>>>(alb, Vtb, attcb);
    // 6) f_v hidden via mma.sync (K-split 8) -> partials
    fv1_mma_k<<<dim3(1, 8, 8), 256>>>(attcb, fvwt, P);
    // 7) x2 (scalar, K-split 4); A-loader reduces fv1 partials
    float* P8 = P + 8 * NM * DD;
    gemm_k<F_AR, 4><<<dim3(1, 16, 4), gb>>>(
        P, fv_w2, nullptr, nullptr, P8, DD, DD, DD, 0, 0, 0, 1, 0, 0,
        (int64_t)NM * DD, fv_b1, 8, (int64_t)NM * DD);
    reduce_k<F_BIAS | F_ADD, 4><<<256, 256>>>(
        (const float2*)P8, fv_b2, (const float2*)h, (float2*)x2, MN2, NC2);
    // 8) A/B for edges (scalar, K-split 2 + reduce)
    float* P9 = P8 + 4 * NM * DD;
    gemm_k<0, 2><<<dim3(1, 16, 4), gb>>>(
        x2, fe_w1, nullptr, nullptr, P9, DD, DD, DD,
        0, (int64_t)DD * DD, 0, 1, (int64_t)NM * DD, 0, (int64_t)2 * NM * DD,
        nullptr, 1, 0);
    reduce_k<0, 2><<<512, 256>>>(
        (const float2*)P9, nullptr, nullptr, (float2*)ABuf, 2 * MN2, NC2);
    // 9) edge (packed f32x2)
    edge_k<<<dim3(16, 16, NB), 256>>>(ABuf, fe_b1, fe_w2, fe_b2, edge);
}